// round 10
// baseline (speedup 1.0000x reference)
#include <cuda_runtime.h>
#include <cuda_bf16.h>
#include <math.h>
#include <stdint.h>

#define BB 16
#define CC 256
#define HH 96
#define WW 96
#define HWSZ (HH*WW)           // 9216
#define NELEM (BB*CC*HWSZ)     // 37,748,736

// Scratch (device globals: allocation-free rule)
__device__ __nv_bfloat16 g_thb[NELEM];       // y = M x (rounds 1-2)
__device__ __nv_bfloat16 g_gb[NELEM];        // g = Wg x + bg
__device__ __nv_bfloat16 g_xb[NELEM];        // bf16 mirror of current x
__device__ float g_x1[NELEM];
__device__ float g_x2[NELEM];
__device__ float g_S[BB*CC*CC];              // logits fp32
__device__ __nv_bfloat16 g_Pb[BB*CC*CC];     // probabilities bf16
__device__ __nv_bfloat16 g_Wbf[3*CC*CC];     // [Wt; Wp; Wg] bf16
__device__ __nv_bfloat16 g_W2[2*CC*CC];      // [M = Wt^T Wp ; Wg] bf16 (512x256)
__device__ float g_G[BB*CC*CC];              // Gram X X^T fp32
__device__ float g_T1[BB*CC*CC];             // Wt @ G fp32
__device__ float g_xs[BB*CC*96];             // per-axis sums of x
__device__ float g_xs2[BB*CC];               // full-hw sums of x
__device__ float g_u[BB*96];
__device__ float g_v[BB*96];
__device__ float g_w1[CC];
__device__ float g_w2[CC];
__device__ float g_c0[1];
__device__ float g_sA[BB*CC];
__device__ float g_sB2[BB*CC];

// ---------------------------------------------------------------------------
// helpers
// ---------------------------------------------------------------------------
__device__ __forceinline__ uint32_t smem_u32(const void* p) {
    return (uint32_t)__cvta_generic_to_shared(p);
}
__device__ __forceinline__ uint32_t packbf(float lo, float hi) {
    __nv_bfloat162 h = __floats2bfloat162_rn(lo, hi);
    return *(uint32_t*)&h;
}
__device__ __forceinline__ float tf32r(float f) {
    uint32_t u;
    asm("cvt.rna.tf32.f32 %0, %1;" : "=r"(u) : "f"(f));
    return __uint_as_float(u);
}
__device__ __forceinline__ void cpa16(uint32_t dst, const void* src) {
    asm volatile("cp.async.cg.shared.global [%0], [%1], 16;" :: "r"(dst), "l"(src));
}
#define CP_COMMIT() asm volatile("cp.async.commit_group;")
template<int N> __device__ __forceinline__ void cp_wait() {
    asm volatile("cp.async.wait_group %0;" :: "n"(N));
}
__device__ __forceinline__ void ldsm4(uint32_t& r0, uint32_t& r1, uint32_t& r2, uint32_t& r3, uint32_t a) {
    asm volatile("ldmatrix.sync.aligned.m8n8.x4.shared.b16 {%0,%1,%2,%3},[%4];"
                 : "=r"(r0), "=r"(r1), "=r"(r2), "=r"(r3) : "r"(a));
}
__device__ __forceinline__ void ldsm4t(uint32_t& r0, uint32_t& r1, uint32_t& r2, uint32_t& r3, uint32_t a) {
    asm volatile("ldmatrix.sync.aligned.m8n8.x4.trans.shared.b16 {%0,%1,%2,%3},[%4];"
                 : "=r"(r0), "=r"(r1), "=r"(r2), "=r"(r3) : "r"(a));
}
__device__ __forceinline__ void ldsm2(uint32_t& r0, uint32_t& r1, uint32_t a) {
    asm volatile("ldmatrix.sync.aligned.m8n8.x2.shared.b16 {%0,%1},[%2];"
                 : "=r"(r0), "=r"(r1) : "r"(a));
}
__device__ __forceinline__ void ldsm2t(uint32_t& r0, uint32_t& r1, uint32_t a) {
    asm volatile("ldmatrix.sync.aligned.m8n8.x2.trans.shared.b16 {%0,%1},[%2];"
                 : "=r"(r0), "=r"(r1) : "r"(a));
}
__device__ __forceinline__ void mma_bf16(float (&d)[4], uint32_t a0, uint32_t a1, uint32_t a2, uint32_t a3,
                                         uint32_t b0, uint32_t b1) {
    asm volatile(
        "mma.sync.aligned.m16n8k16.row.col.f32.bf16.bf16.f32 "
        "{%0,%1,%2,%3},{%4,%5,%6,%7},{%8,%9},{%0,%1,%2,%3};"
        : "+f"(d[0]), "+f"(d[1]), "+f"(d[2]), "+f"(d[3])
        : "r"(a0), "r"(a1), "r"(a2), "r"(a3), "r"(b0), "r"(b1));
}
__device__ __forceinline__ void mma_tf32(float (&d)[4], const uint32_t (&a)[4],
                                         uint32_t b0, uint32_t b1) {
    asm volatile(
        "mma.sync.aligned.m16n8k8.row.col.f32.tf32.tf32.f32 "
        "{%0,%1,%2,%3},{%4,%5,%6,%7},{%8,%9},{%0,%1,%2,%3};\n"
        : "+f"(d[0]), "+f"(d[1]), "+f"(d[2]), "+f"(d[3])
        : "r"(a[0]), "r"(a[1]), "r"(a[2]), "r"(a[3]), "r"(b0), "r"(b1));
}

// tf32 warp MMA: As [m][k] lda, Bs [k][n] ldb, KS k-steps of 8.
template<int MF, int NF, int LDA, int LDB, int KS>
__device__ __forceinline__ void warp_mma_tf32(const float* As, const float* Bs,
                                              int m_warp, int n_warp, int lane,
                                              float (&acc)[MF][NF][4]) {
    int g = lane >> 2, tg = lane & 3;
    #pragma unroll
    for (int ks = 0; ks < KS; ks++) {
        int k0 = ks * 8;
        uint32_t a[MF][4];
        #pragma unroll
        for (int mf = 0; mf < MF; mf++) {
            const float* p = As + (m_warp + mf*16 + g) * LDA + k0 + tg;
            a[mf][0] = __float_as_uint(p[0]);
            a[mf][2] = __float_as_uint(p[4]);
            const float* p2 = p + 8 * LDA;
            a[mf][1] = __float_as_uint(p2[0]);
            a[mf][3] = __float_as_uint(p2[4]);
        }
        #pragma unroll
        for (int nf = 0; nf < NF; nf++) {
            const float* q = Bs + (k0 + tg) * LDB + n_warp + nf*8 + g;
            uint32_t b0 = __float_as_uint(q[0]);
            uint32_t b1 = __float_as_uint(q[4 * LDB]);
            #pragma unroll
            for (int mf = 0; mf < MF; mf++)
                mma_tf32(acc[mf][nf], a[mf], b0, b1);
        }
    }
}

// 128(M)x128(N) tile step: A [m][k] non-trans lda=LDA, B [k][n] trans ldb=LDB, KS k-steps.
template<int LDA, int LDB, int KS>
__device__ __forceinline__ void mma_tileT(const __nv_bfloat16* As, const __nv_bfloat16* Bs,
                                          int mw, int nw, int lane, float (&acc)[4][4][4])
{
    #pragma unroll
    for (int ks = 0; ks < KS; ks++) {
        int k0 = ks * 16;
        uint32_t a[4][4], bf[4][2];
        #pragma unroll
        for (int mf = 0; mf < 4; mf++)
            ldsm4(a[mf][0], a[mf][1], a[mf][2], a[mf][3],
                  smem_u32(As + (mw + mf*16 + (lane & 15)) * LDA + k0 + (lane >> 4) * 8));
        #pragma unroll
        for (int nb = 0; nb < 2; nb++)
            ldsm4t(bf[nb*2][0], bf[nb*2][1], bf[nb*2+1][0], bf[nb*2+1][1],
                   smem_u32(Bs + (k0 + (lane & 15)) * LDB + nw + nb*16 + (lane >> 4) * 8));
        #pragma unroll
        for (int mf = 0; mf < 4; mf++)
            #pragma unroll
            for (int nf = 0; nf < 4; nf++)
                mma_bf16(acc[mf][nf], a[mf][0], a[mf][1], a[mf][2], a[mf][3],
                         bf[nf][0], bf[nf][1]);
    }
}

// 128x128 tile step, B [n][k] non-trans (for gram).
template<int LDA, int LDB, int KS>
__device__ __forceinline__ void mma_tileNN(const __nv_bfloat16* As, const __nv_bfloat16* Bs,
                                           int mw, int nw, int lane, float (&acc)[4][4][4])
{
    #pragma unroll
    for (int ks = 0; ks < KS; ks++) {
        int k0 = ks * 16;
        uint32_t a[4][4], bf[4][2];
        #pragma unroll
        for (int mf = 0; mf < 4; mf++)
            ldsm4(a[mf][0], a[mf][1], a[mf][2], a[mf][3],
                  smem_u32(As + (mw + mf*16 + (lane & 15)) * LDA + k0 + (lane >> 4) * 8));
        #pragma unroll
        for (int nb = 0; nb < 2; nb++)
            ldsm4(bf[nb*2][0], bf[nb*2][1], bf[nb*2+1][0], bf[nb*2+1][1],
                  smem_u32(Bs + (nw + nb*16 + (lane>>4)*8 + (lane&7)) * LDB + k0 + ((lane>>3)&1)*8));
        #pragma unroll
        for (int mf = 0; mf < 4; mf++)
            #pragma unroll
            for (int nf = 0; nf < 4; nf++)
                mma_bf16(acc[mf][nf], a[mf][0], a[mf][1], a[mf][2], a[mf][3],
                         bf[nf][0], bf[nf][1]);
    }
}

// ---------------------------------------------------------------------------
// one-time converts / precomputes
// ---------------------------------------------------------------------------
__global__ void wconv_kernel(const float* __restrict__ wt, const float* __restrict__ wp,
                             const float* __restrict__ wg) {
    int i = blockIdx.x * 256 + threadIdx.x;
    const float* src = (i < 65536) ? wt : (i < 131072 ? wp : wg);
    __nv_bfloat16 v = __float2bfloat16(src[i & 65535]);
    g_Wbf[i] = v;
    if (i >= 131072) g_W2[65536 + (i - 131072)] = v;
}
__global__ void xconv_kernel(const float* __restrict__ x) {
    size_t base = ((size_t)blockIdx.x * 256 + threadIdx.x) * 8;
    float4 f0 = *(const float4*)(x + base);
    float4 f1 = *(const float4*)(x + base + 4);
    uint4 v;
    v.x = packbf(f0.x, f0.y); v.y = packbf(f0.z, f0.w);
    v.z = packbf(f1.x, f1.y); v.w = packbf(f1.z, f1.w);
    *(uint4*)(g_xb + base) = v;
}

// M = Wt^T Wp (256x256) -> g_W2 rows 0-255. Tile 64x64, K=256, 4 warps (2x2).
__global__ __launch_bounds__(128) void mprep_kernel()
{
    __shared__ __align__(16) __nv_bfloat16 As[64][72];
    __shared__ __align__(16) __nv_bfloat16 Bs[64][72];

    int m0 = blockIdx.y * 64, n0 = blockIdx.x * 64;
    int tid = threadIdx.x, wid = tid >> 5, lane = tid & 31;
    int mw = (wid >> 1) * 32, nw = (wid & 1) * 32;
    int g = lane >> 2, tg = lane & 3;

    float acc[2][4][4] = {};
    int cr = tid >> 1, mc = (tid & 1) * 32;

    for (int kk = 0; kk < 256; kk += 64) {
        uint32_t ad = smem_u32(&As[cr][mc]);
        uint32_t bd = smem_u32(&Bs[cr][mc]);
        const __nv_bfloat16* asrc = g_Wbf + (size_t)(kk + cr) * 256 + m0 + mc;
        const __nv_bfloat16* bsrc = g_Wbf + 65536 + (size_t)(kk + cr) * 256 + n0 + mc;
        #pragma unroll
        for (int j = 0; j < 4; j++) { cpa16(ad + j*16, asrc + j*8); cpa16(bd + j*16, bsrc + j*8); }
        CP_COMMIT();
        cp_wait<0>();
        __syncthreads();
        #pragma unroll
        for (int ks = 0; ks < 4; ks++) {
            int k0 = ks * 16;
            uint32_t a[2][4], bf[4][2];
            #pragma unroll
            for (int mf = 0; mf < 2; mf++)
                ldsm4t(a[mf][0], a[mf][1], a[mf][2], a[mf][3],
                    smem_u32(&As[k0 + ((lane>>4)&1)*8 + (lane&7)][mw + mf*16 + ((lane>>3)&1)*8]));
            ldsm4t(bf[0][0], bf[0][1], bf[1][0], bf[1][1],
                   smem_u32(&Bs[k0 + (lane&15)][nw + (lane>>4)*8]));
            ldsm4t(bf[2][0], bf[2][1], bf[3][0], bf[3][1],
                   smem_u32(&Bs[k0 + (lane&15)][nw + 16 + (lane>>4)*8]));
            #pragma unroll
            for (int mf = 0; mf < 2; mf++)
                #pragma unroll
                for (int nf = 0; nf < 4; nf++)
                    mma_bf16(acc[mf][nf], a[mf][0], a[mf][1], a[mf][2], a[mf][3],
                             bf[nf][0], bf[nf][1]);
        }
        __syncthreads();
    }
    #pragma unroll
    for (int mf = 0; mf < 2; mf++) {
        int r1 = m0 + mw + mf*16 + g, r2 = r1 + 8;
        #pragma unroll
        for (int nf = 0; nf < 4; nf++) {
            int col = n0 + nw + nf*8 + tg*2;
            *(uint32_t*)&g_W2[r1*256 + col] = packbf(acc[mf][nf][0], acc[mf][nf][1]);
            *(uint32_t*)&g_W2[r2*256 + col] = packbf(acc[mf][nf][2], acc[mf][nf][3]);
        }
    }
}

// bias fold vectors
__global__ __launch_bounds__(256) void biasvec_kernel(const float* __restrict__ wt,
                                                      const float* __restrict__ wp,
                                                      const float* __restrict__ bt,
                                                      const float* __restrict__ bp)
{
    int k = blockIdx.x, o = threadIdx.x;
    __shared__ float r1[8], r2[8], r3[8];
    float btv = bt[o], bpv = bp[o];
    float s1 = wt[o*256 + k] * bpv;
    float s2 = wp[o*256 + k] * btv;
    float c  = btv * bpv;
    #pragma unroll
    for (int off = 16; off; off >>= 1) {
        s1 += __shfl_xor_sync(0xffffffffu, s1, off);
        s2 += __shfl_xor_sync(0xffffffffu, s2, off);
        c  += __shfl_xor_sync(0xffffffffu, c, off);
    }
    if ((o & 31) == 0) { r1[o>>5] = s1; r2[o>>5] = s2; r3[o>>5] = c; }
    __syncthreads();
    if (o == 0) {
        float a = 0.f, b2 = 0.f, cc = 0.f;
        #pragma unroll
        for (int w = 0; w < 8; w++) { a += r1[w]; b2 += r2[w]; cc += r3[w]; }
        g_w1[k] = a; g_w2[k] = b2;
        if (k == 0) g_c0[0] = 96.f * cc;
    }
}

// ---------------------------------------------------------------------------
// conv panel: B panel (256K x 128N of xb) resident in smem; loop mtiles of A.
// BK=64 A chunks (2x128x72 double buffer) -> 64 HMMA/warp per sync pair.
// smem: 256*136*2 + 2*128*72*2 = 106,496 B; 2 blocks/SM.
// ---------------------------------------------------------------------------
__global__ __launch_bounds__(256) void conv_panel_kernel(
    const __nv_bfloat16* __restrict__ W, int mtiles,
    __nv_bfloat16* dst0, const float* bias0,
    __nv_bfloat16* dst1, const float* bias1)
{
    extern __shared__ __align__(16) __nv_bfloat16 dynsm[];
    __nv_bfloat16* Bs = dynsm;                               // [256][136]
    __nv_bfloat16* Ab[2] = { dynsm + 256*136, dynsm + 256*136 + 128*72 };

    int b = blockIdx.z, n0 = blockIdx.x * 128;
    int tid = threadIdx.x, wid = tid >> 5, lane = tid & 31;
    int mw = (wid >> 2) * 64, nw = (wid & 3) * 32;
    int g = lane >> 2, tg = lane & 3;

    const __nv_bfloat16* bbase = g_xb + (size_t)b * CC * HWSZ + n0;
    #pragma unroll
    for (int j = 0; j < 16; j++) {
        int idx = j * 256 + tid;
        int row = idx >> 4, cb8 = (idx & 15) * 8;
        cpa16(smem_u32(Bs + row*136 + cb8), bbase + (size_t)row * HWSZ + cb8);
    }
    CP_COMMIT();

    int arow = tid >> 1, akb = (tid & 1) * 32;

    for (int mt = 0; mt < mtiles; mt++) {
        int mbase = mt * 128;
        const __nv_bfloat16* asrc = W + (size_t)(mbase + arow) * 256 + akb;
        {
            uint32_t ad = smem_u32(Ab[0] + arow*72 + akb);
            #pragma unroll
            for (int j = 0; j < 4; j++) cpa16(ad + j*16, asrc + j*8);
            CP_COMMIT();
        }
        float acc[4][4][4] = {};
        for (int kc = 0; kc < 4; kc++) {
            if (kc < 3) {
                uint32_t ad = smem_u32(Ab[(kc+1)&1] + arow*72 + akb);
                const __nv_bfloat16* as = asrc + (kc + 1) * 64;
                #pragma unroll
                for (int j = 0; j < 4; j++) cpa16(ad + j*16, as + j*8);
                CP_COMMIT();
                cp_wait<1>();
            } else cp_wait<0>();
            __syncthreads();
            mma_tileT<72, 136, 4>(Ab[kc&1], Bs + kc*64*136, mw, nw, lane, acc);
            __syncthreads();
        }
        int mat = mbase >> 8, ob = mbase & 255;
        __nv_bfloat16* dst = mat ? dst1 : dst0;
        const float* bias = mat ? bias1 : bias0;
        #pragma unroll
        for (int mf = 0; mf < 4; mf++) {
            int r = mw + mf * 16 + g;
            int o1 = ob + r, o2 = o1 + 8;
            float b1 = bias ? bias[o1] : 0.f;
            float b2 = bias ? bias[o2] : 0.f;
            size_t base1 = ((size_t)b * CC + o1) * HWSZ + n0;
            size_t base2 = ((size_t)b * CC + o2) * HWSZ + n0;
            #pragma unroll
            for (int nf = 0; nf < 4; nf++) {
                int col = nw + nf * 8 + tg * 2;
                *(uint32_t*)&dst[base1 + col] = packbf(acc[mf][nf][0] + b1, acc[mf][nf][1] + b1);
                *(uint32_t*)&dst[base2 + col] = packbf(acc[mf][nf][2] + b2, acc[mf][nf][3] + b2);
            }
        }
    }
}

// ---------------------------------------------------------------------------
// apply channel panel: out = xin + beta * (P @ g), B = g panel resident. BK=64.
// ---------------------------------------------------------------------------
__global__ __launch_bounds__(256) void apply_channel_panel_kernel(
    const float* __restrict__ xin, float* __restrict__ xout, const float* __restrict__ beta_p)
{
    extern __shared__ __align__(16) __nv_bfloat16 dynsm[];
    __nv_bfloat16* Bs = dynsm;
    __nv_bfloat16* Ab[2] = { dynsm + 256*136, dynsm + 256*136 + 128*72 };

    int b = blockIdx.z, n0 = blockIdx.x * 128;
    int tid = threadIdx.x, wid = tid >> 5, lane = tid & 31;
    int mw = (wid >> 2) * 64, nw = (wid & 3) * 32;
    int g = lane >> 2, tg = lane & 3;

    const __nv_bfloat16* bbase = g_gb + (size_t)b * CC * HWSZ + n0;
    #pragma unroll
    for (int j = 0; j < 16; j++) {
        int idx = j * 256 + tid;
        int row = idx >> 4, cb8 = (idx & 15) * 8;
        cpa16(smem_u32(Bs + row*136 + cb8), bbase + (size_t)row * HWSZ + cb8);
    }
    CP_COMMIT();

    int arow = tid >> 1, akb = (tid & 1) * 32;
    float beta = *beta_p;

    for (int mt = 0; mt < 2; mt++) {
        int mbase = mt * 128;
        const __nv_bfloat16* asrc = g_Pb + (size_t)b * 65536 + (size_t)(mbase + arow) * 256 + akb;
        {
            uint32_t ad = smem_u32(Ab[0] + arow*72 + akb);
            #pragma unroll
            for (int j = 0; j < 4; j++) cpa16(ad + j*16, asrc + j*8);
            CP_COMMIT();
        }
        float acc[4][4][4] = {};
        for (int kc = 0; kc < 4; kc++) {
            if (kc < 3) {
                uint32_t ad = smem_u32(Ab[(kc+1)&1] + arow*72 + akb);
                const __nv_bfloat16* as = asrc + (kc + 1) * 64;
                #pragma unroll
                for (int j = 0; j < 4; j++) cpa16(ad + j*16, as + j*8);
                CP_COMMIT();
                cp_wait<1>();
            } else cp_wait<0>();
            __syncthreads();
            mma_tileT<72, 136, 4>(Ab[kc&1], Bs + kc*64*136, mw, nw, lane, acc);
            __syncthreads();
        }
        #pragma unroll
        for (int mf = 0; mf < 4; mf++) {
            int r1 = mbase + mw + mf * 16 + g, r2 = r1 + 8;
            size_t base1 = ((size_t)b * CC + r1) * HWSZ + n0;
            size_t base2 = ((size_t)b * CC + r2) * HWSZ + n0;
            #pragma unroll
            for (int nf = 0; nf < 4; nf++) {
                int col = nw + nf * 8 + tg * 2;
                float2 xa = *(const float2*)&xin[base1 + col];
                float2 xb2 = *(const float2*)&xin[base2 + col];
                *(float2*)&xout[base1 + col] =
                    make_float2(xa.x + beta*acc[mf][nf][0], xa.y + beta*acc[mf][nf][1]);
                *(float2*)&xout[base2 + col] =
                    make_float2(xb2.x + beta*acc[mf][nf][2], xb2.y + beta*acc[mf][nf][3]);
            }
        }
    }
}

// ---------------------------------------------------------------------------
// per-axis x sums
// ---------------------------------------------------------------------------
template<int MODE>
__global__ __launch_bounds__(96) void xsum_kernel()
{
    int k = blockIdx.x, b = blockIdx.y, i = threadIdx.x;
    const __nv_bfloat16* src = g_xb + ((size_t)b * CC + k) * HWSZ;
    float s = 0.f;
    if (MODE == 0) {
        #pragma unroll 8
        for (int h = 0; h < 96; h++) s += __bfloat162float(src[h*96 + i]);
    } else {
        #pragma unroll 8
        for (int w = 0; w < 96; w++) s += __bfloat162float(src[i*96 + w]);
    }
    g_xs[((size_t)b * CC + k) * 96 + i] = s;
}

__global__ __launch_bounds__(96) void uv_kernel()
{
    int b = blockIdx.x, j = threadIdx.x;
    float su = 0.f, sv = 0.f;
    #pragma unroll 8
    for (int k = 0; k < 256; k++) {
        float xv = g_xs[((size_t)b * CC + k) * 96 + j];
        su += g_w2[k] * xv;
        sv += g_w1[k] * xv;
    }
    g_u[b*96 + j] = su;
    g_v[b*96 + j] = sv;
}

// ---------------------------------------------------------------------------
// slice logits (8 channels/block, grid 32x16)
// ---------------------------------------------------------------------------
template<int MODE>
__global__ __launch_bounds__(256) void slice_logits_bf16_kernel(
    const __nv_bfloat16* __restrict__ Abase, const __nv_bfloat16* __restrict__ Bbase)
{
    extern __shared__ __align__(16) __nv_bfloat16 dynsm[];
    __nv_bfloat16* Tb[2] = { dynsm,            dynsm + 2*96*104 };
    __nv_bfloat16* Pb[2] = { dynsm + 96*104,   dynsm + 3*96*104 };

    int b = blockIdx.y, cch = blockIdx.x;
    int tid = threadIdx.x, wid = tid >> 5, lane = tid & 31;
    int mw = (wid >> 2) * 48, nw = (wid & 3) * 24;
    int g = lane >> 2, tg = lane & 3;

    const __nv_bfloat16* tbase = Abase + ((size_t)b * CC + cch * 8) * HWSZ;
    const __nv_bfloat16* pbase = Bbase + ((size_t)b * CC + cch * 8) * HWSZ;

    float acc[3][3][4] = {};

    auto stage = [&](int cc, int bi) {
        const __nv_bfloat16* ts = tbase + (size_t)cc * HWSZ;
        const __nv_bfloat16* ps = pbase + (size_t)cc * HWSZ;
        #pragma unroll
        for (int j = 0; j < 9; j++) {
            int c = j * 256 + tid;
            int cc2 = (c < 1152) ? c : c - 1152;
            int row = cc2 / 12, col = (cc2 % 12) * 8;
            if (c < 1152) cpa16(smem_u32(Tb[bi] + row*104 + col), ts + row*96 + col);
            else          cpa16(smem_u32(Pb[bi] + row*104 + col), ps + row*96 + col);
        }
        CP_COMMIT();
    };

    stage(0, 0);
    for (int cc = 0; cc < 8; cc++) {
        if (cc < 7) { stage(cc + 1, (cc + 1) & 1); cp_wait<1>(); }
        else cp_wait<0>();
        __syncthreads();
        const __nv_bfloat16* As = Tb[cc & 1];
        const __nv_bfloat16* Bs = Pb[cc & 1];
        #pragma unroll
        for (int ks = 0; ks < 6; ks++) {
            int k0 = ks * 16;
            uint32_t a[3][4], bf[3][2];
            #pragma unroll
            for (int mf = 0; mf < 3; mf++) {
                if (MODE == 0)
                    ldsm4t(a[mf][0], a[mf][1], a[mf][2], a[mf][3],
                        smem_u32(As + (k0 + ((lane>>4)&1)*8 + (lane&7))*104 + mw + mf*16 + ((lane>>3)&1)*8));
                else
                    ldsm4(a[mf][0], a[mf][1], a[mf][2], a[mf][3],
                        smem_u32(As + (mw + mf*16 + (lane&15))*104 + k0 + (lane>>4)*8));
            }
            if (MODE == 0) {
                ldsm4t(bf[0][0], bf[0][1], bf[1][0], bf[1][1],
                       smem_u32(Bs + (k0 + (lane&15))*104 + nw + (lane>>4)*8));
                ldsm2t(bf[2][0], bf[2][1],
                       smem_u32(Bs + (k0 + (lane&15))*104 + nw + 16));
            } else {
                ldsm4(bf[0][0], bf[0][1], bf[1][0], bf[1][1],
                      smem_u32(Bs + (nw + (lane>>4)*8 + (lane&7))*104 + k0 + ((lane>>3)&1)*8));
                ldsm2(bf[2][0], bf[2][1],
                      smem_u32(Bs + (nw + 16 + (lane&7))*104 + k0 + ((lane>>3)&1)*8));
            }
            #pragma unroll
            for (int mf = 0; mf < 3; mf++)
                #pragma unroll
                for (int nf = 0; nf < 3; nf++)
                    mma_bf16(acc[mf][nf], a[mf][0], a[mf][1], a[mf][2], a[mf][3],
                             bf[nf][0], bf[nf][1]);
        }
        __syncthreads();
    }
    float* Sb = g_S + (size_t)b * 9216;
    #pragma unroll
    for (int mf = 0; mf < 3; mf++) {
        int i1 = mw + mf * 16 + g, i2 = i1 + 8;
        #pragma unroll
        for (int nf = 0; nf < 3; nf++) {
            int jc = nw + nf * 8 + tg * 2;
            atomicAdd(&Sb[i1 * 96 + jc],     acc[mf][nf][0]);
            atomicAdd(&Sb[i1 * 96 + jc + 1], acc[mf][nf][1]);
            atomicAdd(&Sb[i2 * 96 + jc],     acc[mf][nf][2]);
            atomicAdd(&Sb[i2 * 96 + jc + 1], acc[mf][nf][3]);
        }
    }
}

// ---------------------------------------------------------------------------
// softmax: optional additive bias. writes bf16 P.
// ---------------------------------------------------------------------------
__global__ __launch_bounds__(256) void softmax_kernel(int n, const float* u,
                                                      const float* v, const float* c0p)
{
    size_t base = (size_t)blockIdx.x * n;
    int tid = threadIdx.x;
    __shared__ float red[8];

    float rowadd = 0.f;
    int ub = 0;
    if (u) {
        rowadd = v[blockIdx.x] + *c0p;
        ub = (blockIdx.x / 96) * 96;
    }

    float m = -INFINITY;
    for (int j = tid; j < n; j += 256) {
        float val = g_S[base + j] + rowadd + (u ? u[ub + j] : 0.f);
        m = fmaxf(m, val);
    }
    #pragma unroll
    for (int o = 16; o; o >>= 1) m = fmaxf(m, __shfl_xor_sync(0xffffffffu, m, o));
    if ((tid & 31) == 0) red[tid >> 5] = m;
    __syncthreads();
    float mm = red[0];
    #pragma unroll
    for (int w = 1; w < 8; w++) mm = fmaxf(mm, red[w]);

    float s = 0.f;
    float ev[2];
    int cnt = 0;
    for (int j = tid; j < n; j += 256) {
        float val = g_S[base + j] + rowadd + (u ? u[ub + j] : 0.f);
        float e = __expf(val - mm);
        ev[cnt++] = e;
        s += e;
    }
    #pragma unroll
    for (int o = 16; o; o >>= 1) s += __shfl_xor_sync(0xffffffffu, s, o);
    if ((tid & 31) == 0) red[tid >> 5] = s;
    __syncthreads();
    float st = 0.f;
    #pragma unroll
    for (int w = 0; w < 8; w++) st += red[w];
    float inv = 1.0f / st;
    cnt = 0;
    for (int j = tid; j < n; j += 256)
        g_Pb[base + j] = __float2bfloat16(ev[cnt++] * inv);
}

// ---------------------------------------------------------------------------
// apply width / height
// ---------------------------------------------------------------------------
__global__ __launch_bounds__(256) void apply_slice_w_kernel(
    const float* __restrict__ xin, float* __restrict__ xout, const float* __restrict__ beta_p)
{
    __shared__ __align__(16) __nv_bfloat16 As[128][104];
    __shared__ __align__(16) __nv_bfloat16 Bs[96][104];

    int b = blockIdx.y, m0 = blockIdx.x * 128;
    int tid = threadIdx.x, wid = tid >> 5, lane = tid & 31;
    int mw = (wid >> 1) * 32, nw = (wid & 1) * 48;
    int g = lane >> 2, tg = lane & 3;

    const __nv_bfloat16* gsrc = g_gb + (size_t)b * CC * HWSZ + (size_t)m0 * 96;
    const __nv_bfloat16* psrc = g_Pb + (size_t)b * 9216;
    #pragma unroll
    for (int j = 0; j < 6; j++) {
        int c = j * 256 + tid;
        int row = c / 12, col = (c % 12) * 8;
        cpa16(smem_u32(&As[row][col]), gsrc + row*96 + col);
    }
    #pragma unroll
    for (int j = 0; j < 5; j++) {
        int c = j * 256 + tid;
        if (c < 1152) {
            int row = c / 12, col = (c % 12) * 8;
            cpa16(smem_u32(&Bs[row][col]), psrc + row*96 + col);
        }
    }
    CP_COMMIT();
    cp_wait<0>();
    __syncthreads();

    float acc[2][6][4] = {};
    #pragma unroll
    for (int ks = 0; ks < 6; ks++) {
        int k0 = ks * 16;
        uint32_t a[2][4], bf[6][2];
        #pragma unroll
        for (int mf = 0; mf < 2; mf++)
            ldsm4(a[mf][0], a[mf][1], a[mf][2], a[mf][3],
                  smem_u32(&As[mw + mf*16 + (lane&15)][k0 + (lane>>4)*8]));
        #pragma unroll
        for (int nb = 0; nb < 3; nb++)
            ldsm4(bf[nb*2][0], bf[nb*2][1], bf[nb*2+1][0], bf[nb*2+1][1],
                  smem_u32(&Bs[nw + nb*16 + (lane>>4)*8 + (lane&7)][k0 + ((lane>>3)&1)*8]));
        #pragma unroll
        for (int mf = 0; mf < 2; mf++)
            #pragma unroll
            for (int nf = 0; nf < 6; nf++)
                mma_bf16(acc[mf][nf], a[mf][0], a[mf][1], a[mf][2], a[mf][3],
                         bf[nf][0], bf[nf][1]);
    }
    float beta = *beta_p;
    size_t gb = (size_t)b * CC * HWSZ;
    #pragma unroll
    for (int mf = 0; mf < 2; mf++) {
        int r1 = m0 + mw + mf * 16 + g, r2 = r1 + 8;
        #pragma unroll
        for (int nf = 0; nf < 6; nf++) {
            int col = nw + nf * 8 + tg * 2;
            size_t o1 = gb + (size_t)r1 * 96 + col;
            size_t o2 = gb + (size_t)r2 * 96 + col;
            float2 xa = *(const float2*)&xin[o1];
            float2 xb2 = *(const float2*)&xin[o2];
            float v0 = xa.x + beta*acc[mf][nf][0], v1 = xa.y + beta*acc[mf][nf][1];
            float v2 = xb2.x + beta*acc[mf][nf][2], v3 = xb2.y + beta*acc[mf][nf][3];
            *(float2*)&xout[o1] = make_float2(v0, v1);
            *(float2*)&xout[o2] = make_float2(v2, v3);
            *(uint32_t*)&g_xb[o1] = packbf(v0, v1);
            *(uint32_t*)&g_xb[o2] = packbf(v2, v3);
        }
    }
}

__global__ __launch_bounds__(256) void apply_slice_h_kernel(
    const float* __restrict__ xin, float* __restrict__ xout, const float* __restrict__ beta_p)
{
    __shared__ __align__(16) __nv_bfloat16 As[96][104];
    __shared__ __align__(16) __nv_bfloat16 Bs[96][104];

    int b = blockIdx.y, c = blockIdx.x;
    int tid = threadIdx.x, wid = tid >> 5, lane = tid & 31;
    int mw = (wid >> 2) * 48, nw = (wid & 3) * 24;
    int g = lane >> 2, tg = lane & 3;

    const __nv_bfloat16* psrc = g_Pb + (size_t)b * 9216;
    const __nv_bfloat16* gsrc = g_gb + ((size_t)b * CC + c) * HWSZ;
    #pragma unroll
    for (int j = 0; j < 9; j++) {
        int cidx = j * 256 + tid;
        int c2 = (cidx < 1152) ? cidx : cidx - 1152;
        int row = c2 / 12, col = (c2 % 12) * 8;
        if (cidx < 1152) cpa16(smem_u32(&As[row][col]), psrc + row*96 + col);
        else             cpa16(smem_u32(&Bs[row][col]), gsrc + row*96 + col);
    }
    CP_COMMIT();
    cp_wait<0>();
    __syncthreads();

    float acc[3][3][4] = {};
    #pragma unroll
    for (int ks = 0; ks < 6; ks++) {
        int k0 = ks * 16;
        uint32_t a[3][4], bf[3][2];
        #pragma unroll
        for (int mf = 0; mf < 3; mf++)
            ldsm4(a[mf][0], a[mf][1], a[mf][2], a[mf][3],
                  smem_u32(&As[mw + mf*16 + (lane&15)][k0 + (lane>>4)*8]));
        ldsm4t(bf[0][0], bf[0][1], bf[1][0], bf[1][1],
               smem_u32(&Bs[k0 + (lane&15)][nw + (lane>>4)*8]));
        ldsm2t(bf[2][0], bf[2][1],
               smem_u32(&Bs[k0 + (lane&15)][nw + 16]));
        #pragma unroll
        for (int mf = 0; mf < 3; mf++)
            #pragma unroll
            for (int nf = 0; nf < 3; nf++)
                mma_bf16(acc[mf][nf], a[mf][0], a[mf][1], a[mf][2], a[mf][3],
                         bf[nf][0], bf[nf][1]);
    }
    float beta = *beta_p;
    size_t base = ((size_t)b * CC + c) * HWSZ;
    #pragma unroll
    for (int mf = 0; mf < 3; mf++) {
        int i1 = mw + mf * 16 + g, i2 = i1 + 8;
        #pragma unroll
        for (int nf = 0; nf < 3; nf++) {
            int col = nw + nf * 8 + tg * 2;
            size_t o1 = base + (size_t)i1 * 96 + col;
            size_t o2 = base + (size_t)i2 * 96 + col;
            float2 xa = *(const float2*)&xin[o1];
            float2 xb2 = *(const float2*)&xin[o2];
            float v0 = xa.x + beta*acc[mf][nf][0], v1 = xa.y + beta*acc[mf][nf][1];
            float v2 = xb2.x + beta*acc[mf][nf][2], v3 = xb2.y + beta*acc[mf][nf][3];
            *(float2*)&xout[o1] = make_float2(v0, v1);
            *(float2*)&xout[o2] = make_float2(v2, v3);
            *(uint32_t*)&g_xb[o1] = packbf(v0, v1);
            *(uint32_t*)&g_xb[o2] = packbf(v2, v3);
        }
    }
}

// ---------------------------------------------------------------------------
// Gram: 128x128 tiles, symmetric (3 tile-blocks per b), BK=32 double-buffered.
// ---------------------------------------------------------------------------
__global__ __launch_bounds__(256) void gram_kernel()
{
    __shared__ __align__(16) __nv_bfloat16 Asm[2][128][40];
    __shared__ __align__(16) __nv_bfloat16 Bsm[2][128][40];

    int ti = blockIdx.x, b = blockIdx.y;
    int i0 = (ti == 2) ? 128 : 0;
    int j0 = (ti == 0) ? 0 : 128;
    int tid = threadIdx.x, wid = tid >> 5, lane = tid & 31;
    int mw = (wid >> 2) * 64, nw = (wid & 3) * 32;
    int g = lane >> 2, tg = lane & 3;

    int row = tid >> 1, cb = (tid & 1) * 16;
    const __nv_bfloat16* as0 = g_xb + ((size_t)b * CC + i0 + row) * HWSZ + cb;
    const __nv_bfloat16* bs0 = g_xb + ((size_t)b * CC + j0 + row) * HWSZ + cb;

    float acc[4][4][4] = {};

    auto stage = [&](int kk, int bi) {
        uint32_t ad = smem_u32(&Asm[bi][row][cb]);
        uint32_t bd = smem_u32(&Bsm[bi][row][cb]);
        cpa16(ad, as0 + kk); cpa16(ad + 16, as0 + kk + 8);
        cpa16(bd, bs0 + kk); cpa16(bd + 16, bs0 + kk + 8);
        CP_COMMIT();
    };

    stage(0, 0);
    for (int s = 0; s < 288; s++) {
        if (s < 287) { stage((s + 1) * 32, (s + 1) & 1); cp_wait<1>(); }
        else cp_wait<0>();
        __syncthreads();
        mma_tileNN<40, 40, 2>(&Asm[s&1][0][0], &Bsm[s&1][0][0], mw, nw, lane, acc);
        __syncthreads();
    }
    float* Gb = g_G + (size_t)b * 65536;
    #pragma unroll
    for (int mf = 0; mf < 4; mf++) {
        int i1 = i0 + mw + mf * 16 + g, i2 = i1 + 8;
        #pragma unroll
        for (int nf = 0; nf < 4; nf++) {
            int jc = j0 + nw + nf * 8 + tg * 2;
            *(float2*)&Gb[(size_t)i1 * 256 + jc] = make_float2(acc[mf][nf][0], acc[mf][nf][1]);
            *(float2*)&Gb[(size_t)i2 * 256 + jc] = make_float2(acc[mf][nf][2], acc[mf][nf][3]);
            if (ti == 1) {
                Gb[(size_t)jc * 256 + i1]       = acc[mf][nf][0];
                Gb[(size_t)(jc + 1) * 256 + i1] = acc[mf][nf][1];
                Gb[(size_t)jc * 256 + i2]       = acc[mf][nf][2];
                Gb[(size_t)(jc + 1) * 256 + i2] = acc[mf][nf][3];
            }
        }
    }
}

// xs2[b,c] = sum_hw x[b,c,:]
__global__ __launch_bounds__(256) void xsum2_kernel()
{
    int k = blockIdx.x, b = blockIdx.y, tid = threadIdx.x;
    const __nv_bfloat16* src = g_xb + ((size_t)b * CC + k) * HWSZ;
    __shared__ float red[8];
    float s = 0.f;
    for (int e = tid; e < HWSZ; e += 256) s += __bfloat162float(src[e]);
    #pragma unroll
    for (int o = 16; o; o >>= 1) s += __shfl_xor_sync(0xffffffffu, s, o);
    if ((tid & 31) == 0) red[tid >> 5] = s;
    __syncthreads();
    if (tid == 0) {
        float t = 0.f;
        #pragma unroll
        for (int w = 0; w < 8; w++) t += red[w];
        g_xs2[b * CC + k] = t;
    }
}

__global__ __launch_bounds__(256) void sAsB_kernel(const float* __restrict__ wt,
                                                   const float* __restrict__ wp,
                                                   const float* __restrict__ bp)
{
    int i = blockIdx.x, b = blockIdx.y, c = threadIdx.x;
    __shared__ float r1[8], r2[8];
    float xv = g_xs2[b*CC + c];
    float sa = wt[i*256 + c] * xv;
    float sb = wp[i*256 + c] * xv;
    #pragma unroll
    for (int off = 16; off; off >>= 1) {
        sa += __shfl_xor_sync(0xffffffffu, sa, off);
        sb += __shfl_xor_sync(0xffffffffu, sb, off);
    }
    if ((c & 31) == 0) { r1[c>>5] = sa; r2[c>>5] = sb; }
    __syncthreads();
    if (c == 0) {
        float a = 0.f, b2 = 0.f;
        #pragma unroll
        for (int w = 0; w < 8; w++) { a += r1[w]; b2 += r2[w]; }
        g_sA[b*CC + i] = a;
        g_sB2[b*CC + i] = b2 + 9216.f * bp[i];
    }
}

// ---------------------------------------------------------------------------
// tf32 GEMM NN: T1[b] = wt @ G[b]. Tile 64x64, BK=32, 128 threads (2x2 warps).
// ---------------------------------------------------------------------------
__global__ __launch_bounds__(128) void tf32gemm_nn_kernel(const float* __restrict__ wt)
{
    __shared__ __align__(16) float As[64 * 36];
    __shared__ __align__(16) float Bs[32 * 68];

    int b = blockIdx.z, i0 = blockIdx.y * 64, n0 = blockIdx.x * 64;
    int tid = threadIdx.x, wid = tid >> 5, lane = tid & 31;
    int mw = (wid >> 1) * 32, nw = (wid & 1) * 32;
    int g = lane >> 2, tg = lane & 3;

    const float* Gb = g_G + (size_t)b * 65536;
    float acc[2][4][4] = {};
    int am = tid >> 1, akh = (tid & 1) * 16;
    int bk = tid >> 2, bnh = (tid & 3) * 16;

    for (int kk = 0; kk < 256; kk += 32) {
        {
            const float4* s = (const float4*)(wt + (size_t)(i0 + am) * 256 + kk + akh);
            float* d = As + am * 36 + akh;
            #pragma unroll
            for (int j = 0; j < 4; j++) {
                float4 v = s[j];
                *(float4*)(d + j*4) = make_float4(tf32r(v.x), tf32r(v.y), tf32r(v.z), tf32r(v.w));
            }
        }
        {
            const float4* s = (const float4*)(Gb + (size_t)(kk + bk) * 256 + n0 + bnh);
            float* d = Bs + bk * 68 + bnh;
            #pragma unroll
            for (int j = 0; j < 4; j++) {
                float4 v = s[j];
                *(float4*)(d + j*4) = make_float4(tf32r(v.x), tf32r(v.y), tf32r(v.z), tf32r(v.w));
            }
        }
        __syncthreads();
        warp_mma_tf32<2, 4, 36, 68, 4>(As, Bs, mw, nw, lane, acc);
        __syncthreads();
    }

    float* T1b = g_T1 + (size_t)b * 65536;
    #pragma unroll
    for (int mf = 0; mf < 2; mf++) {
        int r1 = i0 + mw + mf * 16 + g, r2 = r1 + 8;
        #pragma unroll
        for (int nf = 0; nf < 4; nf++) {
            int col = n0 + nw + nf * 8 + tg * 2;
            *(float2*)&T1b[(size_t)r1 * 256 + col] = make_float2(acc[mf][nf][0], acc[mf][nf][1]);
            *(float2*)&T1b[(size_t)r2 * 256 + col] = make_float2(acc[mf][nf][2], acc[mf][nf][3]);
        }
    }
}

// ---------------------------------------------------------------------------
// tf32 GEMM NT + channel-bias epilogue: S = T1 @ wp^T + bias terms.
// ---------------------------------------------------------------------------
__global__ __launch_bounds__(128) void tf32gemm_nt_kernel(const float* __restrict__ wp,
                                                          const float* __restrict__ bt,
                                                          const float* __restrict__ bp)
{
    __shared__ __align__(16) float As[64 * 36];
    __shared__ __align__(16) float Bs[32 * 68];

    int b = blockIdx.z, i0 = blockIdx.y * 64, j0 = blockIdx.x * 64;
    int tid = threadIdx.x, wid = tid >> 5, lane = tid & 31;
    int mw = (wid >> 1) * 32, nw = (wid & 1) * 32;
    int g = lane >> 2, tg = lane & 3;

    const float* T1b = g_T1 + (size_t)b * 65536;
    float acc[2][4][4] = {};
    int am = tid >> 1, akh = (tid & 1) * 16;
    int lc = tid & 31, lr = tid >> 5;

    for (int kk = 0; kk < 256; kk += 32) {
        {
            const float4* s = (const float4*)(T1b + (size_t)(i0 + am) * 256 + kk + akh);
            float* d = As + am * 36 + akh;
            #pragma unroll
            for (int j = 0; j < 4; j++) {
                float4 v = s[j];
                *(float4*)(d + j*4) = make_float4(tf32r(v.x), tf32r(v.y), tf32r(v.z), tf32r(v.w));
            }
        }
        #pragma unroll
        for (int rr = 0; rr < 16; rr++) {
            int r = rr * 4 + lr;
            Bs[lc * 68 + r] = tf32r(wp[(j0 + r) * 256 + kk + lc]);
        }
        __syncthreads();
        warp_mma_tf32<2, 4, 36, 68, 4>(As, Bs, mw, nw, lane, acc);
        __syncthreads();
    }

    float* Sb = g_S + (size_t)b * 65536;
    #pragma unroll
    for (int mf = 0; mf < 2; mf++) {
        int r1 = i0 + mw + mf * 16 + g, r2 = r1 + 8;
        float bt1 = bt[r1], sa1 = g_sA[b*CC + r1];
        float bt2 = bt[r2], sa2 = g_sA[b*CC + r2];
        #pragma unroll
        for (int nf = 0; nf < 4; nf++) {
            int col = j0 + nw + nf * 8 + tg * 2;
            float sb0 = g_sB2[b*CC + col], sb1 = g_sB2[b*CC + col + 1];
            float bp0 = bp[col], bp1 = bp[col + 1];
            Sb[(size_t)r1 * 256 + col]     = acc[mf][nf][0] + bt1 * sb0 + bp0 * sa1;
            Sb[(size_t)r1 * 256 + col + 1] = acc[mf][nf][1] + bt1 * sb1 + bp1 * sa1;
            Sb[(size_t)r2 * 256 + col]     = acc[mf][nf][2] + bt2 * sb0 + bp0 * sa2;
            Sb[(size_t)r2 * 256 + col + 1] = acc[mf][nf][3] + bt2 * sb1 + bp1 * sa2;
        }
    }
}

// ---------------------------------------------------------------------------
extern "C" void kernel_launch(void* const* d_in, const int* in_sizes, int n_in,
                              void* d_out, int out_size)
{
    const float* x      = (const float*)d_in[0];
    const float* wt     = (const float*)d_in[1];
    const float* bt     = (const float*)d_in[2];
    const float* wp     = (const float*)d_in[3];
    const float* bp     = (const float*)d_in[4];
    const float* wg     = (const float*)d_in[5];
    const float* bg     = (const float*)d_in[6];
    const float* beta_w = (const float*)d_in[7];
    const float* beta_h = (const float*)d_in[8];
    const float* beta_c = (const float*)d_in[9];
    float* out = (float*)d_out;

    float *x1, *x2, *S, *uu, *vv, *c0;
    __nv_bfloat16 *thb, *gbb, *W2, *xbb, *Wbf;
    cudaGetSymbolAddress((void**)&x1, g_x1);
    cudaGetSymbolAddress((void**)&x2, g_x2);
    cudaGetSymbolAddress((void**)&S,  g_S);
    cudaGetSymbolAddress((void**)&uu, g_u);
    cudaGetSymbolAddress((void**)&vv, g_v);
    cudaGetSymbolAddress((void**)&c0, g_c0);
    cudaGetSymbolAddress((void**)&thb, g_thb);
    cudaGetSymbolAddress((void**)&gbb, g_gb);
    cudaGetSymbolAddress((void**)&W2,  g_W2);
    cudaGetSymbolAddress((void**)&xbb, g_xb);
    cudaGetSymbolAddress((void**)&Wbf, g_Wbf);

    int panel_smem = 256*136*2 + 2*128*72*2;      // 106,496 B
    int slice_smem = 4 * 96 * 104 * 2;            // 79,872 B
    cudaFuncSetAttribute(conv_panel_kernel,
                         cudaFuncAttributeMaxDynamicSharedMemorySize, panel_smem);
    cudaFuncSetAttribute(apply_channel_panel_kernel,
                         cudaFuncAttributeMaxDynamicSharedMemorySize, panel_smem);
    cudaFuncSetAttribute(slice_logits_bf16_kernel<0>,
                         cudaFuncAttributeMaxDynamicSharedMemorySize, slice_smem);
    cudaFuncSetAttribute(slice_logits_bf16_kernel<1>,
                         cudaFuncAttributeMaxDynamicSharedMemorySize, slice_smem);

    static cudaStream_t s2 = nullptr;
    static cudaEvent_t ev[8];
    if (!s2) {
        cudaStreamCreateWithFlags(&s2, cudaStreamNonBlocking);
        for (int i = 0; i < 8; i++)
            cudaEventCreateWithFlags(&ev[i], cudaEventDisableTiming);
    }
    cudaStream_t s0 = 0;

    // ---- fork s2 immediately (weight prep does not depend on x) ----
    cudaEventRecord(ev[0], s0);
    cudaStreamWaitEvent(s2, ev[0], 0);
    wconv_kernel<<<768, 256, 0, s2>>>(wt, wp, wg);
    mprep_kernel<<<dim3(4, 4), 128, 0, s2>>>();
    cudaEventRecord(ev[1], s2);                               // W2 ready
    biasvec_kernel<<<256, 256, 0, s2>>>(wt, wp, bt, bp);
    cudaMemsetAsync(S, 0, (size_t)16 * 9216 * sizeof(float), s2);

    // ---- x conversion on main stream, parallel with weight prep ----
    xconv_kernel<<<NELEM / (256 * 8), 256, 0, s0>>>(x);
    cudaEventRecord(ev[7], s0);                               // g_xb ready

    cudaStreamWaitEvent(s2, ev[7], 0);
    xsum_kernel<0><<<dim3(256, 16), 96, 0, s2>>>();
    uv_kernel<<<16, 96, 0, s2>>>();
    cudaEventRecord(ev[2], s2);                               // S zeroed + u/v ready

    // ---- round 1: width attention ----
    cudaStreamWaitEvent(s0, ev[1], 0);
    conv_panel_kernel<<<dim3(72, 1, 16), 256, panel_smem, s0>>>(W2, 4, thb, nullptr, gbb, bg);
    cudaStreamWaitEvent(s0, ev[2], 0);
    slice_logits_bf16_kernel<0><<<dim3(32, 16), 256, slice_smem, s0>>>(xbb, thb);
    softmax_kernel<<<16 * 96, 256, 0, s0>>>(96, uu, vv, c0);
    apply_slice_w_kernel<<<dim3(192, 16), 256, 0, s0>>>(x, x1, beta_w);
    cudaEventRecord(ev[3], s0);                               // new x (g_xb) ready

    // ---- round 2: height attention ----
    cudaStreamWaitEvent(s2, ev[3], 0);
    cudaMemsetAsync(S, 0, (size_t)16 * 9216 * sizeof(float), s2);
    xsum_kernel<1><<<dim3(256, 16), 96, 0, s2>>>();
    uv_kernel<<<16, 96, 0, s2>>>();
    cudaEventRecord(ev[4], s2);

    conv_panel_kernel<<<dim3(72, 1, 16), 256, panel_smem, s0>>>(W2, 4, thb, nullptr, gbb, bg);
    cudaStreamWaitEvent(s0, ev[4], 0);
    slice_logits_bf16_kernel<1><<<dim3(32, 16), 256, slice_smem, s0>>>(xbb, thb);
    softmax_kernel<<<16 * 96, 256, 0, s0>>>(96, uu, vv, c0);
    apply_slice_h_kernel<<<dim3(256, 16), 256, 0, s0>>>(x1, x2, beta_h);
    cudaEventRecord(ev[5], s0);                               // new x (g_xb) ready

    // ---- round 3: channel attention ----
    cudaStreamWaitEvent(s2, ev[5], 0);
    xsum2_kernel<<<dim3(256, 16), 256, 0, s2>>>();
    sAsB_kernel<<<dim3(256, 16), 256, 0, s2>>>(wt, wp, bp);
    gram_kernel<<<dim3(3, 16), 256, 0, s2>>>();
    cudaEventRecord(ev[6], s2);                               // G + sA/sB2 ready

    conv_panel_kernel<<<dim3(72, 1, 16), 256, panel_smem, s0>>>(Wbf + 2*65536, 2, gbb, bg, gbb, bg);
    cudaStreamWaitEvent(s0, ev[6], 0);
    tf32gemm_nn_kernel<<<dim3(4, 4, 16), 128, 0, s0>>>(wt);
    tf32gemm_nt_kernel<<<dim3(4, 4, 16), 128, 0, s0>>>(wp, bt, bp);
    softmax_kernel<<<16 * 256, 256, 0, s0>>>(256, nullptr, nullptr, nullptr);
    apply_channel_panel_kernel<<<dim3(72, 1, 16), 256, panel_smem, s0>>>(x2, out, beta_c);
}

// round 11
// speedup vs baseline: 1.0441x; 1.0441x over previous
#include <cuda_runtime.h>
#include <cuda_bf16.h>
#include <math.h>
#include <stdint.h>

#define BB 16
#define CC 256
#define HH 96
#define WW 96
#define HWSZ (HH*WW)           // 9216
#define NELEM (BB*CC*HWSZ)     // 37,748,736

// Scratch (device globals: allocation-free rule)
__device__ __nv_bfloat16 g_thb[NELEM];       // y = M x (rounds 1-2)
__device__ __nv_bfloat16 g_gb[NELEM];        // g = Wg x + bg
__device__ __nv_bfloat16 g_xb[NELEM];        // bf16 mirror of current x
__device__ float g_x1[NELEM];
__device__ float g_x2[NELEM];
__device__ float g_S[BB*CC*CC];              // logits fp32
__device__ __nv_bfloat16 g_Pb[BB*CC*CC];     // probabilities bf16
__device__ __nv_bfloat16 g_Wbf[3*CC*CC];     // [Wt; Wp; Wg] bf16
__device__ __nv_bfloat16 g_W2[2*CC*CC];      // [M = Wt^T Wp ; Wg] bf16 (512x256)
__device__ float g_G[BB*CC*CC];              // Gram X X^T fp32
__device__ float g_T1[BB*CC*CC];             // Wt @ G fp32
__device__ float g_xs[BB*CC*96];             // per-axis sums of x
__device__ float g_xs2[BB*CC];               // full-hw sums of x
__device__ float g_u[BB*96];
__device__ float g_v[BB*96];
__device__ float g_w1[CC];
__device__ float g_w2[CC];
__device__ float g_c0[1];
__device__ float g_sA[BB*CC];
__device__ float g_sB2[BB*CC];

// ---------------------------------------------------------------------------
// helpers
// ---------------------------------------------------------------------------
__device__ __forceinline__ uint32_t smem_u32(const void* p) {
    return (uint32_t)__cvta_generic_to_shared(p);
}
__device__ __forceinline__ uint32_t packbf(float lo, float hi) {
    __nv_bfloat162 h = __floats2bfloat162_rn(lo, hi);
    return *(uint32_t*)&h;
}
__device__ __forceinline__ void cpa16(uint32_t dst, const void* src) {
    asm volatile("cp.async.cg.shared.global [%0], [%1], 16;" :: "r"(dst), "l"(src));
}
#define CP_COMMIT() asm volatile("cp.async.commit_group;")
template<int N> __device__ __forceinline__ void cp_wait() {
    asm volatile("cp.async.wait_group %0;" :: "n"(N));
}
__device__ __forceinline__ void ldsm4(uint32_t& r0, uint32_t& r1, uint32_t& r2, uint32_t& r3, uint32_t a) {
    asm volatile("ldmatrix.sync.aligned.m8n8.x4.shared.b16 {%0,%1,%2,%3},[%4];"
                 : "=r"(r0), "=r"(r1), "=r"(r2), "=r"(r3) : "r"(a));
}
__device__ __forceinline__ void ldsm4t(uint32_t& r0, uint32_t& r1, uint32_t& r2, uint32_t& r3, uint32_t a) {
    asm volatile("ldmatrix.sync.aligned.m8n8.x4.trans.shared.b16 {%0,%1,%2,%3},[%4];"
                 : "=r"(r0), "=r"(r1), "=r"(r2), "=r"(r3) : "r"(a));
}
__device__ __forceinline__ void ldsm2(uint32_t& r0, uint32_t& r1, uint32_t a) {
    asm volatile("ldmatrix.sync.aligned.m8n8.x2.shared.b16 {%0,%1},[%2];"
                 : "=r"(r0), "=r"(r1) : "r"(a));
}
__device__ __forceinline__ void ldsm2t(uint32_t& r0, uint32_t& r1, uint32_t a) {
    asm volatile("ldmatrix.sync.aligned.m8n8.x2.trans.shared.b16 {%0,%1},[%2];"
                 : "=r"(r0), "=r"(r1) : "r"(a));
}
__device__ __forceinline__ void mma_bf16(float (&d)[4], uint32_t a0, uint32_t a1, uint32_t a2, uint32_t a3,
                                         uint32_t b0, uint32_t b1) {
    asm volatile(
        "mma.sync.aligned.m16n8k16.row.col.f32.bf16.bf16.f32 "
        "{%0,%1,%2,%3},{%4,%5,%6,%7},{%8,%9},{%0,%1,%2,%3};"
        : "+f"(d[0]), "+f"(d[1]), "+f"(d[2]), "+f"(d[3])
        : "r"(a0), "r"(a1), "r"(a2), "r"(a3), "r"(b0), "r"(b1));
}

// 128(M)x128(N) tile step: A [m][k] non-trans lda=LDA, B [k][n] trans ldb=LDB, KS k-steps.
template<int LDA, int LDB, int KS>
__device__ __forceinline__ void mma_tileT(const __nv_bfloat16* As, const __nv_bfloat16* Bs,
                                          int mw, int nw, int lane, float (&acc)[4][4][4])
{
    #pragma unroll
    for (int ks = 0; ks < KS; ks++) {
        int k0 = ks * 16;
        uint32_t a[4][4], bf[4][2];
        #pragma unroll
        for (int mf = 0; mf < 4; mf++)
            ldsm4(a[mf][0], a[mf][1], a[mf][2], a[mf][3],
                  smem_u32(As + (mw + mf*16 + (lane & 15)) * LDA + k0 + (lane >> 4) * 8));
        #pragma unroll
        for (int nb = 0; nb < 2; nb++)
            ldsm4t(bf[nb*2][0], bf[nb*2][1], bf[nb*2+1][0], bf[nb*2+1][1],
                   smem_u32(Bs + (k0 + (lane & 15)) * LDB + nw + nb*16 + (lane >> 4) * 8));
        #pragma unroll
        for (int mf = 0; mf < 4; mf++)
            #pragma unroll
            for (int nf = 0; nf < 4; nf++)
                mma_bf16(acc[mf][nf], a[mf][0], a[mf][1], a[mf][2], a[mf][3],
                         bf[nf][0], bf[nf][1]);
    }
}

// 128x128 tile step, B [n][k] non-trans (for gram).
template<int LDA, int LDB, int KS>
__device__ __forceinline__ void mma_tileNN(const __nv_bfloat16* As, const __nv_bfloat16* Bs,
                                           int mw, int nw, int lane, float (&acc)[4][4][4])
{
    #pragma unroll
    for (int ks = 0; ks < KS; ks++) {
        int k0 = ks * 16;
        uint32_t a[4][4], bf[4][2];
        #pragma unroll
        for (int mf = 0; mf < 4; mf++)
            ldsm4(a[mf][0], a[mf][1], a[mf][2], a[mf][3],
                  smem_u32(As + (mw + mf*16 + (lane & 15)) * LDA + k0 + (lane >> 4) * 8));
        #pragma unroll
        for (int nb = 0; nb < 2; nb++)
            ldsm4(bf[nb*2][0], bf[nb*2][1], bf[nb*2+1][0], bf[nb*2+1][1],
                  smem_u32(Bs + (nw + nb*16 + (lane>>4)*8 + (lane&7)) * LDB + k0 + ((lane>>3)&1)*8));
        #pragma unroll
        for (int mf = 0; mf < 4; mf++)
            #pragma unroll
            for (int nf = 0; nf < 4; nf++)
                mma_bf16(acc[mf][nf], a[mf][0], a[mf][1], a[mf][2], a[mf][3],
                         bf[nf][0], bf[nf][1]);
    }
}

// ---------------------------------------------------------------------------
// one-time converts / precomputes
// ---------------------------------------------------------------------------
__global__ void wconv_kernel(const float* __restrict__ wt, const float* __restrict__ wp,
                             const float* __restrict__ wg) {
    int i = blockIdx.x * 256 + threadIdx.x;
    const float* src = (i < 65536) ? wt : (i < 131072 ? wp : wg);
    __nv_bfloat16 v = __float2bfloat16(src[i & 65535]);
    g_Wbf[i] = v;
    if (i >= 131072) g_W2[65536 + (i - 131072)] = v;
}
__global__ void xconv_kernel(const float* __restrict__ x) {
    size_t base = ((size_t)blockIdx.x * 256 + threadIdx.x) * 8;
    float4 f0 = *(const float4*)(x + base);
    float4 f1 = *(const float4*)(x + base + 4);
    uint4 v;
    v.x = packbf(f0.x, f0.y); v.y = packbf(f0.z, f0.w);
    v.z = packbf(f1.x, f1.y); v.w = packbf(f1.z, f1.w);
    *(uint4*)(g_xb + base) = v;
}

// M = Wt^T Wp (256x256) -> g_W2 rows 0-255. Tile 64x64, K=256, 4 warps (2x2).
__global__ __launch_bounds__(128) void mprep_kernel()
{
    __shared__ __align__(16) __nv_bfloat16 As[64][72];
    __shared__ __align__(16) __nv_bfloat16 Bs[64][72];

    int m0 = blockIdx.y * 64, n0 = blockIdx.x * 64;
    int tid = threadIdx.x, wid = tid >> 5, lane = tid & 31;
    int mw = (wid >> 1) * 32, nw = (wid & 1) * 32;
    int g = lane >> 2, tg = lane & 3;

    float acc[2][4][4] = {};
    int cr = tid >> 1, mc = (tid & 1) * 32;

    for (int kk = 0; kk < 256; kk += 64) {
        uint32_t ad = smem_u32(&As[cr][mc]);
        uint32_t bd = smem_u32(&Bs[cr][mc]);
        const __nv_bfloat16* asrc = g_Wbf + (size_t)(kk + cr) * 256 + m0 + mc;
        const __nv_bfloat16* bsrc = g_Wbf + 65536 + (size_t)(kk + cr) * 256 + n0 + mc;
        #pragma unroll
        for (int j = 0; j < 4; j++) { cpa16(ad + j*16, asrc + j*8); cpa16(bd + j*16, bsrc + j*8); }
        CP_COMMIT();
        cp_wait<0>();
        __syncthreads();
        #pragma unroll
        for (int ks = 0; ks < 4; ks++) {
            int k0 = ks * 16;
            uint32_t a[2][4], bf[4][2];
            #pragma unroll
            for (int mf = 0; mf < 2; mf++)
                ldsm4t(a[mf][0], a[mf][1], a[mf][2], a[mf][3],
                    smem_u32(&As[k0 + ((lane>>4)&1)*8 + (lane&7)][mw + mf*16 + ((lane>>3)&1)*8]));
            ldsm4t(bf[0][0], bf[0][1], bf[1][0], bf[1][1],
                   smem_u32(&Bs[k0 + (lane&15)][nw + (lane>>4)*8]));
            ldsm4t(bf[2][0], bf[2][1], bf[3][0], bf[3][1],
                   smem_u32(&Bs[k0 + (lane&15)][nw + 16 + (lane>>4)*8]));
            #pragma unroll
            for (int mf = 0; mf < 2; mf++)
                #pragma unroll
                for (int nf = 0; nf < 4; nf++)
                    mma_bf16(acc[mf][nf], a[mf][0], a[mf][1], a[mf][2], a[mf][3],
                             bf[nf][0], bf[nf][1]);
        }
        __syncthreads();
    }
    #pragma unroll
    for (int mf = 0; mf < 2; mf++) {
        int r1 = m0 + mw + mf*16 + g, r2 = r1 + 8;
        #pragma unroll
        for (int nf = 0; nf < 4; nf++) {
            int col = n0 + nw + nf*8 + tg*2;
            *(uint32_t*)&g_W2[r1*256 + col] = packbf(acc[mf][nf][0], acc[mf][nf][1]);
            *(uint32_t*)&g_W2[r2*256 + col] = packbf(acc[mf][nf][2], acc[mf][nf][3]);
        }
    }
}

// bias fold vectors
__global__ __launch_bounds__(256) void biasvec_kernel(const float* __restrict__ wt,
                                                      const float* __restrict__ wp,
                                                      const float* __restrict__ bt,
                                                      const float* __restrict__ bp)
{
    int k = blockIdx.x, o = threadIdx.x;
    __shared__ float r1[8], r2[8], r3[8];
    float btv = bt[o], bpv = bp[o];
    float s1 = wt[o*256 + k] * bpv;
    float s2 = wp[o*256 + k] * btv;
    float c  = btv * bpv;
    #pragma unroll
    for (int off = 16; off; off >>= 1) {
        s1 += __shfl_xor_sync(0xffffffffu, s1, off);
        s2 += __shfl_xor_sync(0xffffffffu, s2, off);
        c  += __shfl_xor_sync(0xffffffffu, c, off);
    }
    if ((o & 31) == 0) { r1[o>>5] = s1; r2[o>>5] = s2; r3[o>>5] = c; }
    __syncthreads();
    if (o == 0) {
        float a = 0.f, b2 = 0.f, cc = 0.f;
        #pragma unroll
        for (int w = 0; w < 8; w++) { a += r1[w]; b2 += r2[w]; cc += r3[w]; }
        g_w1[k] = a; g_w2[k] = b2;
        if (k == 0) g_c0[0] = 96.f * cc;
    }
}

// ---------------------------------------------------------------------------
// conv panel: B panel (256K x 128N of xb) resident; A chunks BK=32 in a
// 3-buffer rotation -> ONE __syncthreads per chunk.
// smem: 256*136*2 + 3*128*40*2 = 100,352 B; 2 blocks/SM.
// ---------------------------------------------------------------------------
__global__ __launch_bounds__(256) void conv_panel_kernel(
    const __nv_bfloat16* __restrict__ W, int mtiles,
    __nv_bfloat16* dst0, const float* bias0,
    __nv_bfloat16* dst1, const float* bias1)
{
    extern __shared__ __align__(16) __nv_bfloat16 dynsm[];
    __nv_bfloat16* Bs = dynsm;                               // [256][136]
    __nv_bfloat16* Ab = dynsm + 256*136;                     // 3 x [128][40]

    int b = blockIdx.z, n0 = blockIdx.x * 128;
    int tid = threadIdx.x, wid = tid >> 5, lane = tid & 31;
    int mw = (wid >> 2) * 64, nw = (wid & 3) * 32;
    int g = lane >> 2, tg = lane & 3;

    const __nv_bfloat16* bbase = g_xb + (size_t)b * CC * HWSZ + n0;
    #pragma unroll
    for (int j = 0; j < 16; j++) {
        int idx = j * 256 + tid;
        int row = idx >> 4, cb8 = (idx & 15) * 8;
        cpa16(smem_u32(Bs + row*136 + cb8), bbase + (size_t)row * HWSZ + cb8);
    }
    CP_COMMIT();

    int arow = tid >> 1, acb = (tid & 1) * 16;
    int total = mtiles * 8;

    auto stageA = [&](int c) {
        int mt = c >> 3, kc = c & 7;
        const __nv_bfloat16* as = W + (size_t)(mt * 128 + arow) * 256 + kc * 32 + acb;
        uint32_t ad = smem_u32(Ab + (c % 3) * (128*40) + arow*40 + acb);
        cpa16(ad, as); cpa16(ad + 16, as + 8);
        CP_COMMIT();
    };
    stageA(0);
    stageA(1);

    float acc[4][4][4] = {};
    for (int c = 0; c < total; c++) {
        if (c == total - 1) cp_wait<0>(); else cp_wait<1>();
        __syncthreads();
        if (c + 2 < total) stageA(c + 2);
        mma_tileT<40, 136, 2>(Ab + (c % 3) * (128*40), Bs + (c & 7)*32*136, mw, nw, lane, acc);
        if ((c & 7) == 7) {
            int mbase = (c >> 3) * 128;
            int mat = mbase >> 8, ob = mbase & 255;
            __nv_bfloat16* dst = mat ? dst1 : dst0;
            const float* bias = mat ? bias1 : bias0;
            #pragma unroll
            for (int mf = 0; mf < 4; mf++) {
                int r = mw + mf * 16 + g;
                int o1 = ob + r, o2 = o1 + 8;
                float b1 = bias ? bias[o1] : 0.f;
                float b2 = bias ? bias[o2] : 0.f;
                size_t base1 = ((size_t)b * CC + o1) * HWSZ + n0;
                size_t base2 = ((size_t)b * CC + o2) * HWSZ + n0;
                #pragma unroll
                for (int nf = 0; nf < 4; nf++) {
                    int col = nw + nf * 8 + tg * 2;
                    *(uint32_t*)&dst[base1 + col] = packbf(acc[mf][nf][0] + b1, acc[mf][nf][1] + b1);
                    *(uint32_t*)&dst[base2 + col] = packbf(acc[mf][nf][2] + b2, acc[mf][nf][3] + b2);
                    acc[mf][nf][0] = 0.f; acc[mf][nf][1] = 0.f;
                    acc[mf][nf][2] = 0.f; acc[mf][nf][3] = 0.f;
                }
            }
        }
    }
}

// ---------------------------------------------------------------------------
// apply channel panel: out = xin + beta * (P @ g). Same 3-buffer pipeline.
// ---------------------------------------------------------------------------
__global__ __launch_bounds__(256) void apply_channel_panel_kernel(
    const float* __restrict__ xin, float* __restrict__ xout, const float* __restrict__ beta_p)
{
    extern __shared__ __align__(16) __nv_bfloat16 dynsm[];
    __nv_bfloat16* Bs = dynsm;
    __nv_bfloat16* Ab = dynsm + 256*136;

    int b = blockIdx.z, n0 = blockIdx.x * 128;
    int tid = threadIdx.x, wid = tid >> 5, lane = tid & 31;
    int mw = (wid >> 2) * 64, nw = (wid & 3) * 32;
    int g = lane >> 2, tg = lane & 3;

    const __nv_bfloat16* bbase = g_gb + (size_t)b * CC * HWSZ + n0;
    #pragma unroll
    for (int j = 0; j < 16; j++) {
        int idx = j * 256 + tid;
        int row = idx >> 4, cb8 = (idx & 15) * 8;
        cpa16(smem_u32(Bs + row*136 + cb8), bbase + (size_t)row * HWSZ + cb8);
    }
    CP_COMMIT();

    int arow = tid >> 1, acb = (tid & 1) * 16;
    const __nv_bfloat16* Pbb = g_Pb + (size_t)b * 65536;
    float beta = *beta_p;
    const int total = 16;

    auto stageA = [&](int c) {
        int mt = c >> 3, kc = c & 7;
        const __nv_bfloat16* as = Pbb + (size_t)(mt * 128 + arow) * 256 + kc * 32 + acb;
        uint32_t ad = smem_u32(Ab + (c % 3) * (128*40) + arow*40 + acb);
        cpa16(ad, as); cpa16(ad + 16, as + 8);
        CP_COMMIT();
    };
    stageA(0);
    stageA(1);

    float acc[4][4][4] = {};
    for (int c = 0; c < total; c++) {
        if (c == total - 1) cp_wait<0>(); else cp_wait<1>();
        __syncthreads();
        if (c + 2 < total) stageA(c + 2);
        mma_tileT<40, 136, 2>(Ab + (c % 3) * (128*40), Bs + (c & 7)*32*136, mw, nw, lane, acc);
        if ((c & 7) == 7) {
            int mbase = (c >> 3) * 128;
            #pragma unroll
            for (int mf = 0; mf < 4; mf++) {
                int r1 = mbase + mw + mf * 16 + g, r2 = r1 + 8;
                size_t base1 = ((size_t)b * CC + r1) * HWSZ + n0;
                size_t base2 = ((size_t)b * CC + r2) * HWSZ + n0;
                #pragma unroll
                for (int nf = 0; nf < 4; nf++) {
                    int col = nw + nf * 8 + tg * 2;
                    float2 xa = *(const float2*)&xin[base1 + col];
                    float2 xb2 = *(const float2*)&xin[base2 + col];
                    *(float2*)&xout[base1 + col] =
                        make_float2(xa.x + beta*acc[mf][nf][0], xa.y + beta*acc[mf][nf][1]);
                    *(float2*)&xout[base2 + col] =
                        make_float2(xb2.x + beta*acc[mf][nf][2], xb2.y + beta*acc[mf][nf][3]);
                    acc[mf][nf][0] = 0.f; acc[mf][nf][1] = 0.f;
                    acc[mf][nf][2] = 0.f; acc[mf][nf][3] = 0.f;
                }
            }
        }
    }
}

// ---------------------------------------------------------------------------
// per-axis x sums
// ---------------------------------------------------------------------------
template<int MODE>
__global__ __launch_bounds__(96) void xsum_kernel()
{
    int k = blockIdx.x, b = blockIdx.y, i = threadIdx.x;
    const __nv_bfloat16* src = g_xb + ((size_t)b * CC + k) * HWSZ;
    float s = 0.f;
    if (MODE == 0) {
        #pragma unroll 8
        for (int h = 0; h < 96; h++) s += __bfloat162float(src[h*96 + i]);
    } else {
        #pragma unroll 8
        for (int w = 0; w < 96; w++) s += __bfloat162float(src[i*96 + w]);
    }
    g_xs[((size_t)b * CC + k) * 96 + i] = s;
}

__global__ __launch_bounds__(96) void uv_kernel()
{
    int b = blockIdx.x, j = threadIdx.x;
    float su = 0.f, sv = 0.f;
    #pragma unroll 8
    for (int k = 0; k < 256; k++) {
        float xv = g_xs[((size_t)b * CC + k) * 96 + j];
        su += g_w2[k] * xv;
        sv += g_w1[k] * xv;
    }
    g_u[b*96 + j] = su;
    g_v[b*96 + j] = sv;
}

// ---------------------------------------------------------------------------
// slice logits (16 channels/block, grid 16x16)
// ---------------------------------------------------------------------------
template<int MODE>
__global__ __launch_bounds__(256) void slice_logits_bf16_kernel(
    const __nv_bfloat16* __restrict__ Abase, const __nv_bfloat16* __restrict__ Bbase)
{
    extern __shared__ __align__(16) __nv_bfloat16 dynsm[];
    __nv_bfloat16* Tb[2] = { dynsm,            dynsm + 2*96*104 };
    __nv_bfloat16* Pb[2] = { dynsm + 96*104,   dynsm + 3*96*104 };

    int b = blockIdx.y, cch = blockIdx.x;
    int tid = threadIdx.x, wid = tid >> 5, lane = tid & 31;
    int mw = (wid >> 2) * 48, nw = (wid & 3) * 24;
    int g = lane >> 2, tg = lane & 3;

    const __nv_bfloat16* tbase = Abase + ((size_t)b * CC + cch * 16) * HWSZ;
    const __nv_bfloat16* pbase = Bbase + ((size_t)b * CC + cch * 16) * HWSZ;

    float acc[3][3][4] = {};

    auto stage = [&](int cc, int bi) {
        const __nv_bfloat16* ts = tbase + (size_t)cc * HWSZ;
        const __nv_bfloat16* ps = pbase + (size_t)cc * HWSZ;
        #pragma unroll
        for (int j = 0; j < 9; j++) {
            int c = j * 256 + tid;
            int cc2 = (c < 1152) ? c : c - 1152;
            int row = cc2 / 12, col = (cc2 % 12) * 8;
            if (c < 1152) cpa16(smem_u32(Tb[bi] + row*104 + col), ts + row*96 + col);
            else          cpa16(smem_u32(Pb[bi] + row*104 + col), ps + row*96 + col);
        }
        CP_COMMIT();
    };

    stage(0, 0);
    for (int cc = 0; cc < 16; cc++) {
        if (cc < 15) { stage(cc + 1, (cc + 1) & 1); cp_wait<1>(); }
        else cp_wait<0>();
        __syncthreads();
        const __nv_bfloat16* As = Tb[cc & 1];
        const __nv_bfloat16* Bs = Pb[cc & 1];
        #pragma unroll
        for (int ks = 0; ks < 6; ks++) {
            int k0 = ks * 16;
            uint32_t a[3][4], bf[3][2];
            #pragma unroll
            for (int mf = 0; mf < 3; mf++) {
                if (MODE == 0)
                    ldsm4t(a[mf][0], a[mf][1], a[mf][2], a[mf][3],
                        smem_u32(As + (k0 + ((lane>>4)&1)*8 + (lane&7))*104 + mw + mf*16 + ((lane>>3)&1)*8));
                else
                    ldsm4(a[mf][0], a[mf][1], a[mf][2], a[mf][3],
                        smem_u32(As + (mw + mf*16 + (lane&15))*104 + k0 + (lane>>4)*8));
            }
            if (MODE == 0) {
                ldsm4t(bf[0][0], bf[0][1], bf[1][0], bf[1][1],
                       smem_u32(Bs + (k0 + (lane&15))*104 + nw + (lane>>4)*8));
                ldsm2t(bf[2][0], bf[2][1],
                       smem_u32(Bs + (k0 + (lane&15))*104 + nw + 16));
            } else {
                ldsm4(bf[0][0], bf[0][1], bf[1][0], bf[1][1],
                      smem_u32(Bs + (nw + (lane>>4)*8 + (lane&7))*104 + k0 + ((lane>>3)&1)*8));
                ldsm2(bf[2][0], bf[2][1],
                      smem_u32(Bs + (nw + 16 + (lane&7))*104 + k0 + ((lane>>3)&1)*8));
            }
            #pragma unroll
            for (int mf = 0; mf < 3; mf++)
                #pragma unroll
                for (int nf = 0; nf < 3; nf++)
                    mma_bf16(acc[mf][nf], a[mf][0], a[mf][1], a[mf][2], a[mf][3],
                             bf[nf][0], bf[nf][1]);
        }
        __syncthreads();
    }
    float* Sb = g_S + (size_t)b * 9216;
    #pragma unroll
    for (int mf = 0; mf < 3; mf++) {
        int i1 = mw + mf * 16 + g, i2 = i1 + 8;
        #pragma unroll
        for (int nf = 0; nf < 3; nf++) {
            int jc = nw + nf * 8 + tg * 2;
            atomicAdd(&Sb[i1 * 96 + jc],     acc[mf][nf][0]);
            atomicAdd(&Sb[i1 * 96 + jc + 1], acc[mf][nf][1]);
            atomicAdd(&Sb[i2 * 96 + jc],     acc[mf][nf][2]);
            atomicAdd(&Sb[i2 * 96 + jc + 1], acc[mf][nf][3]);
        }
    }
}

// ---------------------------------------------------------------------------
// softmax: optional additive bias. writes bf16 P.
// ---------------------------------------------------------------------------
__global__ __launch_bounds__(256) void softmax_kernel(int n, const float* u,
                                                      const float* v, const float* c0p)
{
    size_t base = (size_t)blockIdx.x * n;
    int tid = threadIdx.x;
    __shared__ float red[8];

    float rowadd = 0.f;
    int ub = 0;
    if (u) {
        rowadd = v[blockIdx.x] + *c0p;
        ub = (blockIdx.x / 96) * 96;
    }

    float m = -INFINITY;
    for (int j = tid; j < n; j += 256) {
        float val = g_S[base + j] + rowadd + (u ? u[ub + j] : 0.f);
        m = fmaxf(m, val);
    }
    #pragma unroll
    for (int o = 16; o; o >>= 1) m = fmaxf(m, __shfl_xor_sync(0xffffffffu, m, o));
    if ((tid & 31) == 0) red[tid >> 5] = m;
    __syncthreads();
    float mm = red[0];
    #pragma unroll
    for (int w = 1; w < 8; w++) mm = fmaxf(mm, red[w]);

    float s = 0.f;
    float ev[2];
    int cnt = 0;
    for (int j = tid; j < n; j += 256) {
        float val = g_S[base + j] + rowadd + (u ? u[ub + j] : 0.f);
        float e = __expf(val - mm);
        ev[cnt++] = e;
        s += e;
    }
    #pragma unroll
    for (int o = 16; o; o >>= 1) s += __shfl_xor_sync(0xffffffffu, s, o);
    if ((tid & 31) == 0) red[tid >> 5] = s;
    __syncthreads();
    float st = 0.f;
    #pragma unroll
    for (int w = 0; w < 8; w++) st += red[w];
    float inv = 1.0f / st;
    cnt = 0;
    for (int j = tid; j < n; j += 256)
        g_Pb[base + j] = __float2bfloat16(ev[cnt++] * inv);
}

// ---------------------------------------------------------------------------
// apply width / height
// ---------------------------------------------------------------------------
__global__ __launch_bounds__(256) void apply_slice_w_kernel(
    const float* __restrict__ xin, float* __restrict__ xout, const float* __restrict__ beta_p)
{
    __shared__ __align__(16) __nv_bfloat16 As[128][104];
    __shared__ __align__(16) __nv_bfloat16 Bs[96][104];

    int b = blockIdx.y, m0 = blockIdx.x * 128;
    int tid = threadIdx.x, wid = tid >> 5, lane = tid & 31;
    int mw = (wid >> 1) * 32, nw = (wid & 1) * 48;
    int g = lane >> 2, tg = lane & 3;

    const __nv_bfloat16* gsrc = g_gb + (size_t)b * CC * HWSZ + (size_t)m0 * 96;
    const __nv_bfloat16* psrc = g_Pb + (size_t)b * 9216;
    #pragma unroll
    for (int j = 0; j < 6; j++) {
        int c = j * 256 + tid;
        int row = c / 12, col = (c % 12) * 8;
        cpa16(smem_u32(&As[row][col]), gsrc + row*96 + col);
    }
    #pragma unroll
    for (int j = 0; j < 5; j++) {
        int c = j * 256 + tid;
        if (c < 1152) {
            int row = c / 12, col = (c % 12) * 8;
            cpa16(smem_u32(&Bs[row][col]), psrc + row*96 + col);
        }
    }
    CP_COMMIT();
    cp_wait<0>();
    __syncthreads();

    float acc[2][6][4] = {};
    #pragma unroll
    for (int ks = 0; ks < 6; ks++) {
        int k0 = ks * 16;
        uint32_t a[2][4], bf[6][2];
        #pragma unroll
        for (int mf = 0; mf < 2; mf++)
            ldsm4(a[mf][0], a[mf][1], a[mf][2], a[mf][3],
                  smem_u32(&As[mw + mf*16 + (lane&15)][k0 + (lane>>4)*8]));
        #pragma unroll
        for (int nb = 0; nb < 3; nb++)
            ldsm4(bf[nb*2][0], bf[nb*2][1], bf[nb*2+1][0], bf[nb*2+1][1],
                  smem_u32(&Bs[nw + nb*16 + (lane>>4)*8 + (lane&7)][k0 + ((lane>>3)&1)*8]));
        #pragma unroll
        for (int mf = 0; mf < 2; mf++)
            #pragma unroll
            for (int nf = 0; nf < 6; nf++)
                mma_bf16(acc[mf][nf], a[mf][0], a[mf][1], a[mf][2], a[mf][3],
                         bf[nf][0], bf[nf][1]);
    }
    float beta = *beta_p;
    size_t gb = (size_t)b * CC * HWSZ;
    #pragma unroll
    for (int mf = 0; mf < 2; mf++) {
        int r1 = m0 + mw + mf * 16 + g, r2 = r1 + 8;
        #pragma unroll
        for (int nf = 0; nf < 6; nf++) {
            int col = nw + nf * 8 + tg * 2;
            size_t o1 = gb + (size_t)r1 * 96 + col;
            size_t o2 = gb + (size_t)r2 * 96 + col;
            float2 xa = *(const float2*)&xin[o1];
            float2 xb2 = *(const float2*)&xin[o2];
            float v0 = xa.x + beta*acc[mf][nf][0], v1 = xa.y + beta*acc[mf][nf][1];
            float v2 = xb2.x + beta*acc[mf][nf][2], v3 = xb2.y + beta*acc[mf][nf][3];
            *(float2*)&xout[o1] = make_float2(v0, v1);
            *(float2*)&xout[o2] = make_float2(v2, v3);
            *(uint32_t*)&g_xb[o1] = packbf(v0, v1);
            *(uint32_t*)&g_xb[o2] = packbf(v2, v3);
        }
    }
}

__global__ __launch_bounds__(256) void apply_slice_h_kernel(
    const float* __restrict__ xin, float* __restrict__ xout, const float* __restrict__ beta_p)
{
    __shared__ __align__(16) __nv_bfloat16 As[96][104];
    __shared__ __align__(16) __nv_bfloat16 Bs[96][104];

    int b = blockIdx.y, c = blockIdx.x;
    int tid = threadIdx.x, wid = tid >> 5, lane = tid & 31;
    int mw = (wid >> 2) * 48, nw = (wid & 3) * 24;
    int g = lane >> 2, tg = lane & 3;

    const __nv_bfloat16* psrc = g_Pb + (size_t)b * 9216;
    const __nv_bfloat16* gsrc = g_gb + ((size_t)b * CC + c) * HWSZ;
    #pragma unroll
    for (int j = 0; j < 9; j++) {
        int cidx = j * 256 + tid;
        int c2 = (cidx < 1152) ? cidx : cidx - 1152;
        int row = c2 / 12, col = (c2 % 12) * 8;
        if (cidx < 1152) cpa16(smem_u32(&As[row][col]), psrc + row*96 + col);
        else             cpa16(smem_u32(&Bs[row][col]), gsrc + row*96 + col);
    }
    CP_COMMIT();
    cp_wait<0>();
    __syncthreads();

    float acc[3][3][4] = {};
    #pragma unroll
    for (int ks = 0; ks < 6; ks++) {
        int k0 = ks * 16;
        uint32_t a[3][4], bf[3][2];
        #pragma unroll
        for (int mf = 0; mf < 3; mf++)
            ldsm4(a[mf][0], a[mf][1], a[mf][2], a[mf][3],
                  smem_u32(&As[mw + mf*16 + (lane&15)][k0 + (lane>>4)*8]));
        ldsm4t(bf[0][0], bf[0][1], bf[1][0], bf[1][1],
               smem_u32(&Bs[k0 + (lane&15)][nw + (lane>>4)*8]));
        ldsm2t(bf[2][0], bf[2][1],
               smem_u32(&Bs[k0 + (lane&15)][nw + 16]));
        #pragma unroll
        for (int mf = 0; mf < 3; mf++)
            #pragma unroll
            for (int nf = 0; nf < 3; nf++)
                mma_bf16(acc[mf][nf], a[mf][0], a[mf][1], a[mf][2], a[mf][3],
                         bf[nf][0], bf[nf][1]);
    }
    float beta = *beta_p;
    size_t base = ((size_t)b * CC + c) * HWSZ;
    #pragma unroll
    for (int mf = 0; mf < 3; mf++) {
        int i1 = mw + mf * 16 + g, i2 = i1 + 8;
        #pragma unroll
        for (int nf = 0; nf < 3; nf++) {
            int col = nw + nf * 8 + tg * 2;
            size_t o1 = base + (size_t)i1 * 96 + col;
            size_t o2 = base + (size_t)i2 * 96 + col;
            float2 xa = *(const float2*)&xin[o1];
            float2 xb2 = *(const float2*)&xin[o2];
            float v0 = xa.x + beta*acc[mf][nf][0], v1 = xa.y + beta*acc[mf][nf][1];
            float v2 = xb2.x + beta*acc[mf][nf][2], v3 = xb2.y + beta*acc[mf][nf][3];
            *(float2*)&xout[o1] = make_float2(v0, v1);
            *(float2*)&xout[o2] = make_float2(v2, v3);
            *(uint32_t*)&g_xb[o1] = packbf(v0, v1);
            *(uint32_t*)&g_xb[o2] = packbf(v2, v3);
        }
    }
}

// ---------------------------------------------------------------------------
// Gram: 128x128 tiles, symmetric (3 tile-blocks per b), BK=32 double-buffered.
// ---------------------------------------------------------------------------
__global__ __launch_bounds__(256) void gram_kernel()
{
    __shared__ __align__(16) __nv_bfloat16 Asm[2][128][40];
    __shared__ __align__(16) __nv_bfloat16 Bsm[2][128][40];

    int ti = blockIdx.x, b = blockIdx.y;
    int i0 = (ti == 2) ? 128 : 0;
    int j0 = (ti == 0) ? 0 : 128;
    int tid = threadIdx.x, wid = tid >> 5, lane = tid & 31;
    int mw = (wid >> 2) * 64, nw = (wid & 3) * 32;
    int g = lane >> 2, tg = lane & 3;

    int row = tid >> 1, cb = (tid & 1) * 16;
    const __nv_bfloat16* as0 = g_xb + ((size_t)b * CC + i0 + row) * HWSZ + cb;
    const __nv_bfloat16* bs0 = g_xb + ((size_t)b * CC + j0 + row) * HWSZ + cb;

    float acc[4][4][4] = {};

    auto stage = [&](int kk, int bi) {
        uint32_t ad = smem_u32(&Asm[bi][row][cb]);
        uint32_t bd = smem_u32(&Bsm[bi][row][cb]);
        cpa16(ad, as0 + kk); cpa16(ad + 16, as0 + kk + 8);
        cpa16(bd, bs0 + kk); cpa16(bd + 16, bs0 + kk + 8);
        CP_COMMIT();
    };

    stage(0, 0);
    for (int s = 0; s < 288; s++) {
        if (s < 287) { stage((s + 1) * 32, (s + 1) & 1); cp_wait<1>(); }
        else cp_wait<0>();
        __syncthreads();
        mma_tileNN<40, 40, 2>(&Asm[s&1][0][0], &Bsm[s&1][0][0], mw, nw, lane, acc);
        __syncthreads();
    }
    float* Gb = g_G + (size_t)b * 65536;
    #pragma unroll
    for (int mf = 0; mf < 4; mf++) {
        int i1 = i0 + mw + mf * 16 + g, i2 = i1 + 8;
        #pragma unroll
        for (int nf = 0; nf < 4; nf++) {
            int jc = j0 + nw + nf * 8 + tg * 2;
            *(float2*)&Gb[(size_t)i1 * 256 + jc] = make_float2(acc[mf][nf][0], acc[mf][nf][1]);
            *(float2*)&Gb[(size_t)i2 * 256 + jc] = make_float2(acc[mf][nf][2], acc[mf][nf][3]);
            if (ti == 1) {
                Gb[(size_t)jc * 256 + i1]       = acc[mf][nf][0];
                Gb[(size_t)(jc + 1) * 256 + i1] = acc[mf][nf][1];
                Gb[(size_t)jc * 256 + i2]       = acc[mf][nf][2];
                Gb[(size_t)(jc + 1) * 256 + i2] = acc[mf][nf][3];
            }
        }
    }
}

// xs2[b,c] = sum_hw x[b,c,:]
__global__ __launch_bounds__(256) void xsum2_kernel()
{
    int k = blockIdx.x, b = blockIdx.y, tid = threadIdx.x;
    const __nv_bfloat16* src = g_xb + ((size_t)b * CC + k) * HWSZ;
    __shared__ float red[8];
    float s = 0.f;
    for (int e = tid; e < HWSZ; e += 256) s += __bfloat162float(src[e]);
    #pragma unroll
    for (int o = 16; o; o >>= 1) s += __shfl_xor_sync(0xffffffffu, s, o);
    if ((tid & 31) == 0) red[tid >> 5] = s;
    __syncthreads();
    if (tid == 0) {
        float t = 0.f;
        #pragma unroll
        for (int w = 0; w < 8; w++) t += red[w];
        g_xs2[b * CC + k] = t;
    }
}

__global__ __launch_bounds__(256) void sAsB_kernel(const float* __restrict__ wt,
                                                   const float* __restrict__ wp,
                                                   const float* __restrict__ bp)
{
    int i = blockIdx.x, b = blockIdx.y, c = threadIdx.x;
    __shared__ float r1[8], r2[8];
    float xv = g_xs2[b*CC + c];
    float sa = wt[i*256 + c] * xv;
    float sb = wp[i*256 + c] * xv;
    #pragma unroll
    for (int off = 16; off; off >>= 1) {
        sa += __shfl_xor_sync(0xffffffffu, sa, off);
        sb += __shfl_xor_sync(0xffffffffu, sb, off);
    }
    if ((c & 31) == 0) { r1[c>>5] = sa; r2[c>>5] = sb; }
    __syncthreads();
    if (c == 0) {
        float a = 0.f, b2 = 0.f;
        #pragma unroll
        for (int w = 0; w < 8; w++) { a += r1[w]; b2 += r2[w]; }
        g_sA[b*CC + i] = a;
        g_sB2[b*CC + i] = b2 + 9216.f * bp[i];
    }
}

// ---------------------------------------------------------------------------
// fp32 GEMM NN: T1[b] = wt @ G[b]. Tile 64x64, BK=16.
// ---------------------------------------------------------------------------
__global__ __launch_bounds__(256) void f32gemm_nn_kernel(const float* __restrict__ wt)
{
    int b  = blockIdx.z;
    int i0 = blockIdx.y * 64;
    int n0 = blockIdx.x * 64;

    __shared__ __align__(16) float As[16 * 68];
    __shared__ __align__(16) float Gs[16 * 68];

    int tid = threadIdx.x;
    int ti4 = (tid >> 4) * 4, tj4 = (tid & 15) * 4;
    float acc[4][4] = {};

    const float* Gb = g_G + (size_t)b * 65536;

    for (int kk = 0; kk < 256; kk += 16) {
        #pragma unroll
        for (int rr = 0; rr < 4; rr++) {
            int r = rr * 16 + (tid >> 4);
            int cload = tid & 15;
            As[cload * 68 + r] = wt[(i0 + r) * 256 + kk + cload];
        }
        #pragma unroll
        for (int rr = 0; rr < 4; rr++) {
            int k = rr * 4 + (tid >> 6);
            int n = tid & 63;
            Gs[k * 68 + n] = Gb[(size_t)(kk + k) * 256 + n0 + n];
        }
        __syncthreads();
        #pragma unroll
        for (int k = 0; k < 16; k++) {
            float4 a = *(float4*)&As[k * 68 + ti4];
            float4 g4 = *(float4*)&Gs[k * 68 + tj4];
            float ar[4] = {a.x, a.y, a.z, a.w};
            float gr[4] = {g4.x, g4.y, g4.z, g4.w};
            #pragma unroll
            for (int i = 0; i < 4; i++)
                #pragma unroll
                for (int j = 0; j < 4; j++)
                    acc[i][j] += ar[i] * gr[j];
        }
        __syncthreads();
    }

    float* T1b = g_T1 + (size_t)b * 65536;
    #pragma unroll
    for (int i = 0; i < 4; i++)
        #pragma unroll
        for (int j = 0; j < 4; j++)
            T1b[(size_t)(i0 + ti4 + i) * 256 + n0 + tj4 + j] = acc[i][j];
}

// ---------------------------------------------------------------------------
// fp32 GEMM NT + channel-bias epilogue.
// ---------------------------------------------------------------------------
__global__ __launch_bounds__(256) void f32gemm_nt_kernel(const float* __restrict__ wp,
                                                         const float* __restrict__ bt,
                                                         const float* __restrict__ bp)
{
    int b  = blockIdx.z;
    int i0 = blockIdx.y * 64;
    int j0 = blockIdx.x * 64;

    __shared__ __align__(16) float Ts[32 * 68];
    __shared__ __align__(16) float Ps[32 * 68];

    int tid = threadIdx.x;
    int lc = tid & 31, lr = tid >> 5;
    int ti4 = (tid >> 4) * 4, tj4 = (tid & 15) * 4;

    float acc[4][4] = {};
    const float* T1b = g_T1 + (size_t)b * 65536;

    for (int kb = 0; kb < 8; kb++) {
        int k0 = kb * 32;
        #pragma unroll
        for (int rr = 0; rr < 8; rr++) {
            int r = rr * 8 + lr;
            Ts[lc * 68 + r] = T1b[(size_t)(i0 + r) * 256 + k0 + lc];
            Ps[lc * 68 + r] = wp[(j0 + r) * 256 + k0 + lc];
        }
        __syncthreads();
        #pragma unroll
        for (int k = 0; k < 32; k++) {
            float4 a = *(float4*)&Ts[k * 68 + ti4];
            float4 p = *(float4*)&Ps[k * 68 + tj4];
            float ar[4] = {a.x, a.y, a.z, a.w};
            float pr[4] = {p.x, p.y, p.z, p.w};
            #pragma unroll
            for (int i = 0; i < 4; i++)
                #pragma unroll
                for (int j = 0; j < 4; j++)
                    acc[i][j] += ar[i] * pr[j];
        }
        __syncthreads();
    }

    float* Sb = g_S + (size_t)b * 65536;
    #pragma unroll
    for (int i = 0; i < 4; i++) {
        int irow = i0 + ti4 + i;
        float bti = bt[irow], sai = g_sA[b*CC + irow];
        #pragma unroll
        for (int j = 0; j < 4; j++) {
            int jcol = j0 + tj4 + j;
            Sb[(size_t)irow * 256 + jcol] =
                acc[i][j] + bti * g_sB2[b*CC + jcol] + bp[jcol] * sai;
        }
    }
}

// ---------------------------------------------------------------------------
extern "C" void kernel_launch(void* const* d_in, const int* in_sizes, int n_in,
                              void* d_out, int out_size)
{
    const float* x      = (const float*)d_in[0];
    const float* wt     = (const float*)d_in[1];
    const float* bt     = (const float*)d_in[2];
    const float* wp     = (const float*)d_in[3];
    const float* bp     = (const float*)d_in[4];
    const float* wg     = (const float*)d_in[5];
    const float* bg     = (const float*)d_in[6];
    const float* beta_w = (const float*)d_in[7];
    const float* beta_h = (const float*)d_in[8];
    const float* beta_c = (const float*)d_in[9];
    float* out = (float*)d_out;

    float *x1, *x2, *S, *uu, *vv, *c0;
    __nv_bfloat16 *thb, *gbb, *W2, *xbb, *Wbf;
    cudaGetSymbolAddress((void**)&x1, g_x1);
    cudaGetSymbolAddress((void**)&x2, g_x2);
    cudaGetSymbolAddress((void**)&S,  g_S);
    cudaGetSymbolAddress((void**)&uu, g_u);
    cudaGetSymbolAddress((void**)&vv, g_v);
    cudaGetSymbolAddress((void**)&c0, g_c0);
    cudaGetSymbolAddress((void**)&thb, g_thb);
    cudaGetSymbolAddress((void**)&gbb, g_gb);
    cudaGetSymbolAddress((void**)&W2,  g_W2);
    cudaGetSymbolAddress((void**)&xbb, g_xb);
    cudaGetSymbolAddress((void**)&Wbf, g_Wbf);

    int panel_smem = 256*136*2 + 3*128*40*2;      // 100,352 B
    int slice_smem = 4 * 96 * 104 * 2;            // 79,872 B
    cudaFuncSetAttribute(conv_panel_kernel,
                         cudaFuncAttributeMaxDynamicSharedMemorySize, panel_smem);
    cudaFuncSetAttribute(apply_channel_panel_kernel,
                         cudaFuncAttributeMaxDynamicSharedMemorySize, panel_smem);
    cudaFuncSetAttribute(slice_logits_bf16_kernel<0>,
                         cudaFuncAttributeMaxDynamicSharedMemorySize, slice_smem);
    cudaFuncSetAttribute(slice_logits_bf16_kernel<1>,
                         cudaFuncAttributeMaxDynamicSharedMemorySize, slice_smem);

    static cudaStream_t s2 = nullptr;
    static cudaEvent_t ev[8];
    if (!s2) {
        cudaStreamCreateWithFlags(&s2, cudaStreamNonBlocking);
        for (int i = 0; i < 8; i++)
            cudaEventCreateWithFlags(&ev[i], cudaEventDisableTiming);
    }
    cudaStream_t s0 = 0;

    // ---- prologue ----
    xconv_kernel<<<NELEM / (256 * 8), 256, 0, s0>>>(x);
    cudaEventRecord(ev[0], s0);                               // g_xb ready

    cudaStreamWaitEvent(s2, ev[0], 0);                        // fork s2
    wconv_kernel<<<768, 256, 0, s2>>>(wt, wp, wg);
    mprep_kernel<<<dim3(4, 4), 128, 0, s2>>>();
    cudaEventRecord(ev[1], s2);                               // W2 ready
    biasvec_kernel<<<256, 256, 0, s2>>>(wt, wp, bt, bp);
    cudaMemsetAsync(S, 0, (size_t)16 * 9216 * sizeof(float), s2);
    xsum_kernel<0><<<dim3(256, 16), 96, 0, s2>>>();
    uv_kernel<<<16, 96, 0, s2>>>();
    cudaEventRecord(ev[2], s2);                               // S zeroed + u/v ready

    // ---- round 1: width attention ----
    cudaStreamWaitEvent(s0, ev[1], 0);
    conv_panel_kernel<<<dim3(72, 1, 16), 256, panel_smem, s0>>>(W2, 4, thb, nullptr, gbb, bg);
    cudaStreamWaitEvent(s0, ev[2], 0);
    slice_logits_bf16_kernel<0><<<dim3(16, 16), 256, slice_smem, s0>>>(xbb, thb);
    softmax_kernel<<<16 * 96, 256, 0, s0>>>(96, uu, vv, c0);
    apply_slice_w_kernel<<<dim3(192, 16), 256, 0, s0>>>(x, x1, beta_w);
    cudaEventRecord(ev[3], s0);                               // new x (g_xb) ready

    // ---- round 2: height attention ----
    cudaStreamWaitEvent(s2, ev[3], 0);
    cudaMemsetAsync(S, 0, (size_t)16 * 9216 * sizeof(float), s2);
    xsum_kernel<1><<<dim3(256, 16), 96, 0, s2>>>();
    uv_kernel<<<16, 96, 0, s2>>>();
    cudaEventRecord(ev[4], s2);

    conv_panel_kernel<<<dim3(72, 1, 16), 256, panel_smem, s0>>>(W2, 4, thb, nullptr, gbb, bg);
    cudaStreamWaitEvent(s0, ev[4], 0);
    slice_logits_bf16_kernel<1><<<dim3(16, 16), 256, slice_smem, s0>>>(xbb, thb);
    softmax_kernel<<<16 * 96, 256, 0, s0>>>(96, uu, vv, c0);
    apply_slice_h_kernel<<<dim3(256, 16), 256, 0, s0>>>(x1, x2, beta_h);
    cudaEventRecord(ev[5], s0);                               // new x (g_xb) ready

    // ---- round 3: channel attention ----
    cudaStreamWaitEvent(s2, ev[5], 0);
    xsum2_kernel<<<dim3(256, 16), 256, 0, s2>>>();
    sAsB_kernel<<<dim3(256, 16), 256, 0, s2>>>(wt, wp, bp);
    gram_kernel<<<dim3(3, 16), 256, 0, s2>>>();
    cudaEventRecord(ev[6], s2);                               // G + sA/sB2 ready

    conv_panel_kernel<<<dim3(72, 1, 16), 256, panel_smem, s0>>>(Wbf + 2*65536, 2, gbb, bg, gbb, bg);
    cudaStreamWaitEvent(s0, ev[6], 0);
    f32gemm_nn_kernel<<<dim3(4, 4, 16), 256, 0, s0>>>(wt);
    f32gemm_nt_kernel<<<dim3(4, 4, 16), 256, 0, s0>>>(wp, bt, bp);
    softmax_kernel<<<16 * 256, 256, 0, s0>>>(256, nullptr, nullptr, nullptr);
    apply_channel_panel_kernel<<<dim3(72, 1, 16), 256, panel_smem, s0>>>(x2, out, beta_c);
}

// round 13
// speedup vs baseline: 1.0489x; 1.0046x over previous
#include <cuda_runtime.h>
#include <cuda_bf16.h>
#include <math.h>
#include <stdint.h>

#define BB 16
#define CC 256
#define HH 96
#define WW 96
#define HWSZ (HH*WW)           // 9216
#define NELEM (BB*CC*HWSZ)     // 37,748,736

// Scratch (device globals: allocation-free rule)
__device__ __nv_bfloat16 g_thb[NELEM];       // y = M x (rounds 1-2)
__device__ __nv_bfloat16 g_gb[NELEM];        // g = Wg x + bg
__device__ __nv_bfloat16 g_xb[NELEM];        // bf16 mirror of current x
__device__ float g_x1[NELEM];
__device__ float g_x2[NELEM];
__device__ float g_S[BB*CC*CC];              // logits fp32
__device__ __nv_bfloat16 g_Pb[BB*CC*CC];     // probabilities bf16
__device__ __nv_bfloat16 g_Wbf[3*CC*CC];     // [Wt; Wp; Wg] bf16
__device__ __nv_bfloat16 g_W2[2*CC*CC];      // [M = Wt^T Wp ; Wg] bf16 (512x256)
__device__ float g_G[BB*CC*CC];              // Gram X X^T fp32
__device__ float g_T1[BB*CC*CC];             // Wt @ G fp32
__device__ float g_xs[BB*CC*96];             // per-axis sums of x
__device__ float g_xs2[BB*CC];               // full-hw sums of x
__device__ float g_u[BB*96];
__device__ float g_v[BB*96];
__device__ float g_w1[CC];
__device__ float g_w2[CC];
__device__ float g_c0[1];
__device__ float g_sA[BB*CC];
__device__ float g_sB2[BB*CC];

// ---------------------------------------------------------------------------
// helpers
// ---------------------------------------------------------------------------
__device__ __forceinline__ uint32_t smem_u32(const void* p) {
    return (uint32_t)__cvta_generic_to_shared(p);
}
__device__ __forceinline__ uint32_t packbf(float lo, float hi) {
    __nv_bfloat162 h = __floats2bfloat162_rn(lo, hi);
    return *(uint32_t*)&h;
}
__device__ __forceinline__ void cpa16(uint32_t dst, const void* src) {
    asm volatile("cp.async.cg.shared.global [%0], [%1], 16;" :: "r"(dst), "l"(src));
}
#define CP_COMMIT() asm volatile("cp.async.commit_group;")
template<int N> __device__ __forceinline__ void cp_wait() {
    asm volatile("cp.async.wait_group %0;" :: "n"(N));
}
__device__ __forceinline__ void ldsm4(uint32_t& r0, uint32_t& r1, uint32_t& r2, uint32_t& r3, uint32_t a) {
    asm volatile("ldmatrix.sync.aligned.m8n8.x4.shared.b16 {%0,%1,%2,%3},[%4];"
                 : "=r"(r0), "=r"(r1), "=r"(r2), "=r"(r3) : "r"(a));
}
__device__ __forceinline__ void ldsm4t(uint32_t& r0, uint32_t& r1, uint32_t& r2, uint32_t& r3, uint32_t a) {
    asm volatile("ldmatrix.sync.aligned.m8n8.x4.trans.shared.b16 {%0,%1,%2,%3},[%4];"
                 : "=r"(r0), "=r"(r1), "=r"(r2), "=r"(r3) : "r"(a));
}
__device__ __forceinline__ void ldsm2(uint32_t& r0, uint32_t& r1, uint32_t a) {
    asm volatile("ldmatrix.sync.aligned.m8n8.x2.shared.b16 {%0,%1},[%2];"
                 : "=r"(r0), "=r"(r1) : "r"(a));
}
__device__ __forceinline__ void ldsm2t(uint32_t& r0, uint32_t& r1, uint32_t a) {
    asm volatile("ldmatrix.sync.aligned.m8n8.x2.trans.shared.b16 {%0,%1},[%2];"
                 : "=r"(r0), "=r"(r1) : "r"(a));
}
__device__ __forceinline__ void mma_bf16(float (&d)[4], uint32_t a0, uint32_t a1, uint32_t a2, uint32_t a3,
                                         uint32_t b0, uint32_t b1) {
    asm volatile(
        "mma.sync.aligned.m16n8k16.row.col.f32.bf16.bf16.f32 "
        "{%0,%1,%2,%3},{%4,%5,%6,%7},{%8,%9},{%0,%1,%2,%3};"
        : "+f"(d[0]), "+f"(d[1]), "+f"(d[2]), "+f"(d[3])
        : "r"(a0), "r"(a1), "r"(a2), "r"(a3), "r"(b0), "r"(b1));
}

// 128(M)x128(N) tile step: A [m][k] non-trans lda=LDA, B [k][n] trans ldb=LDB, KS k-steps.
template<int LDA, int LDB, int KS>
__device__ __forceinline__ void mma_tileT(const __nv_bfloat16* As, const __nv_bfloat16* Bs,
                                          int mw, int nw, int lane, float (&acc)[4][4][4])
{
    #pragma unroll
    for (int ks = 0; ks < KS; ks++) {
        int k0 = ks * 16;
        uint32_t a[4][4], bf[4][2];
        #pragma unroll
        for (int mf = 0; mf < 4; mf++)
            ldsm4(a[mf][0], a[mf][1], a[mf][2], a[mf][3],
                  smem_u32(As + (mw + mf*16 + (lane & 15)) * LDA + k0 + (lane >> 4) * 8));
        #pragma unroll
        for (int nb = 0; nb < 2; nb++)
            ldsm4t(bf[nb*2][0], bf[nb*2][1], bf[nb*2+1][0], bf[nb*2+1][1],
                   smem_u32(Bs + (k0 + (lane & 15)) * LDB + nw + nb*16 + (lane >> 4) * 8));
        #pragma unroll
        for (int mf = 0; mf < 4; mf++)
            #pragma unroll
            for (int nf = 0; nf < 4; nf++)
                mma_bf16(acc[mf][nf], a[mf][0], a[mf][1], a[mf][2], a[mf][3],
                         bf[nf][0], bf[nf][1]);
    }
}

// 128x128 tile step, B [n][k] non-trans (for gram).
template<int LDA, int LDB, int KS>
__device__ __forceinline__ void mma_tileNN(const __nv_bfloat16* As, const __nv_bfloat16* Bs,
                                           int mw, int nw, int lane, float (&acc)[4][4][4])
{
    #pragma unroll
    for (int ks = 0; ks < KS; ks++) {
        int k0 = ks * 16;
        uint32_t a[4][4], bf[4][2];
        #pragma unroll
        for (int mf = 0; mf < 4; mf++)
            ldsm4(a[mf][0], a[mf][1], a[mf][2], a[mf][3],
                  smem_u32(As + (mw + mf*16 + (lane & 15)) * LDA + k0 + (lane >> 4) * 8));
        #pragma unroll
        for (int nb = 0; nb < 2; nb++)
            ldsm4(bf[nb*2][0], bf[nb*2][1], bf[nb*2+1][0], bf[nb*2+1][1],
                  smem_u32(Bs + (nw + nb*16 + (lane>>4)*8 + (lane&7)) * LDB + k0 + ((lane>>3)&1)*8));
        #pragma unroll
        for (int mf = 0; mf < 4; mf++)
            #pragma unroll
            for (int nf = 0; nf < 4; nf++)
                mma_bf16(acc[mf][nf], a[mf][0], a[mf][1], a[mf][2], a[mf][3],
                         bf[nf][0], bf[nf][1]);
    }
}

// ---------------------------------------------------------------------------
// one-time converts / precomputes
// ---------------------------------------------------------------------------
__global__ void wconv_kernel(const float* __restrict__ wt, const float* __restrict__ wp,
                             const float* __restrict__ wg) {
    int i = blockIdx.x * 256 + threadIdx.x;
    const float* src = (i < 65536) ? wt : (i < 131072 ? wp : wg);
    __nv_bfloat16 v = __float2bfloat16(src[i & 65535]);
    g_Wbf[i] = v;
    if (i >= 131072) g_W2[65536 + (i - 131072)] = v;
}
__global__ void xconv_kernel(const float* __restrict__ x) {
    size_t base = ((size_t)blockIdx.x * 256 + threadIdx.x) * 8;
    float4 f0 = *(const float4*)(x + base);
    float4 f1 = *(const float4*)(x + base + 4);
    uint4 v;
    v.x = packbf(f0.x, f0.y); v.y = packbf(f0.z, f0.w);
    v.z = packbf(f1.x, f1.y); v.w = packbf(f1.z, f1.w);
    *(uint4*)(g_xb + base) = v;
}

// M = Wt^T Wp (256x256) -> g_W2 rows 0-255. Tile 64x64, K=256, 4 warps (2x2).
__global__ __launch_bounds__(128) void mprep_kernel()
{
    __shared__ __align__(16) __nv_bfloat16 As[64][72];
    __shared__ __align__(16) __nv_bfloat16 Bs[64][72];

    int m0 = blockIdx.y * 64, n0 = blockIdx.x * 64;
    int tid = threadIdx.x, wid = tid >> 5, lane = tid & 31;
    int mw = (wid >> 1) * 32, nw = (wid & 1) * 32;
    int g = lane >> 2, tg = lane & 3;

    float acc[2][4][4] = {};
    int cr = tid >> 1, mc = (tid & 1) * 32;

    for (int kk = 0; kk < 256; kk += 64) {
        uint32_t ad = smem_u32(&As[cr][mc]);
        uint32_t bd = smem_u32(&Bs[cr][mc]);
        const __nv_bfloat16* asrc = g_Wbf + (size_t)(kk + cr) * 256 + m0 + mc;
        const __nv_bfloat16* bsrc = g_Wbf + 65536 + (size_t)(kk + cr) * 256 + n0 + mc;
        #pragma unroll
        for (int j = 0; j < 4; j++) { cpa16(ad + j*16, asrc + j*8); cpa16(bd + j*16, bsrc + j*8); }
        CP_COMMIT();
        cp_wait<0>();
        __syncthreads();
        #pragma unroll
        for (int ks = 0; ks < 4; ks++) {
            int k0 = ks * 16;
            uint32_t a[2][4], bf[4][2];
            #pragma unroll
            for (int mf = 0; mf < 2; mf++)
                ldsm4t(a[mf][0], a[mf][1], a[mf][2], a[mf][3],
                    smem_u32(&As[k0 + ((lane>>4)&1)*8 + (lane&7)][mw + mf*16 + ((lane>>3)&1)*8]));
            ldsm4t(bf[0][0], bf[0][1], bf[1][0], bf[1][1],
                   smem_u32(&Bs[k0 + (lane&15)][nw + (lane>>4)*8]));
            ldsm4t(bf[2][0], bf[2][1], bf[3][0], bf[3][1],
                   smem_u32(&Bs[k0 + (lane&15)][nw + 16 + (lane>>4)*8]));
            #pragma unroll
            for (int mf = 0; mf < 2; mf++)
                #pragma unroll
                for (int nf = 0; nf < 4; nf++)
                    mma_bf16(acc[mf][nf], a[mf][0], a[mf][1], a[mf][2], a[mf][3],
                             bf[nf][0], bf[nf][1]);
        }
        __syncthreads();
    }
    #pragma unroll
    for (int mf = 0; mf < 2; mf++) {
        int r1 = m0 + mw + mf*16 + g, r2 = r1 + 8;
        #pragma unroll
        for (int nf = 0; nf < 4; nf++) {
            int col = n0 + nw + nf*8 + tg*2;
            *(uint32_t*)&g_W2[r1*256 + col] = packbf(acc[mf][nf][0], acc[mf][nf][1]);
            *(uint32_t*)&g_W2[r2*256 + col] = packbf(acc[mf][nf][2], acc[mf][nf][3]);
        }
    }
}

// bias fold vectors
__global__ __launch_bounds__(256) void biasvec_kernel(const float* __restrict__ wt,
                                                      const float* __restrict__ wp,
                                                      const float* __restrict__ bt,
                                                      const float* __restrict__ bp)
{
    int k = blockIdx.x, o = threadIdx.x;
    __shared__ float r1[8], r2[8], r3[8];
    float btv = bt[o], bpv = bp[o];
    float s1 = wt[o*256 + k] * bpv;
    float s2 = wp[o*256 + k] * btv;
    float c  = btv * bpv;
    #pragma unroll
    for (int off = 16; off; off >>= 1) {
        s1 += __shfl_xor_sync(0xffffffffu, s1, off);
        s2 += __shfl_xor_sync(0xffffffffu, s2, off);
        c  += __shfl_xor_sync(0xffffffffu, c, off);
    }
    if ((o & 31) == 0) { r1[o>>5] = s1; r2[o>>5] = s2; r3[o>>5] = c; }
    __syncthreads();
    if (o == 0) {
        float a = 0.f, b2 = 0.f, cc = 0.f;
        #pragma unroll
        for (int w = 0; w < 8; w++) { a += r1[w]; b2 += r2[w]; cc += r3[w]; }
        g_w1[k] = a; g_w2[k] = b2;
        if (k == 0) g_c0[0] = 96.f * cc;
    }
}

// ---------------------------------------------------------------------------
// conv panel: B panel (256K x 128N of xb) resident in smem; loop mtiles of A.
// BK=32 double-buffered A chunks (R8 champion config).
// ---------------------------------------------------------------------------
__global__ __launch_bounds__(256) void conv_panel_kernel(
    const __nv_bfloat16* __restrict__ W, int mtiles,
    __nv_bfloat16* dst0, const float* bias0,
    __nv_bfloat16* dst1, const float* bias1)
{
    extern __shared__ __align__(16) __nv_bfloat16 dynsm[];
    __nv_bfloat16* Bs = dynsm;                               // [256][136]
    __nv_bfloat16* Ab[2] = { dynsm + 256*136, dynsm + 256*136 + 128*40 };

    int b = blockIdx.z, n0 = blockIdx.x * 128;
    int tid = threadIdx.x, wid = tid >> 5, lane = tid & 31;
    int mw = (wid >> 2) * 64, nw = (wid & 3) * 32;
    int g = lane >> 2, tg = lane & 3;

    const __nv_bfloat16* bbase = g_xb + (size_t)b * CC * HWSZ + n0;
    #pragma unroll
    for (int j = 0; j < 16; j++) {
        int idx = j * 256 + tid;
        int row = idx >> 4, cb8 = (idx & 15) * 8;
        cpa16(smem_u32(Bs + row*136 + cb8), bbase + (size_t)row * HWSZ + cb8);
    }
    CP_COMMIT();

    int arow = tid >> 1, acb = (tid & 1) * 16;

    for (int mt = 0; mt < mtiles; mt++) {
        int mbase = mt * 128;
        const __nv_bfloat16* asrc = W + (size_t)(mbase + arow) * 256 + acb;
        {
            uint32_t ad = smem_u32(Ab[0] + arow*40 + acb);
            cpa16(ad, asrc); cpa16(ad + 16, asrc + 8);
            CP_COMMIT();
        }
        float acc[4][4][4] = {};
        for (int kc = 0; kc < 8; kc++) {
            if (kc < 7) {
                uint32_t ad = smem_u32(Ab[(kc+1)&1] + arow*40 + acb);
                const __nv_bfloat16* as = asrc + (kc + 1) * 32;
                cpa16(ad, as); cpa16(ad + 16, as + 8);
                CP_COMMIT();
                cp_wait<1>();
            } else cp_wait<0>();
            __syncthreads();
            mma_tileT<40, 136, 2>(Ab[kc&1], Bs + kc*32*136, mw, nw, lane, acc);
            __syncthreads();
        }
        int mat = mbase >> 8, ob = mbase & 255;
        __nv_bfloat16* dst = mat ? dst1 : dst0;
        const float* bias = mat ? bias1 : bias0;
        #pragma unroll
        for (int mf = 0; mf < 4; mf++) {
            int r = mw + mf * 16 + g;
            int o1 = ob + r, o2 = o1 + 8;
            float b1 = bias ? bias[o1] : 0.f;
            float b2 = bias ? bias[o2] : 0.f;
            size_t base1 = ((size_t)b * CC + o1) * HWSZ + n0;
            size_t base2 = ((size_t)b * CC + o2) * HWSZ + n0;
            #pragma unroll
            for (int nf = 0; nf < 4; nf++) {
                int col = nw + nf * 8 + tg * 2;
                *(uint32_t*)&dst[base1 + col] = packbf(acc[mf][nf][0] + b1, acc[mf][nf][1] + b1);
                *(uint32_t*)&dst[base2 + col] = packbf(acc[mf][nf][2] + b2, acc[mf][nf][3] + b2);
            }
        }
    }
}

// ---------------------------------------------------------------------------
// apply channel panel: out = xin + beta * (P @ g), B = g panel resident.
// ---------------------------------------------------------------------------
__global__ __launch_bounds__(256) void apply_channel_panel_kernel(
    const float* __restrict__ xin, float* __restrict__ xout, const float* __restrict__ beta_p)
{
    extern __shared__ __align__(16) __nv_bfloat16 dynsm[];
    __nv_bfloat16* Bs = dynsm;
    __nv_bfloat16* Ab[2] = { dynsm + 256*136, dynsm + 256*136 + 128*40 };

    int b = blockIdx.z, n0 = blockIdx.x * 128;
    int tid = threadIdx.x, wid = tid >> 5, lane = tid & 31;
    int mw = (wid >> 2) * 64, nw = (wid & 3) * 32;
    int g = lane >> 2, tg = lane & 3;

    const __nv_bfloat16* bbase = g_gb + (size_t)b * CC * HWSZ + n0;
    #pragma unroll
    for (int j = 0; j < 16; j++) {
        int idx = j * 256 + tid;
        int row = idx >> 4, cb8 = (idx & 15) * 8;
        cpa16(smem_u32(Bs + row*136 + cb8), bbase + (size_t)row * HWSZ + cb8);
    }
    CP_COMMIT();

    int arow = tid >> 1, acb = (tid & 1) * 16;
    float beta = *beta_p;

    for (int mt = 0; mt < 2; mt++) {
        int mbase = mt * 128;
        const __nv_bfloat16* asrc = g_Pb + (size_t)b * 65536 + (size_t)(mbase + arow) * 256 + acb;
        {
            uint32_t ad = smem_u32(Ab[0] + arow*40 + acb);
            cpa16(ad, asrc); cpa16(ad + 16, asrc + 8);
            CP_COMMIT();
        }
        float acc[4][4][4] = {};
        for (int kc = 0; kc < 8; kc++) {
            if (kc < 7) {
                uint32_t ad = smem_u32(Ab[(kc+1)&1] + arow*40 + acb);
                const __nv_bfloat16* as = asrc + (kc + 1) * 32;
                cpa16(ad, as); cpa16(ad + 16, as + 8);
                CP_COMMIT();
                cp_wait<1>();
            } else cp_wait<0>();
            __syncthreads();
            mma_tileT<40, 136, 2>(Ab[kc&1], Bs + kc*32*136, mw, nw, lane, acc);
            __syncthreads();
        }
        #pragma unroll
        for (int mf = 0; mf < 4; mf++) {
            int r1 = mbase + mw + mf * 16 + g, r2 = r1 + 8;
            size_t base1 = ((size_t)b * CC + r1) * HWSZ + n0;
            size_t base2 = ((size_t)b * CC + r2) * HWSZ + n0;
            #pragma unroll
            for (int nf = 0; nf < 4; nf++) {
                int col = nw + nf * 8 + tg * 2;
                float2 xa = *(const float2*)&xin[base1 + col];
                float2 xb2 = *(const float2*)&xin[base2 + col];
                *(float2*)&xout[base1 + col] =
                    make_float2(xa.x + beta*acc[mf][nf][0], xa.y + beta*acc[mf][nf][1]);
                *(float2*)&xout[base2 + col] =
                    make_float2(xb2.x + beta*acc[mf][nf][2], xb2.y + beta*acc[mf][nf][3]);
            }
        }
    }
}

// ---------------------------------------------------------------------------
// per-axis x sums
// ---------------------------------------------------------------------------
template<int MODE>
__global__ __launch_bounds__(96) void xsum_kernel()
{
    int k = blockIdx.x, b = blockIdx.y, i = threadIdx.x;
    const __nv_bfloat16* src = g_xb + ((size_t)b * CC + k) * HWSZ;
    float s = 0.f;
    if (MODE == 0) {
        #pragma unroll 8
        for (int h = 0; h < 96; h++) s += __bfloat162float(src[h*96 + i]);
    } else {
        #pragma unroll 8
        for (int w = 0; w < 96; w++) s += __bfloat162float(src[i*96 + w]);
    }
    g_xs[((size_t)b * CC + k) * 96 + i] = s;
}

__global__ __launch_bounds__(96) void uv_kernel()
{
    int b = blockIdx.x, j = threadIdx.x;
    float su = 0.f, sv = 0.f;
    #pragma unroll 8
    for (int k = 0; k < 256; k++) {
        float xv = g_xs[((size_t)b * CC + k) * 96 + j];
        su += g_w2[k] * xv;
        sv += g_w1[k] * xv;
    }
    g_u[b*96 + j] = su;
    g_v[b*96 + j] = sv;
}

// ---------------------------------------------------------------------------
// slice logits (16 channels/block, grid 16x16)
// ---------------------------------------------------------------------------
template<int MODE>
__global__ __launch_bounds__(256) void slice_logits_bf16_kernel(
    const __nv_bfloat16* __restrict__ Abase, const __nv_bfloat16* __restrict__ Bbase)
{
    extern __shared__ __align__(16) __nv_bfloat16 dynsm[];
    __nv_bfloat16* Tb[2] = { dynsm,            dynsm + 2*96*104 };
    __nv_bfloat16* Pb[2] = { dynsm + 96*104,   dynsm + 3*96*104 };

    int b = blockIdx.y, cch = blockIdx.x;
    int tid = threadIdx.x, wid = tid >> 5, lane = tid & 31;
    int mw = (wid >> 2) * 48, nw = (wid & 3) * 24;
    int g = lane >> 2, tg = lane & 3;

    const __nv_bfloat16* tbase = Abase + ((size_t)b * CC + cch * 16) * HWSZ;
    const __nv_bfloat16* pbase = Bbase + ((size_t)b * CC + cch * 16) * HWSZ;

    float acc[3][3][4] = {};

    auto stage = [&](int cc, int bi) {
        const __nv_bfloat16* ts = tbase + (size_t)cc * HWSZ;
        const __nv_bfloat16* ps = pbase + (size_t)cc * HWSZ;
        #pragma unroll
        for (int j = 0; j < 9; j++) {
            int c = j * 256 + tid;
            int cc2 = (c < 1152) ? c : c - 1152;
            int row = cc2 / 12, col = (cc2 % 12) * 8;
            if (c < 1152) cpa16(smem_u32(Tb[bi] + row*104 + col), ts + row*96 + col);
            else          cpa16(smem_u32(Pb[bi] + row*104 + col), ps + row*96 + col);
        }
        CP_COMMIT();
    };

    stage(0, 0);
    for (int cc = 0; cc < 16; cc++) {
        if (cc < 15) { stage(cc + 1, (cc + 1) & 1); cp_wait<1>(); }
        else cp_wait<0>();
        __syncthreads();
        const __nv_bfloat16* As = Tb[cc & 1];
        const __nv_bfloat16* Bs = Pb[cc & 1];
        #pragma unroll
        for (int ks = 0; ks < 6; ks++) {
            int k0 = ks * 16;
            uint32_t a[3][4], bf[3][2];
            #pragma unroll
            for (int mf = 0; mf < 3; mf++) {
                if (MODE == 0)
                    ldsm4t(a[mf][0], a[mf][1], a[mf][2], a[mf][3],
                        smem_u32(As + (k0 + ((lane>>4)&1)*8 + (lane&7))*104 + mw + mf*16 + ((lane>>3)&1)*8));
                else
                    ldsm4(a[mf][0], a[mf][1], a[mf][2], a[mf][3],
                        smem_u32(As + (mw + mf*16 + (lane&15))*104 + k0 + (lane>>4)*8));
            }
            if (MODE == 0) {
                ldsm4t(bf[0][0], bf[0][1], bf[1][0], bf[1][1],
                       smem_u32(Bs + (k0 + (lane&15))*104 + nw + (lane>>4)*8));
                ldsm2t(bf[2][0], bf[2][1],
                       smem_u32(Bs + (k0 + (lane&15))*104 + nw + 16));
            } else {
                ldsm4(bf[0][0], bf[0][1], bf[1][0], bf[1][1],
                      smem_u32(Bs + (nw + (lane>>4)*8 + (lane&7))*104 + k0 + ((lane>>3)&1)*8));
                ldsm2(bf[2][0], bf[2][1],
                      smem_u32(Bs + (nw + 16 + (lane&7))*104 + k0 + ((lane>>3)&1)*8));
            }
            #pragma unroll
            for (int mf = 0; mf < 3; mf++)
                #pragma unroll
                for (int nf = 0; nf < 3; nf++)
                    mma_bf16(acc[mf][nf], a[mf][0], a[mf][1], a[mf][2], a[mf][3],
                             bf[nf][0], bf[nf][1]);
        }
        __syncthreads();
    }
    float* Sb = g_S + (size_t)b * 9216;
    #pragma unroll
    for (int mf = 0; mf < 3; mf++) {
        int i1 = mw + mf * 16 + g, i2 = i1 + 8;
        #pragma unroll
        for (int nf = 0; nf < 3; nf++) {
            int jc = nw + nf * 8 + tg * 2;
            atomicAdd(&Sb[i1 * 96 + jc],     acc[mf][nf][0]);
            atomicAdd(&Sb[i1 * 96 + jc + 1], acc[mf][nf][1]);
            atomicAdd(&Sb[i2 * 96 + jc],     acc[mf][nf][2]);
            atomicAdd(&Sb[i2 * 96 + jc + 1], acc[mf][nf][3]);
        }
    }
}

// ---------------------------------------------------------------------------
// softmax: optional additive bias. writes bf16 P.
// ---------------------------------------------------------------------------
__global__ __launch_bounds__(256) void softmax_kernel(int n, const float* u,
                                                      const float* v, const float* c0p)
{
    size_t base = (size_t)blockIdx.x * n;
    int tid = threadIdx.x;
    __shared__ float red[8];

    float rowadd = 0.f;
    int ub = 0;
    if (u) {
        rowadd = v[blockIdx.x] + *c0p;
        ub = (blockIdx.x / 96) * 96;
    }

    float m = -INFINITY;
    for (int j = tid; j < n; j += 256) {
        float val = g_S[base + j] + rowadd + (u ? u[ub + j] : 0.f);
        m = fmaxf(m, val);
    }
    #pragma unroll
    for (int o = 16; o; o >>= 1) m = fmaxf(m, __shfl_xor_sync(0xffffffffu, m, o));
    if ((tid & 31) == 0) red[tid >> 5] = m;
    __syncthreads();
    float mm = red[0];
    #pragma unroll
    for (int w = 1; w < 8; w++) mm = fmaxf(mm, red[w]);

    float s = 0.f;
    float ev[2];
    int cnt = 0;
    for (int j = tid; j < n; j += 256) {
        float val = g_S[base + j] + rowadd + (u ? u[ub + j] : 0.f);
        float e = __expf(val - mm);
        ev[cnt++] = e;
        s += e;
    }
    #pragma unroll
    for (int o = 16; o; o >>= 1) s += __shfl_xor_sync(0xffffffffu, s, o);
    if ((tid & 31) == 0) red[tid >> 5] = s;
    __syncthreads();
    float st = 0.f;
    #pragma unroll
    for (int w = 0; w < 8; w++) st += red[w];
    float inv = 1.0f / st;
    cnt = 0;
    for (int j = tid; j < n; j += 256)
        g_Pb[base + j] = __float2bfloat16(ev[cnt++] * inv);
}

// ---------------------------------------------------------------------------
// apply width: D[(c,h), i] = sum_j g[(c,h), j] P[i,j];  out = xin + beta*D.
// ---------------------------------------------------------------------------
__global__ __launch_bounds__(256) void apply_slice_w_kernel(
    const float* __restrict__ xin, float* __restrict__ xout, const float* __restrict__ beta_p)
{
    __shared__ __align__(16) __nv_bfloat16 As[128][104];
    __shared__ __align__(16) __nv_bfloat16 Bs[96][104];

    int b = blockIdx.y, m0 = blockIdx.x * 128;
    int tid = threadIdx.x, wid = tid >> 5, lane = tid & 31;
    int mw = (wid >> 1) * 32, nw = (wid & 1) * 48;
    int g = lane >> 2, tg = lane & 3;

    const __nv_bfloat16* gsrc = g_gb + (size_t)b * CC * HWSZ + (size_t)m0 * 96;
    const __nv_bfloat16* psrc = g_Pb + (size_t)b * 9216;
    #pragma unroll
    for (int j = 0; j < 6; j++) {
        int c = j * 256 + tid;
        int row = c / 12, col = (c % 12) * 8;
        cpa16(smem_u32(&As[row][col]), gsrc + row*96 + col);
    }
    #pragma unroll
    for (int j = 0; j < 5; j++) {
        int c = j * 256 + tid;
        if (c < 1152) {
            int row = c / 12, col = (c % 12) * 8;
            cpa16(smem_u32(&Bs[row][col]), psrc + row*96 + col);
        }
    }
    CP_COMMIT();
    cp_wait<0>();
    __syncthreads();

    float acc[2][6][4] = {};
    #pragma unroll
    for (int ks = 0; ks < 6; ks++) {
        int k0 = ks * 16;
        uint32_t a[2][4], bf[6][2];
        #pragma unroll
        for (int mf = 0; mf < 2; mf++)
            ldsm4(a[mf][0], a[mf][1], a[mf][2], a[mf][3],
                  smem_u32(&As[mw + mf*16 + (lane&15)][k0 + (lane>>4)*8]));
        #pragma unroll
        for (int nb = 0; nb < 3; nb++)
            ldsm4(bf[nb*2][0], bf[nb*2][1], bf[nb*2+1][0], bf[nb*2+1][1],
                  smem_u32(&Bs[nw + nb*16 + (lane>>4)*8 + (lane&7)][k0 + ((lane>>3)&1)*8]));
        #pragma unroll
        for (int mf = 0; mf < 2; mf++)
            #pragma unroll
            for (int nf = 0; nf < 6; nf++)
                mma_bf16(acc[mf][nf], a[mf][0], a[mf][1], a[mf][2], a[mf][3],
                         bf[nf][0], bf[nf][1]);
    }
    float beta = *beta_p;
    size_t gb = (size_t)b * CC * HWSZ;
    #pragma unroll
    for (int mf = 0; mf < 2; mf++) {
        int r1 = m0 + mw + mf * 16 + g, r2 = r1 + 8;
        #pragma unroll
        for (int nf = 0; nf < 6; nf++) {
            int col = nw + nf * 8 + tg * 2;
            size_t o1 = gb + (size_t)r1 * 96 + col;
            size_t o2 = gb + (size_t)r2 * 96 + col;
            float2 xa = *(const float2*)&xin[o1];
            float2 xb2 = *(const float2*)&xin[o2];
            float v0 = xa.x + beta*acc[mf][nf][0], v1 = xa.y + beta*acc[mf][nf][1];
            float v2 = xb2.x + beta*acc[mf][nf][2], v3 = xb2.y + beta*acc[mf][nf][3];
            *(float2*)&xout[o1] = make_float2(v0, v1);
            *(float2*)&xout[o2] = make_float2(v2, v3);
            *(uint32_t*)&g_xb[o1] = packbf(v0, v1);
            *(uint32_t*)&g_xb[o2] = packbf(v2, v3);
        }
    }
}

// ---------------------------------------------------------------------------
// apply height, 2 channels/block: P staged once, g per channel.
// dyn smem: As(P) 96x104 + Bs[2] 96x104 each = 59,904 B.
// ---------------------------------------------------------------------------
__global__ __launch_bounds__(256) void apply_slice_h_kernel(
    const float* __restrict__ xin, float* __restrict__ xout, const float* __restrict__ beta_p)
{
    extern __shared__ __align__(16) __nv_bfloat16 dynsm[];
    __nv_bfloat16* As  = dynsm;                 // P [h][j]
    __nv_bfloat16* Bs0 = dynsm + 96*104;        // g ch c0
    __nv_bfloat16* Bs1 = dynsm + 2*96*104;      // g ch c0+1

    int b = blockIdx.y, c0 = blockIdx.x * 2;
    int tid = threadIdx.x, wid = tid >> 5, lane = tid & 31;
    int mw = (wid >> 2) * 48, nw = (wid & 3) * 24;
    int g = lane >> 2, tg = lane & 3;

    const __nv_bfloat16* psrc = g_Pb + (size_t)b * 9216;
    const __nv_bfloat16* gsrc = g_gb + ((size_t)b * CC + c0) * HWSZ;
    // 3456 16B-chunks total: sel 0 = P, 1 = g[c0], 2 = g[c0+1]
    #pragma unroll
    for (int j = 0; j < 14; j++) {
        int cidx = j * 256 + tid;
        if (cidx < 3456) {
            int sel = cidx / 1152, c2 = cidx % 1152;
            int row = c2 / 12, col = (c2 % 12) * 8;
            if (sel == 0)
                cpa16(smem_u32(As + row*104 + col), psrc + row*96 + col);
            else if (sel == 1)
                cpa16(smem_u32(Bs0 + row*104 + col), gsrc + row*96 + col);
            else
                cpa16(smem_u32(Bs1 + row*104 + col), gsrc + HWSZ + row*96 + col);
        }
    }
    CP_COMMIT();
    cp_wait<0>();
    __syncthreads();

    float beta = *beta_p;

    #pragma unroll
    for (int ch = 0; ch < 2; ch++) {
        const __nv_bfloat16* Bs = ch ? Bs1 : Bs0;
        float acc[3][3][4] = {};
        #pragma unroll
        for (int ks = 0; ks < 6; ks++) {
            int k0 = ks * 16;
            uint32_t a[3][4], bf[3][2];
            #pragma unroll
            for (int mf = 0; mf < 3; mf++)
                ldsm4(a[mf][0], a[mf][1], a[mf][2], a[mf][3],
                      smem_u32(As + (mw + mf*16 + (lane&15))*104 + k0 + (lane>>4)*8));
            ldsm4t(bf[0][0], bf[0][1], bf[1][0], bf[1][1],
                   smem_u32(Bs + (k0 + (lane&15))*104 + nw + (lane>>4)*8));
            ldsm2t(bf[2][0], bf[2][1],
                   smem_u32(Bs + (k0 + (lane&15))*104 + nw + 16));
            #pragma unroll
            for (int mf = 0; mf < 3; mf++)
                #pragma unroll
                for (int nf = 0; nf < 3; nf++)
                    mma_bf16(acc[mf][nf], a[mf][0], a[mf][1], a[mf][2], a[mf][3],
                             bf[nf][0], bf[nf][1]);
        }
        size_t base = ((size_t)b * CC + c0 + ch) * HWSZ;
        #pragma unroll
        for (int mf = 0; mf < 3; mf++) {
            int i1 = mw + mf * 16 + g, i2 = i1 + 8;
            #pragma unroll
            for (int nf = 0; nf < 3; nf++) {
                int col = nw + nf * 8 + tg * 2;
                size_t o1 = base + (size_t)i1 * 96 + col;
                size_t o2 = base + (size_t)i2 * 96 + col;
                float2 xa = *(const float2*)&xin[o1];
                float2 xb2 = *(const float2*)&xin[o2];
                float v0 = xa.x + beta*acc[mf][nf][0], v1 = xa.y + beta*acc[mf][nf][1];
                float v2 = xb2.x + beta*acc[mf][nf][2], v3 = xb2.y + beta*acc[mf][nf][3];
                *(float2*)&xout[o1] = make_float2(v0, v1);
                *(float2*)&xout[o2] = make_float2(v2, v3);
                *(uint32_t*)&g_xb[o1] = packbf(v0, v1);
                *(uint32_t*)&g_xb[o2] = packbf(v2, v3);
            }
        }
    }
}

// ---------------------------------------------------------------------------
// Gram: 128x128 tiles, symmetric (3 tile-blocks per b), BK=32 double-buffered.
// ---------------------------------------------------------------------------
__global__ __launch_bounds__(256) void gram_kernel()
{
    __shared__ __align__(16) __nv_bfloat16 Asm[2][128][40];
    __shared__ __align__(16) __nv_bfloat16 Bsm[2][128][40];

    int ti = blockIdx.x, b = blockIdx.y;
    int i0 = (ti == 2) ? 128 : 0;
    int j0 = (ti == 0) ? 0 : 128;
    int tid = threadIdx.x, wid = tid >> 5, lane = tid & 31;
    int mw = (wid >> 2) * 64, nw = (wid & 3) * 32;
    int g = lane >> 2, tg = lane & 3;

    int row = tid >> 1, cb = (tid & 1) * 16;
    const __nv_bfloat16* as0 = g_xb + ((size_t)b * CC + i0 + row) * HWSZ + cb;
    const __nv_bfloat16* bs0 = g_xb + ((size_t)b * CC + j0 + row) * HWSZ + cb;

    float acc[4][4][4] = {};

    auto stage = [&](int kk, int bi) {
        uint32_t ad = smem_u32(&Asm[bi][row][cb]);
        uint32_t bd = smem_u32(&Bsm[bi][row][cb]);
        cpa16(ad, as0 + kk); cpa16(ad + 16, as0 + kk + 8);
        cpa16(bd, bs0 + kk); cpa16(bd + 16, bs0 + kk + 8);
        CP_COMMIT();
    };

    stage(0, 0);
    for (int s = 0; s < 288; s++) {
        if (s < 287) { stage((s + 1) * 32, (s + 1) & 1); cp_wait<1>(); }
        else cp_wait<0>();
        __syncthreads();
        mma_tileNN<40, 40, 2>(&Asm[s&1][0][0], &Bsm[s&1][0][0], mw, nw, lane, acc);
        __syncthreads();
    }
    float* Gb = g_G + (size_t)b * 65536;
    #pragma unroll
    for (int mf = 0; mf < 4; mf++) {
        int i1 = i0 + mw + mf * 16 + g, i2 = i1 + 8;
        #pragma unroll
        for (int nf = 0; nf < 4; nf++) {
            int jc = j0 + nw + nf * 8 + tg * 2;
            *(float2*)&Gb[(size_t)i1 * 256 + jc] = make_float2(acc[mf][nf][0], acc[mf][nf][1]);
            *(float2*)&Gb[(size_t)i2 * 256 + jc] = make_float2(acc[mf][nf][2], acc[mf][nf][3]);
            if (ti == 1) {
                Gb[(size_t)jc * 256 + i1]       = acc[mf][nf][0];
                Gb[(size_t)(jc + 1) * 256 + i1] = acc[mf][nf][1];
                Gb[(size_t)jc * 256 + i2]       = acc[mf][nf][2];
                Gb[(size_t)(jc + 1) * 256 + i2] = acc[mf][nf][3];
            }
        }
    }
}

// xs2[b,c] = sum_hw x[b,c,:]
__global__ __launch_bounds__(256) void xsum2_kernel()
{
    int k = blockIdx.x, b = blockIdx.y, tid = threadIdx.x;
    const __nv_bfloat16* src = g_xb + ((size_t)b * CC + k) * HWSZ;
    __shared__ float red[8];
    float s = 0.f;
    for (int e = tid; e < HWSZ; e += 256) s += __bfloat162float(src[e]);
    #pragma unroll
    for (int o = 16; o; o >>= 1) s += __shfl_xor_sync(0xffffffffu, s, o);
    if ((tid & 31) == 0) red[tid >> 5] = s;
    __syncthreads();
    if (tid == 0) {
        float t = 0.f;
        #pragma unroll
        for (int w = 0; w < 8; w++) t += red[w];
        g_xs2[b * CC + k] = t;
    }
}

__global__ __launch_bounds__(256) void sAsB_kernel(const float* __restrict__ wt,
                                                   const float* __restrict__ wp,
                                                   const float* __restrict__ bp)
{
    int i = blockIdx.x, b = blockIdx.y, c = threadIdx.x;
    __shared__ float r1[8], r2[8];
    float xv = g_xs2[b*CC + c];
    float sa = wt[i*256 + c] * xv;
    float sb = wp[i*256 + c] * xv;
    #pragma unroll
    for (int off = 16; off; off >>= 1) {
        sa += __shfl_xor_sync(0xffffffffu, sa, off);
        sb += __shfl_xor_sync(0xffffffffu, sb, off);
    }
    if ((c & 31) == 0) { r1[c>>5] = sa; r2[c>>5] = sb; }
    __syncthreads();
    if (c == 0) {
        float a = 0.f, b2 = 0.f;
        #pragma unroll
        for (int w = 0; w < 8; w++) { a += r1[w]; b2 += r2[w]; }
        g_sA[b*CC + i] = a;
        g_sB2[b*CC + i] = b2 + 9216.f * bp[i];
    }
}

// ---------------------------------------------------------------------------
// fp32 GEMM NN: T1[b] = wt @ G[b]. Tile 64x64, BK=16.
// ---------------------------------------------------------------------------
__global__ __launch_bounds__(256) void f32gemm_nn_kernel(const float* __restrict__ wt)
{
    int b  = blockIdx.z;
    int i0 = blockIdx.y * 64;
    int n0 = blockIdx.x * 64;

    __shared__ __align__(16) float As[16 * 68];
    __shared__ __align__(16) float Gs[16 * 68];

    int tid = threadIdx.x;
    int ti4 = (tid >> 4) * 4, tj4 = (tid & 15) * 4;
    float acc[4][4] = {};

    const float* Gb = g_G + (size_t)b * 65536;

    for (int kk = 0; kk < 256; kk += 16) {
        #pragma unroll
        for (int rr = 0; rr < 4; rr++) {
            int r = rr * 16 + (tid >> 4);
            int cload = tid & 15;
            As[cload * 68 + r] = wt[(i0 + r) * 256 + kk + cload];
        }
        #pragma unroll
        for (int rr = 0; rr < 4; rr++) {
            int k = rr * 4 + (tid >> 6);
            int n = tid & 63;
            Gs[k * 68 + n] = Gb[(size_t)(kk + k) * 256 + n0 + n];
        }
        __syncthreads();
        #pragma unroll
        for (int k = 0; k < 16; k++) {
            float4 a = *(float4*)&As[k * 68 + ti4];
            float4 g4 = *(float4*)&Gs[k * 68 + tj4];
            float ar[4] = {a.x, a.y, a.z, a.w};
            float gr[4] = {g4.x, g4.y, g4.z, g4.w};
            #pragma unroll
            for (int i = 0; i < 4; i++)
                #pragma unroll
                for (int j = 0; j < 4; j++)
                    acc[i][j] += ar[i] * gr[j];
        }
        __syncthreads();
    }

    float* T1b = g_T1 + (size_t)b * 65536;
    #pragma unroll
    for (int i = 0; i < 4; i++)
        #pragma unroll
        for (int j = 0; j < 4; j++)
            T1b[(size_t)(i0 + ti4 + i) * 256 + n0 + tj4 + j] = acc[i][j];
}

// ---------------------------------------------------------------------------
// fp32 GEMM NT + channel-bias epilogue.
// ---------------------------------------------------------------------------
__global__ __launch_bounds__(256) void f32gemm_nt_kernel(const float* __restrict__ wp,
                                                         const float* __restrict__ bt,
                                                         const float* __restrict__ bp)
{
    int b  = blockIdx.z;
    int i0 = blockIdx.y * 64;
    int j0 = blockIdx.x * 64;

    __shared__ __align__(16) float Ts[32 * 68];
    __shared__ __align__(16) float Ps[32 * 68];

    int tid = threadIdx.x;
    int lc = tid & 31, lr = tid >> 5;
    int ti4 = (tid >> 4) * 4, tj4 = (tid & 15) * 4;

    float acc[4][4] = {};
    const float* T1b = g_T1 + (size_t)b * 65536;

    for (int kb = 0; kb < 8; kb++) {
        int k0 = kb * 32;
        #pragma unroll
        for (int rr = 0; rr < 8; rr++) {
            int r = rr * 8 + lr;
            Ts[lc * 68 + r] = T1b[(size_t)(i0 + r) * 256 + k0 + lc];
            Ps[lc * 68 + r] = wp[(j0 + r) * 256 + k0 + lc];
        }
        __syncthreads();
        #pragma unroll
        for (int k = 0; k < 32; k++) {
            float4 a = *(float4*)&Ts[k * 68 + ti4];
            float4 p = *(float4*)&Ps[k * 68 + tj4];
            float ar[4] = {a.x, a.y, a.z, a.w};
            float pr[4] = {p.x, p.y, p.z, p.w};
            #pragma unroll
            for (int i = 0; i < 4; i++)
                #pragma unroll
                for (int j = 0; j < 4; j++)
                    acc[i][j] += ar[i] * pr[j];
        }
        __syncthreads();
    }

    float* Sb = g_S + (size_t)b * 65536;
    #pragma unroll
    for (int i = 0; i < 4; i++) {
        int irow = i0 + ti4 + i;
        float bti = bt[irow], sai = g_sA[b*CC + irow];
        #pragma unroll
        for (int j = 0; j < 4; j++) {
            int jcol = j0 + tj4 + j;
            Sb[(size_t)irow * 256 + jcol] =
                acc[i][j] + bti * g_sB2[b*CC + jcol] + bp[jcol] * sai;
        }
    }
}

// ---------------------------------------------------------------------------
extern "C" void kernel_launch(void* const* d_in, const int* in_sizes, int n_in,
                              void* d_out, int out_size)
{
    const float* x      = (const float*)d_in[0];
    const float* wt     = (const float*)d_in[1];
    const float* bt     = (const float*)d_in[2];
    const float* wp     = (const float*)d_in[3];
    const float* bp     = (const float*)d_in[4];
    const float* wg     = (const float*)d_in[5];
    const float* bg     = (const float*)d_in[6];
    const float* beta_w = (const float*)d_in[7];
    const float* beta_h = (const float*)d_in[8];
    const float* beta_c = (const float*)d_in[9];
    float* out = (float*)d_out;

    float *x1, *x2, *S, *uu, *vv, *c0;
    __nv_bfloat16 *thb, *gbb, *W2, *xbb, *Wbf;
    cudaGetSymbolAddress((void**)&x1, g_x1);
    cudaGetSymbolAddress((void**)&x2, g_x2);
    cudaGetSymbolAddress((void**)&S,  g_S);
    cudaGetSymbolAddress((void**)&uu, g_u);
    cudaGetSymbolAddress((void**)&vv, g_v);
    cudaGetSymbolAddress((void**)&c0, g_c0);
    cudaGetSymbolAddress((void**)&thb, g_thb);
    cudaGetSymbolAddress((void**)&gbb, g_gb);
    cudaGetSymbolAddress((void**)&W2,  g_W2);
    cudaGetSymbolAddress((void**)&xbb, g_xb);
    cudaGetSymbolAddress((void**)&Wbf, g_Wbf);

    int panel_smem = 256*136*2 + 2*128*40*2;      // 90,112 B
    int slice_smem = 4 * 96 * 104 * 2;            // 79,872 B
    int hsl_smem   = 3 * 96 * 104 * 2;            // 59,904 B
    cudaFuncSetAttribute(conv_panel_kernel,
                         cudaFuncAttributeMaxDynamicSharedMemorySize, panel_smem);
    cudaFuncSetAttribute(apply_channel_panel_kernel,
                         cudaFuncAttributeMaxDynamicSharedMemorySize, panel_smem);
    cudaFuncSetAttribute(slice_logits_bf16_kernel<0>,
                         cudaFuncAttributeMaxDynamicSharedMemorySize, slice_smem);
    cudaFuncSetAttribute(slice_logits_bf16_kernel<1>,
                         cudaFuncAttributeMaxDynamicSharedMemorySize, slice_smem);
    cudaFuncSetAttribute(apply_slice_h_kernel,
                         cudaFuncAttributeMaxDynamicSharedMemorySize, hsl_smem);

    static cudaStream_t s2 = nullptr;
    static cudaEvent_t ev[8];
    if (!s2) {
        cudaStreamCreateWithFlags(&s2, cudaStreamNonBlocking);
        for (int i = 0; i < 8; i++)
            cudaEventCreateWithFlags(&ev[i], cudaEventDisableTiming);
    }
    cudaStream_t s0 = 0;

    // ---- prologue ----
    xconv_kernel<<<NELEM / (256 * 8), 256, 0, s0>>>(x);
    cudaEventRecord(ev[0], s0);                               // g_xb ready

    cudaStreamWaitEvent(s2, ev[0], 0);                        // fork s2
    wconv_kernel<<<768, 256, 0, s2>>>(wt, wp, wg);
    mprep_kernel<<<dim3(4, 4), 128, 0, s2>>>();
    cudaEventRecord(ev[1], s2);                               // W2 ready
    biasvec_kernel<<<256, 256, 0, s2>>>(wt, wp, bt, bp);
    cudaMemsetAsync(S, 0, (size_t)16 * 9216 * sizeof(float), s2);
    xsum_kernel<0><<<dim3(256, 16), 96, 0, s2>>>();
    uv_kernel<<<16, 96, 0, s2>>>();
    cudaEventRecord(ev[2], s2);                               // S zeroed + u/v ready

    // ---- round 1: width attention ----
    cudaStreamWaitEvent(s0, ev[1], 0);
    conv_panel_kernel<<<dim3(72, 1, 16), 256, panel_smem, s0>>>(W2, 4, thb, nullptr, gbb, bg);
    cudaStreamWaitEvent(s0, ev[2], 0);
    slice_logits_bf16_kernel<0><<<dim3(16, 16), 256, slice_smem, s0>>>(xbb, thb);
    softmax_kernel<<<16 * 96, 256, 0, s0>>>(96, uu, vv, c0);
    apply_slice_w_kernel<<<dim3(192, 16), 256, 0, s0>>>(x, x1, beta_w);
    cudaEventRecord(ev[3], s0);                               // new x (g_xb) ready

    // ---- round 2: height attention ----
    cudaStreamWaitEvent(s2, ev[3], 0);
    cudaMemsetAsync(S, 0, (size_t)16 * 9216 * sizeof(float), s2);
    xsum_kernel<1><<<dim3(256, 16), 96, 0, s2>>>();
    uv_kernel<<<16, 96, 0, s2>>>();
    cudaEventRecord(ev[4], s2);

    conv_panel_kernel<<<dim3(72, 1, 16), 256, panel_smem, s0>>>(W2, 4, thb, nullptr, gbb, bg);
    cudaStreamWaitEvent(s0, ev[4], 0);
    slice_logits_bf16_kernel<1><<<dim3(16, 16), 256, slice_smem, s0>>>(xbb, thb);
    softmax_kernel<<<16 * 96, 256, 0, s0>>>(96, uu, vv, c0);
    apply_slice_h_kernel<<<dim3(128, 16), 256, hsl_smem, s0>>>(x1, x2, beta_h);
    cudaEventRecord(ev[5], s0);                               // new x (g_xb) ready

    // ---- round 3: channel attention ----
    cudaStreamWaitEvent(s2, ev[5], 0);
    xsum2_kernel<<<dim3(256, 16), 256, 0, s2>>>();
    sAsB_kernel<<<dim3(256, 16), 256, 0, s2>>>(wt, wp, bp);
    gram_kernel<<<dim3(3, 16), 256, 0, s2>>>();
    cudaEventRecord(ev[6], s2);                               // G + sA/sB2 ready

    conv_panel_kernel<<<dim3(72, 1, 16), 256, panel_smem, s0>>>(Wbf + 2*65536, 2, gbb, bg, gbb, bg);
    cudaStreamWaitEvent(s0, ev[6], 0);
    f32gemm_nn_kernel<<<dim3(4, 4, 16), 256, 0, s0>>>(wt);
    f32gemm_nt_kernel<<<dim3(4, 4, 16), 256, 0, s0>>>(wp, bt, bp);
    softmax_kernel<<<16 * 256, 256, 0, s0>>>(256, nullptr, nullptr, nullptr);
    apply_channel_panel_kernel<<<dim3(72, 1, 16), 256, panel_smem, s0>>>(x2, out, beta_c);
}

// round 14
// speedup vs baseline: 1.0709x; 1.0210x over previous
#include <cuda_runtime.h>
#include <cuda_bf16.h>
#include <math.h>
#include <stdint.h>

#define BB 16
#define CC 256
#define HH 96
#define WW 96
#define HWSZ (HH*WW)           // 9216
#define NELEM (BB*CC*HWSZ)     // 37,748,736

// Scratch (device globals: allocation-free rule)
__device__ __nv_bfloat16 g_thb[NELEM];       // y = M x (rounds 1-2)
__device__ __nv_bfloat16 g_gb[NELEM];        // g = Wg x + bg
__device__ __nv_bfloat16 g_xb[NELEM];        // bf16 mirror of current x
__device__ float g_x1[NELEM];
__device__ float g_x2[NELEM];
__device__ float g_S[BB*CC*CC];              // logits fp32
__device__ __nv_bfloat16 g_Pb[BB*CC*CC];     // probabilities bf16
__device__ __nv_bfloat16 g_Wbf[3*CC*CC];     // [Wt; Wp; Wg] bf16
__device__ __nv_bfloat16 g_W2[2*CC*CC];      // [M = Wt^T Wp ; Wg] bf16 (512x256)
__device__ float g_G[BB*CC*CC];              // Gram X X^T fp32
__device__ float g_T1[BB*CC*CC];             // Wt @ G fp32
__device__ float g_xs[BB*CC*96];             // per-axis sums of x
__device__ float g_xs2[BB*CC];               // full-hw sums of x
__device__ float g_u[BB*96];
__device__ float g_v[BB*96];
__device__ float g_w1[CC];
__device__ float g_w2[CC];
__device__ float g_c0[1];
__device__ float g_sA[BB*CC];
__device__ float g_sB2[BB*CC];

// ---------------------------------------------------------------------------
// helpers
// ---------------------------------------------------------------------------
__device__ __forceinline__ uint32_t smem_u32(const void* p) {
    return (uint32_t)__cvta_generic_to_shared(p);
}
__device__ __forceinline__ uint32_t packbf(float lo, float hi) {
    __nv_bfloat162 h = __floats2bfloat162_rn(lo, hi);
    return *(uint32_t*)&h;
}
__device__ __forceinline__ void cpa16(uint32_t dst, const void* src) {
    asm volatile("cp.async.cg.shared.global [%0], [%1], 16;" :: "r"(dst), "l"(src));
}
#define CP_COMMIT() asm volatile("cp.async.commit_group;")
template<int N> __device__ __forceinline__ void cp_wait() {
    asm volatile("cp.async.wait_group %0;" :: "n"(N));
}
__device__ __forceinline__ void ldsm4(uint32_t& r0, uint32_t& r1, uint32_t& r2, uint32_t& r3, uint32_t a) {
    asm volatile("ldmatrix.sync.aligned.m8n8.x4.shared.b16 {%0,%1,%2,%3},[%4];"
                 : "=r"(r0), "=r"(r1), "=r"(r2), "=r"(r3) : "r"(a));
}
__device__ __forceinline__ void ldsm4t(uint32_t& r0, uint32_t& r1, uint32_t& r2, uint32_t& r3, uint32_t a) {
    asm volatile("ldmatrix.sync.aligned.m8n8.x4.trans.shared.b16 {%0,%1,%2,%3},[%4];"
                 : "=r"(r0), "=r"(r1), "=r"(r2), "=r"(r3) : "r"(a));
}
__device__ __forceinline__ void ldsm2(uint32_t& r0, uint32_t& r1, uint32_t a) {
    asm volatile("ldmatrix.sync.aligned.m8n8.x2.shared.b16 {%0,%1},[%2];"
                 : "=r"(r0), "=r"(r1) : "r"(a));
}
__device__ __forceinline__ void ldsm2t(uint32_t& r0, uint32_t& r1, uint32_t a) {
    asm volatile("ldmatrix.sync.aligned.m8n8.x2.trans.shared.b16 {%0,%1},[%2];"
                 : "=r"(r0), "=r"(r1) : "r"(a));
}
__device__ __forceinline__ void mma_bf16(float (&d)[4], uint32_t a0, uint32_t a1, uint32_t a2, uint32_t a3,
                                         uint32_t b0, uint32_t b1) {
    asm volatile(
        "mma.sync.aligned.m16n8k16.row.col.f32.bf16.bf16.f32 "
        "{%0,%1,%2,%3},{%4,%5,%6,%7},{%8,%9},{%0,%1,%2,%3};"
        : "+f"(d[0]), "+f"(d[1]), "+f"(d[2]), "+f"(d[3])
        : "r"(a0), "r"(a1), "r"(a2), "r"(a3), "r"(b0), "r"(b1));
}

// 128(M)x128(N) tile step: A [m][k] non-trans lda=LDA, B [k][n] trans ldb=LDB, KS k-steps.
template<int LDA, int LDB, int KS>
__device__ __forceinline__ void mma_tileT(const __nv_bfloat16* As, const __nv_bfloat16* Bs,
                                          int mw, int nw, int lane, float (&acc)[4][4][4])
{
    #pragma unroll
    for (int ks = 0; ks < KS; ks++) {
        int k0 = ks * 16;
        uint32_t a[4][4], bf[4][2];
        #pragma unroll
        for (int mf = 0; mf < 4; mf++)
            ldsm4(a[mf][0], a[mf][1], a[mf][2], a[mf][3],
                  smem_u32(As + (mw + mf*16 + (lane & 15)) * LDA + k0 + (lane >> 4) * 8));
        #pragma unroll
        for (int nb = 0; nb < 2; nb++)
            ldsm4t(bf[nb*2][0], bf[nb*2][1], bf[nb*2+1][0], bf[nb*2+1][1],
                   smem_u32(Bs + (k0 + (lane & 15)) * LDB + nw + nb*16 + (lane >> 4) * 8));
        #pragma unroll
        for (int mf = 0; mf < 4; mf++)
            #pragma unroll
            for (int nf = 0; nf < 4; nf++)
                mma_bf16(acc[mf][nf], a[mf][0], a[mf][1], a[mf][2], a[mf][3],
                         bf[nf][0], bf[nf][1]);
    }
}

// 128x128 tile step, B [n][k] non-trans (for gram).
template<int LDA, int LDB, int KS>
__device__ __forceinline__ void mma_tileNN(const __nv_bfloat16* As, const __nv_bfloat16* Bs,
                                           int mw, int nw, int lane, float (&acc)[4][4][4])
{
    #pragma unroll
    for (int ks = 0; ks < KS; ks++) {
        int k0 = ks * 16;
        uint32_t a[4][4], bf[4][2];
        #pragma unroll
        for (int mf = 0; mf < 4; mf++)
            ldsm4(a[mf][0], a[mf][1], a[mf][2], a[mf][3],
                  smem_u32(As + (mw + mf*16 + (lane & 15)) * LDA + k0 + (lane >> 4) * 8));
        #pragma unroll
        for (int nb = 0; nb < 2; nb++)
            ldsm4(bf[nb*2][0], bf[nb*2][1], bf[nb*2+1][0], bf[nb*2+1][1],
                  smem_u32(Bs + (nw + nb*16 + (lane>>4)*8 + (lane&7)) * LDB + k0 + ((lane>>3)&1)*8));
        #pragma unroll
        for (int mf = 0; mf < 4; mf++)
            #pragma unroll
            for (int nf = 0; nf < 4; nf++)
                mma_bf16(acc[mf][nf], a[mf][0], a[mf][1], a[mf][2], a[mf][3],
                         bf[nf][0], bf[nf][1]);
    }
}

// ---------------------------------------------------------------------------
// one-time converts / precomputes
// ---------------------------------------------------------------------------
__global__ void wconv_kernel(const float* __restrict__ wt, const float* __restrict__ wp,
                             const float* __restrict__ wg) {
    int i = blockIdx.x * 256 + threadIdx.x;
    const float* src = (i < 65536) ? wt : (i < 131072 ? wp : wg);
    __nv_bfloat16 v = __float2bfloat16(src[i & 65535]);
    g_Wbf[i] = v;
    if (i >= 131072) g_W2[65536 + (i - 131072)] = v;
}
__global__ void xconv_kernel(const float* __restrict__ x) {
    size_t base = ((size_t)blockIdx.x * 256 + threadIdx.x) * 8;
    float4 f0 = *(const float4*)(x + base);
    float4 f1 = *(const float4*)(x + base + 4);
    uint4 v;
    v.x = packbf(f0.x, f0.y); v.y = packbf(f0.z, f0.w);
    v.z = packbf(f1.x, f1.y); v.w = packbf(f1.z, f1.w);
    *(uint4*)(g_xb + base) = v;
}

// M = Wt^T Wp (256x256) -> g_W2 rows 0-255. Tile 64x64, K=256, 4 warps (2x2).
__global__ __launch_bounds__(128) void mprep_kernel()
{
    __shared__ __align__(16) __nv_bfloat16 As[64][72];
    __shared__ __align__(16) __nv_bfloat16 Bs[64][72];

    int m0 = blockIdx.y * 64, n0 = blockIdx.x * 64;
    int tid = threadIdx.x, wid = tid >> 5, lane = tid & 31;
    int mw = (wid >> 1) * 32, nw = (wid & 1) * 32;
    int g = lane >> 2, tg = lane & 3;

    float acc[2][4][4] = {};
    int cr = tid >> 1, mc = (tid & 1) * 32;

    for (int kk = 0; kk < 256; kk += 64) {
        uint32_t ad = smem_u32(&As[cr][mc]);
        uint32_t bd = smem_u32(&Bs[cr][mc]);
        const __nv_bfloat16* asrc = g_Wbf + (size_t)(kk + cr) * 256 + m0 + mc;
        const __nv_bfloat16* bsrc = g_Wbf + 65536 + (size_t)(kk + cr) * 256 + n0 + mc;
        #pragma unroll
        for (int j = 0; j < 4; j++) { cpa16(ad + j*16, asrc + j*8); cpa16(bd + j*16, bsrc + j*8); }
        CP_COMMIT();
        cp_wait<0>();
        __syncthreads();
        #pragma unroll
        for (int ks = 0; ks < 4; ks++) {
            int k0 = ks * 16;
            uint32_t a[2][4], bf[4][2];
            #pragma unroll
            for (int mf = 0; mf < 2; mf++)
                ldsm4t(a[mf][0], a[mf][1], a[mf][2], a[mf][3],
                    smem_u32(&As[k0 + ((lane>>4)&1)*8 + (lane&7)][mw + mf*16 + ((lane>>3)&1)*8]));
            ldsm4t(bf[0][0], bf[0][1], bf[1][0], bf[1][1],
                   smem_u32(&Bs[k0 + (lane&15)][nw + (lane>>4)*8]));
            ldsm4t(bf[2][0], bf[2][1], bf[3][0], bf[3][1],
                   smem_u32(&Bs[k0 + (lane&15)][nw + 16 + (lane>>4)*8]));
            #pragma unroll
            for (int mf = 0; mf < 2; mf++)
                #pragma unroll
                for (int nf = 0; nf < 4; nf++)
                    mma_bf16(acc[mf][nf], a[mf][0], a[mf][1], a[mf][2], a[mf][3],
                             bf[nf][0], bf[nf][1]);
        }
        __syncthreads();
    }
    #pragma unroll
    for (int mf = 0; mf < 2; mf++) {
        int r1 = m0 + mw + mf*16 + g, r2 = r1 + 8;
        #pragma unroll
        for (int nf = 0; nf < 4; nf++) {
            int col = n0 + nw + nf*8 + tg*2;
            *(uint32_t*)&g_W2[r1*256 + col] = packbf(acc[mf][nf][0], acc[mf][nf][1]);
            *(uint32_t*)&g_W2[r2*256 + col] = packbf(acc[mf][nf][2], acc[mf][nf][3]);
        }
    }
}

// bias fold vectors
__global__ __launch_bounds__(256) void biasvec_kernel(const float* __restrict__ wt,
                                                      const float* __restrict__ wp,
                                                      const float* __restrict__ bt,
                                                      const float* __restrict__ bp)
{
    int k = blockIdx.x, o = threadIdx.x;
    __shared__ float r1[8], r2[8], r3[8];
    float btv = bt[o], bpv = bp[o];
    float s1 = wt[o*256 + k] * bpv;
    float s2 = wp[o*256 + k] * btv;
    float c  = btv * bpv;
    #pragma unroll
    for (int off = 16; off; off >>= 1) {
        s1 += __shfl_xor_sync(0xffffffffu, s1, off);
        s2 += __shfl_xor_sync(0xffffffffu, s2, off);
        c  += __shfl_xor_sync(0xffffffffu, c, off);
    }
    if ((o & 31) == 0) { r1[o>>5] = s1; r2[o>>5] = s2; r3[o>>5] = c; }
    __syncthreads();
    if (o == 0) {
        float a = 0.f, b2 = 0.f, cc = 0.f;
        #pragma unroll
        for (int w = 0; w < 8; w++) { a += r1[w]; b2 += r2[w]; cc += r3[w]; }
        g_w1[k] = a; g_w2[k] = b2;
        if (k == 0) g_c0[0] = 96.f * cc;
    }
}

// ---------------------------------------------------------------------------
// conv panel: B panel (256K x 128N of xb) resident in smem; loop mtiles of A.
// BK=32 double-buffered A chunks (champion config).
// ---------------------------------------------------------------------------
__global__ __launch_bounds__(256) void conv_panel_kernel(
    const __nv_bfloat16* __restrict__ W, int mtiles,
    __nv_bfloat16* dst0, const float* bias0,
    __nv_bfloat16* dst1, const float* bias1)
{
    extern __shared__ __align__(16) __nv_bfloat16 dynsm[];
    __nv_bfloat16* Bs = dynsm;                               // [256][136]
    __nv_bfloat16* Ab[2] = { dynsm + 256*136, dynsm + 256*136 + 128*40 };

    int b = blockIdx.z, n0 = blockIdx.x * 128;
    int tid = threadIdx.x, wid = tid >> 5, lane = tid & 31;
    int mw = (wid >> 2) * 64, nw = (wid & 3) * 32;
    int g = lane >> 2, tg = lane & 3;

    const __nv_bfloat16* bbase = g_xb + (size_t)b * CC * HWSZ + n0;
    #pragma unroll
    for (int j = 0; j < 16; j++) {
        int idx = j * 256 + tid;
        int row = idx >> 4, cb8 = (idx & 15) * 8;
        cpa16(smem_u32(Bs + row*136 + cb8), bbase + (size_t)row * HWSZ + cb8);
    }
    CP_COMMIT();

    int arow = tid >> 1, acb = (tid & 1) * 16;

    for (int mt = 0; mt < mtiles; mt++) {
        int mbase = mt * 128;
        const __nv_bfloat16* asrc = W + (size_t)(mbase + arow) * 256 + acb;
        {
            uint32_t ad = smem_u32(Ab[0] + arow*40 + acb);
            cpa16(ad, asrc); cpa16(ad + 16, asrc + 8);
            CP_COMMIT();
        }
        float acc[4][4][4] = {};
        for (int kc = 0; kc < 8; kc++) {
            if (kc < 7) {
                uint32_t ad = smem_u32(Ab[(kc+1)&1] + arow*40 + acb);
                const __nv_bfloat16* as = asrc + (kc + 1) * 32;
                cpa16(ad, as); cpa16(ad + 16, as + 8);
                CP_COMMIT();
                cp_wait<1>();
            } else cp_wait<0>();
            __syncthreads();
            mma_tileT<40, 136, 2>(Ab[kc&1], Bs + kc*32*136, mw, nw, lane, acc);
            __syncthreads();
        }
        int mat = mbase >> 8, ob = mbase & 255;
        __nv_bfloat16* dst = mat ? dst1 : dst0;
        const float* bias = mat ? bias1 : bias0;
        #pragma unroll
        for (int mf = 0; mf < 4; mf++) {
            int r = mw + mf * 16 + g;
            int o1 = ob + r, o2 = o1 + 8;
            float b1 = bias ? bias[o1] : 0.f;
            float b2 = bias ? bias[o2] : 0.f;
            size_t base1 = ((size_t)b * CC + o1) * HWSZ + n0;
            size_t base2 = ((size_t)b * CC + o2) * HWSZ + n0;
            #pragma unroll
            for (int nf = 0; nf < 4; nf++) {
                int col = nw + nf * 8 + tg * 2;
                *(uint32_t*)&dst[base1 + col] = packbf(acc[mf][nf][0] + b1, acc[mf][nf][1] + b1);
                *(uint32_t*)&dst[base2 + col] = packbf(acc[mf][nf][2] + b2, acc[mf][nf][3] + b2);
            }
        }
    }
}

// ---------------------------------------------------------------------------
// apply channel panel: out = xin + beta * (P @ g), B = g panel resident.
// ---------------------------------------------------------------------------
__global__ __launch_bounds__(256) void apply_channel_panel_kernel(
    const float* __restrict__ xin, float* __restrict__ xout, const float* __restrict__ beta_p)
{
    extern __shared__ __align__(16) __nv_bfloat16 dynsm[];
    __nv_bfloat16* Bs = dynsm;
    __nv_bfloat16* Ab[2] = { dynsm + 256*136, dynsm + 256*136 + 128*40 };

    int b = blockIdx.z, n0 = blockIdx.x * 128;
    int tid = threadIdx.x, wid = tid >> 5, lane = tid & 31;
    int mw = (wid >> 2) * 64, nw = (wid & 3) * 32;
    int g = lane >> 2, tg = lane & 3;

    const __nv_bfloat16* bbase = g_gb + (size_t)b * CC * HWSZ + n0;
    #pragma unroll
    for (int j = 0; j < 16; j++) {
        int idx = j * 256 + tid;
        int row = idx >> 4, cb8 = (idx & 15) * 8;
        cpa16(smem_u32(Bs + row*136 + cb8), bbase + (size_t)row * HWSZ + cb8);
    }
    CP_COMMIT();

    int arow = tid >> 1, acb = (tid & 1) * 16;
    float beta = *beta_p;

    for (int mt = 0; mt < 2; mt++) {
        int mbase = mt * 128;
        const __nv_bfloat16* asrc = g_Pb + (size_t)b * 65536 + (size_t)(mbase + arow) * 256 + acb;
        {
            uint32_t ad = smem_u32(Ab[0] + arow*40 + acb);
            cpa16(ad, asrc); cpa16(ad + 16, asrc + 8);
            CP_COMMIT();
        }
        float acc[4][4][4] = {};
        for (int kc = 0; kc < 8; kc++) {
            if (kc < 7) {
                uint32_t ad = smem_u32(Ab[(kc+1)&1] + arow*40 + acb);
                const __nv_bfloat16* as = asrc + (kc + 1) * 32;
                cpa16(ad, as); cpa16(ad + 16, as + 8);
                CP_COMMIT();
                cp_wait<1>();
            } else cp_wait<0>();
            __syncthreads();
            mma_tileT<40, 136, 2>(Ab[kc&1], Bs + kc*32*136, mw, nw, lane, acc);
            __syncthreads();
        }
        #pragma unroll
        for (int mf = 0; mf < 4; mf++) {
            int r1 = mbase + mw + mf * 16 + g, r2 = r1 + 8;
            size_t base1 = ((size_t)b * CC + r1) * HWSZ + n0;
            size_t base2 = ((size_t)b * CC + r2) * HWSZ + n0;
            #pragma unroll
            for (int nf = 0; nf < 4; nf++) {
                int col = nw + nf * 8 + tg * 2;
                float2 xa = *(const float2*)&xin[base1 + col];
                float2 xb2 = *(const float2*)&xin[base2 + col];
                *(float2*)&xout[base1 + col] =
                    make_float2(xa.x + beta*acc[mf][nf][0], xa.y + beta*acc[mf][nf][1]);
                *(float2*)&xout[base2 + col] =
                    make_float2(xb2.x + beta*acc[mf][nf][2], xb2.y + beta*acc[mf][nf][3]);
            }
        }
    }
}

// ---------------------------------------------------------------------------
// per-axis x sums
// ---------------------------------------------------------------------------
template<int MODE>
__global__ __launch_bounds__(96) void xsum_kernel()
{
    int k = blockIdx.x, b = blockIdx.y, i = threadIdx.x;
    const __nv_bfloat16* src = g_xb + ((size_t)b * CC + k) * HWSZ;
    float s = 0.f;
    if (MODE == 0) {
        #pragma unroll 8
        for (int h = 0; h < 96; h++) s += __bfloat162float(src[h*96 + i]);
    } else {
        #pragma unroll 8
        for (int w = 0; w < 96; w++) s += __bfloat162float(src[i*96 + w]);
    }
    g_xs[((size_t)b * CC + k) * 96 + i] = s;
}

__global__ __launch_bounds__(96) void uv_kernel()
{
    int b = blockIdx.x, j = threadIdx.x;
    float su = 0.f, sv = 0.f;
    #pragma unroll 8
    for (int k = 0; k < 256; k++) {
        float xv = g_xs[((size_t)b * CC + k) * 96 + j];
        su += g_w2[k] * xv;
        sv += g_w1[k] * xv;
    }
    g_u[b*96 + j] = su;
    g_v[b*96 + j] = sv;
}

// ---------------------------------------------------------------------------
// slice logits (16 channels/block, grid 16x16)
// ---------------------------------------------------------------------------
template<int MODE>
__global__ __launch_bounds__(256) void slice_logits_bf16_kernel(
    const __nv_bfloat16* __restrict__ Abase, const __nv_bfloat16* __restrict__ Bbase)
{
    extern __shared__ __align__(16) __nv_bfloat16 dynsm[];
    __nv_bfloat16* Tb[2] = { dynsm,            dynsm + 2*96*104 };
    __nv_bfloat16* Pb[2] = { dynsm + 96*104,   dynsm + 3*96*104 };

    int b = blockIdx.y, cch = blockIdx.x;
    int tid = threadIdx.x, wid = tid >> 5, lane = tid & 31;
    int mw = (wid >> 2) * 48, nw = (wid & 3) * 24;
    int g = lane >> 2, tg = lane & 3;

    const __nv_bfloat16* tbase = Abase + ((size_t)b * CC + cch * 16) * HWSZ;
    const __nv_bfloat16* pbase = Bbase + ((size_t)b * CC + cch * 16) * HWSZ;

    float acc[3][3][4] = {};

    auto stage = [&](int cc, int bi) {
        const __nv_bfloat16* ts = tbase + (size_t)cc * HWSZ;
        const __nv_bfloat16* ps = pbase + (size_t)cc * HWSZ;
        #pragma unroll
        for (int j = 0; j < 9; j++) {
            int c = j * 256 + tid;
            int cc2 = (c < 1152) ? c : c - 1152;
            int row = cc2 / 12, col = (cc2 % 12) * 8;
            if (c < 1152) cpa16(smem_u32(Tb[bi] + row*104 + col), ts + row*96 + col);
            else          cpa16(smem_u32(Pb[bi] + row*104 + col), ps + row*96 + col);
        }
        CP_COMMIT();
    };

    stage(0, 0);
    for (int cc = 0; cc < 16; cc++) {
        if (cc < 15) { stage(cc + 1, (cc + 1) & 1); cp_wait<1>(); }
        else cp_wait<0>();
        __syncthreads();
        const __nv_bfloat16* As = Tb[cc & 1];
        const __nv_bfloat16* Bs = Pb[cc & 1];
        #pragma unroll
        for (int ks = 0; ks < 6; ks++) {
            int k0 = ks * 16;
            uint32_t a[3][4], bf[3][2];
            #pragma unroll
            for (int mf = 0; mf < 3; mf++) {
                if (MODE == 0)
                    ldsm4t(a[mf][0], a[mf][1], a[mf][2], a[mf][3],
                        smem_u32(As + (k0 + ((lane>>4)&1)*8 + (lane&7))*104 + mw + mf*16 + ((lane>>3)&1)*8));
                else
                    ldsm4(a[mf][0], a[mf][1], a[mf][2], a[mf][3],
                        smem_u32(As + (mw + mf*16 + (lane&15))*104 + k0 + (lane>>4)*8));
            }
            if (MODE == 0) {
                ldsm4t(bf[0][0], bf[0][1], bf[1][0], bf[1][1],
                       smem_u32(Bs + (k0 + (lane&15))*104 + nw + (lane>>4)*8));
                ldsm2t(bf[2][0], bf[2][1],
                       smem_u32(Bs + (k0 + (lane&15))*104 + nw + 16));
            } else {
                ldsm4(bf[0][0], bf[0][1], bf[1][0], bf[1][1],
                      smem_u32(Bs + (nw + (lane>>4)*8 + (lane&7))*104 + k0 + ((lane>>3)&1)*8));
                ldsm2(bf[2][0], bf[2][1],
                      smem_u32(Bs + (nw + 16 + (lane&7))*104 + k0 + ((lane>>3)&1)*8));
            }
            #pragma unroll
            for (int mf = 0; mf < 3; mf++)
                #pragma unroll
                for (int nf = 0; nf < 3; nf++)
                    mma_bf16(acc[mf][nf], a[mf][0], a[mf][1], a[mf][2], a[mf][3],
                             bf[nf][0], bf[nf][1]);
        }
        __syncthreads();
    }
    float* Sb = g_S + (size_t)b * 9216;
    #pragma unroll
    for (int mf = 0; mf < 3; mf++) {
        int i1 = mw + mf * 16 + g, i2 = i1 + 8;
        #pragma unroll
        for (int nf = 0; nf < 3; nf++) {
            int jc = nw + nf * 8 + tg * 2;
            atomicAdd(&Sb[i1 * 96 + jc],     acc[mf][nf][0]);
            atomicAdd(&Sb[i1 * 96 + jc + 1], acc[mf][nf][1]);
            atomicAdd(&Sb[i2 * 96 + jc],     acc[mf][nf][2]);
            atomicAdd(&Sb[i2 * 96 + jc + 1], acc[mf][nf][3]);
        }
    }
}

// ---------------------------------------------------------------------------
// softmax: optional additive bias. writes bf16 P.
// ---------------------------------------------------------------------------
__global__ __launch_bounds__(256) void softmax_kernel(int n, const float* u,
                                                      const float* v, const float* c0p)
{
    size_t base = (size_t)blockIdx.x * n;
    int tid = threadIdx.x;
    __shared__ float red[8];

    float rowadd = 0.f;
    int ub = 0;
    if (u) {
        rowadd = v[blockIdx.x] + *c0p;
        ub = (blockIdx.x / 96) * 96;
    }

    float m = -INFINITY;
    for (int j = tid; j < n; j += 256) {
        float val = g_S[base + j] + rowadd + (u ? u[ub + j] : 0.f);
        m = fmaxf(m, val);
    }
    #pragma unroll
    for (int o = 16; o; o >>= 1) m = fmaxf(m, __shfl_xor_sync(0xffffffffu, m, o));
    if ((tid & 31) == 0) red[tid >> 5] = m;
    __syncthreads();
    float mm = red[0];
    #pragma unroll
    for (int w = 1; w < 8; w++) mm = fmaxf(mm, red[w]);

    float s = 0.f;
    float ev[2];
    int cnt = 0;
    for (int j = tid; j < n; j += 256) {
        float val = g_S[base + j] + rowadd + (u ? u[ub + j] : 0.f);
        float e = __expf(val - mm);
        ev[cnt++] = e;
        s += e;
    }
    #pragma unroll
    for (int o = 16; o; o >>= 1) s += __shfl_xor_sync(0xffffffffu, s, o);
    if ((tid & 31) == 0) red[tid >> 5] = s;
    __syncthreads();
    float st = 0.f;
    #pragma unroll
    for (int w = 0; w < 8; w++) st += red[w];
    float inv = 1.0f / st;
    cnt = 0;
    for (int j = tid; j < n; j += 256)
        g_Pb[base + j] = __float2bfloat16(ev[cnt++] * inv);
}

// ---------------------------------------------------------------------------
// apply width: D[(c,h), i] = sum_j g[(c,h), j] P[i,j];  out = xin + beta*D.
// ---------------------------------------------------------------------------
__global__ __launch_bounds__(256) void apply_slice_w_kernel(
    const float* __restrict__ xin, float* __restrict__ xout, const float* __restrict__ beta_p)
{
    __shared__ __align__(16) __nv_bfloat16 As[128][104];
    __shared__ __align__(16) __nv_bfloat16 Bs[96][104];

    int b = blockIdx.y, m0 = blockIdx.x * 128;
    int tid = threadIdx.x, wid = tid >> 5, lane = tid & 31;
    int mw = (wid >> 1) * 32, nw = (wid & 1) * 48;
    int g = lane >> 2, tg = lane & 3;

    const __nv_bfloat16* gsrc = g_gb + (size_t)b * CC * HWSZ + (size_t)m0 * 96;
    const __nv_bfloat16* psrc = g_Pb + (size_t)b * 9216;
    #pragma unroll
    for (int j = 0; j < 6; j++) {
        int c = j * 256 + tid;
        int row = c / 12, col = (c % 12) * 8;
        cpa16(smem_u32(&As[row][col]), gsrc + row*96 + col);
    }
    #pragma unroll
    for (int j = 0; j < 5; j++) {
        int c = j * 256 + tid;
        if (c < 1152) {
            int row = c / 12, col = (c % 12) * 8;
            cpa16(smem_u32(&Bs[row][col]), psrc + row*96 + col);
        }
    }
    CP_COMMIT();
    cp_wait<0>();
    __syncthreads();

    float acc[2][6][4] = {};
    #pragma unroll
    for (int ks = 0; ks < 6; ks++) {
        int k0 = ks * 16;
        uint32_t a[2][4], bf[6][2];
        #pragma unroll
        for (int mf = 0; mf < 2; mf++)
            ldsm4(a[mf][0], a[mf][1], a[mf][2], a[mf][3],
                  smem_u32(&As[mw + mf*16 + (lane&15)][k0 + (lane>>4)*8]));
        #pragma unroll
        for (int nb = 0; nb < 3; nb++)
            ldsm4(bf[nb*2][0], bf[nb*2][1], bf[nb*2+1][0], bf[nb*2+1][1],
                  smem_u32(&Bs[nw + nb*16 + (lane>>4)*8 + (lane&7)][k0 + ((lane>>3)&1)*8]));
        #pragma unroll
        for (int mf = 0; mf < 2; mf++)
            #pragma unroll
            for (int nf = 0; nf < 6; nf++)
                mma_bf16(acc[mf][nf], a[mf][0], a[mf][1], a[mf][2], a[mf][3],
                         bf[nf][0], bf[nf][1]);
    }
    float beta = *beta_p;
    size_t gb = (size_t)b * CC * HWSZ;
    #pragma unroll
    for (int mf = 0; mf < 2; mf++) {
        int r1 = m0 + mw + mf * 16 + g, r2 = r1 + 8;
        #pragma unroll
        for (int nf = 0; nf < 6; nf++) {
            int col = nw + nf * 8 + tg * 2;
            size_t o1 = gb + (size_t)r1 * 96 + col;
            size_t o2 = gb + (size_t)r2 * 96 + col;
            float2 xa = *(const float2*)&xin[o1];
            float2 xb2 = *(const float2*)&xin[o2];
            float v0 = xa.x + beta*acc[mf][nf][0], v1 = xa.y + beta*acc[mf][nf][1];
            float v2 = xb2.x + beta*acc[mf][nf][2], v3 = xb2.y + beta*acc[mf][nf][3];
            *(float2*)&xout[o1] = make_float2(v0, v1);
            *(float2*)&xout[o2] = make_float2(v2, v3);
            *(uint32_t*)&g_xb[o1] = packbf(v0, v1);
            *(uint32_t*)&g_xb[o2] = packbf(v2, v3);
        }
    }
}

__global__ __launch_bounds__(256) void apply_slice_h_kernel(
    const float* __restrict__ xin, float* __restrict__ xout, const float* __restrict__ beta_p)
{
    __shared__ __align__(16) __nv_bfloat16 As[96][104];
    __shared__ __align__(16) __nv_bfloat16 Bs[96][104];

    int b = blockIdx.y, c = blockIdx.x;
    int tid = threadIdx.x, wid = tid >> 5, lane = tid & 31;
    int mw = (wid >> 2) * 48, nw = (wid & 3) * 24;
    int g = lane >> 2, tg = lane & 3;

    const __nv_bfloat16* psrc = g_Pb + (size_t)b * 9216;
    const __nv_bfloat16* gsrc = g_gb + ((size_t)b * CC + c) * HWSZ;
    #pragma unroll
    for (int j = 0; j < 9; j++) {
        int cidx = j * 256 + tid;
        int c2 = (cidx < 1152) ? cidx : cidx - 1152;
        int row = c2 / 12, col = (c2 % 12) * 8;
        if (cidx < 1152) cpa16(smem_u32(&As[row][col]), psrc + row*96 + col);
        else             cpa16(smem_u32(&Bs[row][col]), gsrc + row*96 + col);
    }
    CP_COMMIT();
    cp_wait<0>();
    __syncthreads();

    float acc[3][3][4] = {};
    #pragma unroll
    for (int ks = 0; ks < 6; ks++) {
        int k0 = ks * 16;
        uint32_t a[3][4], bf[3][2];
        #pragma unroll
        for (int mf = 0; mf < 3; mf++)
            ldsm4(a[mf][0], a[mf][1], a[mf][2], a[mf][3],
                  smem_u32(&As[mw + mf*16 + (lane&15)][k0 + (lane>>4)*8]));
        ldsm4t(bf[0][0], bf[0][1], bf[1][0], bf[1][1],
               smem_u32(&Bs[k0 + (lane&15)][nw + (lane>>4)*8]));
        ldsm2t(bf[2][0], bf[2][1],
               smem_u32(&Bs[k0 + (lane&15)][nw + 16]));
        #pragma unroll
        for (int mf = 0; mf < 3; mf++)
            #pragma unroll
            for (int nf = 0; nf < 3; nf++)
                mma_bf16(acc[mf][nf], a[mf][0], a[mf][1], a[mf][2], a[mf][3],
                         bf[nf][0], bf[nf][1]);
    }
    float beta = *beta_p;
    size_t base = ((size_t)b * CC + c) * HWSZ;
    #pragma unroll
    for (int mf = 0; mf < 3; mf++) {
        int i1 = mw + mf * 16 + g, i2 = i1 + 8;
        #pragma unroll
        for (int nf = 0; nf < 3; nf++) {
            int col = nw + nf * 8 + tg * 2;
            size_t o1 = base + (size_t)i1 * 96 + col;
            size_t o2 = base + (size_t)i2 * 96 + col;
            float2 xa = *(const float2*)&xin[o1];
            float2 xb2 = *(const float2*)&xin[o2];
            float v0 = xa.x + beta*acc[mf][nf][0], v1 = xa.y + beta*acc[mf][nf][1];
            float v2 = xb2.x + beta*acc[mf][nf][2], v3 = xb2.y + beta*acc[mf][nf][3];
            *(float2*)&xout[o1] = make_float2(v0, v1);
            *(float2*)&xout[o2] = make_float2(v2, v3);
            *(uint32_t*)&g_xb[o1] = packbf(v0, v1);
            *(uint32_t*)&g_xb[o2] = packbf(v2, v3);
        }
    }
}

// ---------------------------------------------------------------------------
// Gram: 128x128 tiles, symmetric (3 tile-blocks per b), BK=32 double-buffered.
// ---------------------------------------------------------------------------
__global__ __launch_bounds__(256) void gram_kernel()
{
    __shared__ __align__(16) __nv_bfloat16 Asm[2][128][40];
    __shared__ __align__(16) __nv_bfloat16 Bsm[2][128][40];

    int ti = blockIdx.x, b = blockIdx.y;
    int i0 = (ti == 2) ? 128 : 0;
    int j0 = (ti == 0) ? 0 : 128;
    int tid = threadIdx.x, wid = tid >> 5, lane = tid & 31;
    int mw = (wid >> 2) * 64, nw = (wid & 3) * 32;
    int g = lane >> 2, tg = lane & 3;

    int row = tid >> 1, cb = (tid & 1) * 16;
    const __nv_bfloat16* as0 = g_xb + ((size_t)b * CC + i0 + row) * HWSZ + cb;
    const __nv_bfloat16* bs0 = g_xb + ((size_t)b * CC + j0 + row) * HWSZ + cb;

    float acc[4][4][4] = {};

    auto stage = [&](int kk, int bi) {
        uint32_t ad = smem_u32(&Asm[bi][row][cb]);
        uint32_t bd = smem_u32(&Bsm[bi][row][cb]);
        cpa16(ad, as0 + kk); cpa16(ad + 16, as0 + kk + 8);
        cpa16(bd, bs0 + kk); cpa16(bd + 16, bs0 + kk + 8);
        CP_COMMIT();
    };

    stage(0, 0);
    for (int s = 0; s < 288; s++) {
        if (s < 287) { stage((s + 1) * 32, (s + 1) & 1); cp_wait<1>(); }
        else cp_wait<0>();
        __syncthreads();
        mma_tileNN<40, 40, 2>(&Asm[s&1][0][0], &Bsm[s&1][0][0], mw, nw, lane, acc);
        __syncthreads();
    }
    float* Gb = g_G + (size_t)b * 65536;
    #pragma unroll
    for (int mf = 0; mf < 4; mf++) {
        int i1 = i0 + mw + mf * 16 + g, i2 = i1 + 8;
        #pragma unroll
        for (int nf = 0; nf < 4; nf++) {
            int jc = j0 + nw + nf * 8 + tg * 2;
            *(float2*)&Gb[(size_t)i1 * 256 + jc] = make_float2(acc[mf][nf][0], acc[mf][nf][1]);
            *(float2*)&Gb[(size_t)i2 * 256 + jc] = make_float2(acc[mf][nf][2], acc[mf][nf][3]);
            if (ti == 1) {
                Gb[(size_t)jc * 256 + i1]       = acc[mf][nf][0];
                Gb[(size_t)(jc + 1) * 256 + i1] = acc[mf][nf][1];
                Gb[(size_t)jc * 256 + i2]       = acc[mf][nf][2];
                Gb[(size_t)(jc + 1) * 256 + i2] = acc[mf][nf][3];
            }
        }
    }
}

// xs2[b,c] = sum_hw x[b,c,:]
__global__ __launch_bounds__(256) void xsum2_kernel()
{
    int k = blockIdx.x, b = blockIdx.y, tid = threadIdx.x;
    const __nv_bfloat16* src = g_xb + ((size_t)b * CC + k) * HWSZ;
    __shared__ float red[8];
    float s = 0.f;
    for (int e = tid; e < HWSZ; e += 256) s += __bfloat162float(src[e]);
    #pragma unroll
    for (int o = 16; o; o >>= 1) s += __shfl_xor_sync(0xffffffffu, s, o);
    if ((tid & 31) == 0) red[tid >> 5] = s;
    __syncthreads();
    if (tid == 0) {
        float t = 0.f;
        #pragma unroll
        for (int w = 0; w < 8; w++) t += red[w];
        g_xs2[b * CC + k] = t;
    }
}

__global__ __launch_bounds__(256) void sAsB_kernel(const float* __restrict__ wt,
                                                   const float* __restrict__ wp,
                                                   const float* __restrict__ bp)
{
    int i = blockIdx.x, b = blockIdx.y, c = threadIdx.x;
    __shared__ float r1[8], r2[8];
    float xv = g_xs2[b*CC + c];
    float sa = wt[i*256 + c] * xv;
    float sb = wp[i*256 + c] * xv;
    #pragma unroll
    for (int off = 16; off; off >>= 1) {
        sa += __shfl_xor_sync(0xffffffffu, sa, off);
        sb += __shfl_xor_sync(0xffffffffu, sb, off);
    }
    if ((c & 31) == 0) { r1[c>>5] = sa; r2[c>>5] = sb; }
    __syncthreads();
    if (c == 0) {
        float a = 0.f, b2 = 0.f;
        #pragma unroll
        for (int w = 0; w < 8; w++) { a += r1[w]; b2 += r2[w]; }
        g_sA[b*CC + i] = a;
        g_sB2[b*CC + i] = b2 + 9216.f * bp[i];
    }
}

// ---------------------------------------------------------------------------
// fp32 GEMM NN: T1[b] = wt @ G[b]. Tile 64x64, BK=16.
// ---------------------------------------------------------------------------
__global__ __launch_bounds__(256) void f32gemm_nn_kernel(const float* __restrict__ wt)
{
    int b  = blockIdx.z;
    int i0 = blockIdx.y * 64;
    int n0 = blockIdx.x * 64;

    __shared__ __align__(16) float As[16 * 68];
    __shared__ __align__(16) float Gs[16 * 68];

    int tid = threadIdx.x;
    int ti4 = (tid >> 4) * 4, tj4 = (tid & 15) * 4;
    float acc[4][4] = {};

    const float* Gb = g_G + (size_t)b * 65536;

    for (int kk = 0; kk < 256; kk += 16) {
        #pragma unroll
        for (int rr = 0; rr < 4; rr++) {
            int r = rr * 16 + (tid >> 4);
            int cload = tid & 15;
            As[cload * 68 + r] = wt[(i0 + r) * 256 + kk + cload];
        }
        #pragma unroll
        for (int rr = 0; rr < 4; rr++) {
            int k = rr * 4 + (tid >> 6);
            int n = tid & 63;
            Gs[k * 68 + n] = Gb[(size_t)(kk + k) * 256 + n0 + n];
        }
        __syncthreads();
        #pragma unroll
        for (int k = 0; k < 16; k++) {
            float4 a = *(float4*)&As[k * 68 + ti4];
            float4 g4 = *(float4*)&Gs[k * 68 + tj4];
            float ar[4] = {a.x, a.y, a.z, a.w};
            float gr[4] = {g4.x, g4.y, g4.z, g4.w};
            #pragma unroll
            for (int i = 0; i < 4; i++)
                #pragma unroll
                for (int j = 0; j < 4; j++)
                    acc[i][j] += ar[i] * gr[j];
        }
        __syncthreads();
    }

    float* T1b = g_T1 + (size_t)b * 65536;
    #pragma unroll
    for (int i = 0; i < 4; i++)
        #pragma unroll
        for (int j = 0; j < 4; j++)
            T1b[(size_t)(i0 + ti4 + i) * 256 + n0 + tj4 + j] = acc[i][j];
}

// ---------------------------------------------------------------------------
// fp32 GEMM NT + channel-bias epilogue.
// ---------------------------------------------------------------------------
__global__ __launch_bounds__(256) void f32gemm_nt_kernel(const float* __restrict__ wp,
                                                         const float* __restrict__ bt,
                                                         const float* __restrict__ bp)
{
    int b  = blockIdx.z;
    int i0 = blockIdx.y * 64;
    int j0 = blockIdx.x * 64;

    __shared__ __align__(16) float Ts[32 * 68];
    __shared__ __align__(16) float Ps[32 * 68];

    int tid = threadIdx.x;
    int lc = tid & 31, lr = tid >> 5;
    int ti4 = (tid >> 4) * 4, tj4 = (tid & 15) * 4;

    float acc[4][4] = {};
    const float* T1b = g_T1 + (size_t)b * 65536;

    for (int kb = 0; kb < 8; kb++) {
        int k0 = kb * 32;
        #pragma unroll
        for (int rr = 0; rr < 8; rr++) {
            int r = rr * 8 + lr;
            Ts[lc * 68 + r] = T1b[(size_t)(i0 + r) * 256 + k0 + lc];
            Ps[lc * 68 + r] = wp[(j0 + r) * 256 + k0 + lc];
        }
        __syncthreads();
        #pragma unroll
        for (int k = 0; k < 32; k++) {
            float4 a = *(float4*)&Ts[k * 68 + ti4];
            float4 p = *(float4*)&Ps[k * 68 + tj4];
            float ar[4] = {a.x, a.y, a.z, a.w};
            float pr[4] = {p.x, p.y, p.z, p.w};
            #pragma unroll
            for (int i = 0; i < 4; i++)
                #pragma unroll
                for (int j = 0; j < 4; j++)
                    acc[i][j] += ar[i] * pr[j];
        }
        __syncthreads();
    }

    float* Sb = g_S + (size_t)b * 65536;
    #pragma unroll
    for (int i = 0; i < 4; i++) {
        int irow = i0 + ti4 + i;
        float bti = bt[irow], sai = g_sA[b*CC + irow];
        #pragma unroll
        for (int j = 0; j < 4; j++) {
            int jcol = j0 + tj4 + j;
            Sb[(size_t)irow * 256 + jcol] =
                acc[i][j] + bti * g_sB2[b*CC + jcol] + bp[jcol] * sai;
        }
    }
}

// ---------------------------------------------------------------------------
extern "C" void kernel_launch(void* const* d_in, const int* in_sizes, int n_in,
                              void* d_out, int out_size)
{
    const float* x      = (const float*)d_in[0];
    const float* wt     = (const float*)d_in[1];
    const float* bt     = (const float*)d_in[2];
    const float* wp     = (const float*)d_in[3];
    const float* bp     = (const float*)d_in[4];
    const float* wg     = (const float*)d_in[5];
    const float* bg     = (const float*)d_in[6];
    const float* beta_w = (const float*)d_in[7];
    const float* beta_h = (const float*)d_in[8];
    const float* beta_c = (const float*)d_in[9];
    float* out = (float*)d_out;

    float *x1, *x2, *S, *uu, *vv, *c0;
    __nv_bfloat16 *thb, *gbb, *W2, *xbb, *Wbf;
    cudaGetSymbolAddress((void**)&x1, g_x1);
    cudaGetSymbolAddress((void**)&x2, g_x2);
    cudaGetSymbolAddress((void**)&S,  g_S);
    cudaGetSymbolAddress((void**)&uu, g_u);
    cudaGetSymbolAddress((void**)&vv, g_v);
    cudaGetSymbolAddress((void**)&c0, g_c0);
    cudaGetSymbolAddress((void**)&thb, g_thb);
    cudaGetSymbolAddress((void**)&gbb, g_gb);
    cudaGetSymbolAddress((void**)&W2,  g_W2);
    cudaGetSymbolAddress((void**)&xbb, g_xb);
    cudaGetSymbolAddress((void**)&Wbf, g_Wbf);

    int panel_smem = 256*136*2 + 2*128*40*2;      // 90,112 B
    int slice_smem = 4 * 96 * 104 * 2;            // 79,872 B
    cudaFuncSetAttribute(conv_panel_kernel,
                         cudaFuncAttributeMaxDynamicSharedMemorySize, panel_smem);
    cudaFuncSetAttribute(apply_channel_panel_kernel,
                         cudaFuncAttributeMaxDynamicSharedMemorySize, panel_smem);
    cudaFuncSetAttribute(slice_logits_bf16_kernel<0>,
                         cudaFuncAttributeMaxDynamicSharedMemorySize, slice_smem);
    cudaFuncSetAttribute(slice_logits_bf16_kernel<1>,
                         cudaFuncAttributeMaxDynamicSharedMemorySize, slice_smem);

    static cudaStream_t s2 = nullptr;
    static cudaEvent_t ev[8];
    if (!s2) {
        cudaStreamCreateWithFlags(&s2, cudaStreamNonBlocking);
        for (int i = 0; i < 8; i++)
            cudaEventCreateWithFlags(&ev[i], cudaEventDisableTiming);
    }
    cudaStream_t s0 = 0;

    // ---- prologue ----
    xconv_kernel<<<NELEM / (256 * 8), 256, 0, s0>>>(x);
    cudaEventRecord(ev[0], s0);                               // g_xb ready

    cudaStreamWaitEvent(s2, ev[0], 0);                        // fork s2
    wconv_kernel<<<768, 256, 0, s2>>>(wt, wp, wg);
    mprep_kernel<<<dim3(4, 4), 128, 0, s2>>>();
    cudaEventRecord(ev[1], s2);                               // W2 ready
    biasvec_kernel<<<256, 256, 0, s2>>>(wt, wp, bt, bp);
    cudaMemsetAsync(S, 0, (size_t)16 * 9216 * sizeof(float), s2);
    xsum_kernel<0><<<dim3(256, 16), 96, 0, s2>>>();
    uv_kernel<<<16, 96, 0, s2>>>();
    cudaEventRecord(ev[2], s2);                               // S zeroed + u/v ready

    // ---- round 1: width attention ----
    cudaStreamWaitEvent(s0, ev[1], 0);
    conv_panel_kernel<<<dim3(72, 1, 16), 256, panel_smem, s0>>>(W2, 4, thb, nullptr, gbb, bg);
    cudaStreamWaitEvent(s0, ev[2], 0);
    slice_logits_bf16_kernel<0><<<dim3(16, 16), 256, slice_smem, s0>>>(xbb, thb);
    softmax_kernel<<<16 * 96, 256, 0, s0>>>(96, uu, vv, c0);
    apply_slice_w_kernel<<<dim3(192, 16), 256, 0, s0>>>(x, x1, beta_w);
    cudaEventRecord(ev[3], s0);                               // new x (g_xb) ready

    // ---- round 2: height attention ----
    cudaStreamWaitEvent(s2, ev[3], 0);
    cudaMemsetAsync(S, 0, (size_t)16 * 9216 * sizeof(float), s2);
    xsum_kernel<1><<<dim3(256, 16), 96, 0, s2>>>();
    uv_kernel<<<16, 96, 0, s2>>>();
    cudaEventRecord(ev[4], s2);

    conv_panel_kernel<<<dim3(72, 1, 16), 256, panel_smem, s0>>>(W2, 4, thb, nullptr, gbb, bg);
    cudaStreamWaitEvent(s0, ev[4], 0);
    slice_logits_bf16_kernel<1><<<dim3(16, 16), 256, slice_smem, s0>>>(xbb, thb);
    softmax_kernel<<<16 * 96, 256, 0, s0>>>(96, uu, vv, c0);
    apply_slice_h_kernel<<<dim3(256, 16), 256, 0, s0>>>(x1, x2, beta_h);
    cudaEventRecord(ev[5], s0);                               // new x (g_xb) ready

    // ---- round 3: channel attention ----
    cudaStreamWaitEvent(s2, ev[5], 0);
    xsum2_kernel<<<dim3(256, 16), 256, 0, s2>>>();
    sAsB_kernel<<<dim3(256, 16), 256, 0, s2>>>(wt, wp, bp);
    gram_kernel<<<dim3(3, 16), 256, 0, s2>>>();
    cudaEventRecord(ev[6], s2);                               // G + sA/sB2 ready

    conv_panel_kernel<<<dim3(72, 1, 16), 256, panel_smem, s0>>>(Wbf + 2*65536, 2, gbb, bg, gbb, bg);
    cudaStreamWaitEvent(s0, ev[6], 0);
    f32gemm_nn_kernel<<<dim3(4, 4, 16), 256, 0, s0>>>(wt);
    f32gemm_nt_kernel<<<dim3(4, 4, 16), 256, 0, s0>>>(wp, bt, bp);
    softmax_kernel<<<16 * 256, 256, 0, s0>>>(256, nullptr, nullptr, nullptr);
    apply_channel_panel_kernel<<<dim3(72, 1, 16), 256, panel_smem, s0>>>(x2, out, beta_c);
}